// round 1
// baseline (speedup 1.0000x reference)
#include <cuda_runtime.h>

#define B_  8
#define N_  2048
#define C_  512
#define CR_ 64
#define PD_ 640   // projection buffer width: [0,64)=K, [64,128)=V, [128,640)=Q

// Scratch: projections of every token row. 8*2048*640*4 = ~42 MB.
__device__ float g_P[(size_t)B_ * N_ * PD_];

// ---------------------------------------------------------------------------
// Kernel 1: fused projection GEMM.
// out[r, o] = sum_c x[r,c] * W[o,c] + bias[o], where W is Wk/Wv/Wq per o-tile.
// Grid: (PD_/64 = 10 o-tiles, 16384/64 = 256 row-tiles), 256 threads.
// ---------------------------------------------------------------------------
__global__ __launch_bounds__(256) void proj_kernel(
    const float* __restrict__ x,
    const float* __restrict__ Wk, const float* __restrict__ bk,
    const float* __restrict__ Wv, const float* __restrict__ bv,
    const float* __restrict__ Wq, const float* __restrict__ bq)
{
    __shared__ float sAT[64][68];   // [k][row], transposed for LDS.128 reads
    __shared__ float sWT[64][68];   // [k][o]

    const int ot  = blockIdx.x;     // 0..9
    const int rt  = blockIdx.y;     // 0..255
    const int tid = threadIdx.x;

    const float* W; const float* bias; int wrow0;
    if (ot == 0)      { W = Wk; bias = bk; wrow0 = 0; }
    else if (ot == 1) { W = Wv; bias = bv; wrow0 = 0; }
    else              { W = Wq; bias = bq; wrow0 = (ot - 2) * 64; }

    const int row0 = rt * 64;
    const int tx = tid & 15;        // o quad
    const int ty = tid >> 4;        // row quad

    float acc[4][4];
    #pragma unroll
    for (int i = 0; i < 4; i++)
        #pragma unroll
        for (int j = 0; j < 4; j++) acc[i][j] = 0.f;

    for (int kc = 0; kc < C_; kc += 64) {
        #pragma unroll
        for (int l = 0; l < 4; l++) {
            int idx = tid + l * 256;            // 0..1023 float4 slots
            int r   = idx >> 4;
            int c4  = (idx & 15) << 2;
            float4 v = *(const float4*)&x[(size_t)(row0 + r) * C_ + kc + c4];
            sAT[c4 + 0][r] = v.x; sAT[c4 + 1][r] = v.y;
            sAT[c4 + 2][r] = v.z; sAT[c4 + 3][r] = v.w;
        }
        #pragma unroll
        for (int l = 0; l < 4; l++) {
            int idx = tid + l * 256;
            int r   = idx >> 4;                 // o local
            int c4  = (idx & 15) << 2;
            float4 v = *(const float4*)&W[(size_t)(wrow0 + r) * C_ + kc + c4];
            sWT[c4 + 0][r] = v.x; sWT[c4 + 1][r] = v.y;
            sWT[c4 + 2][r] = v.z; sWT[c4 + 3][r] = v.w;
        }
        __syncthreads();

        #pragma unroll 8
        for (int k = 0; k < 64; k++) {
            float4 a4 = *(const float4*)&sAT[k][ty << 2];
            float4 w4 = *(const float4*)&sWT[k][tx << 2];
            float a[4] = {a4.x, a4.y, a4.z, a4.w};
            float w[4] = {w4.x, w4.y, w4.z, w4.w};
            #pragma unroll
            for (int i = 0; i < 4; i++)
                #pragma unroll
                for (int j = 0; j < 4; j++)
                    acc[i][j] += a[i] * w[j];
        }
        __syncthreads();
    }

    const int olocal0 = tx << 2;
    const int ocol0   = ot * 64 + olocal0;
    float bb[4];
    #pragma unroll
    for (int j = 0; j < 4; j++) bb[j] = bias[wrow0 + olocal0 + j];

    #pragma unroll
    for (int i = 0; i < 4; i++) {
        int r = row0 + (ty << 2) + i;
        float4 o;
        o.x = acc[i][0] + bb[0];
        o.y = acc[i][1] + bb[1];
        o.z = acc[i][2] + bb[2];
        o.w = acc[i][3] + bb[3];
        *(float4*)&g_P[(size_t)r * PD_ + ocol0] = o;
    }
}

// ---------------------------------------------------------------------------
// Kernel 2: fused attention.
// Per CTA: (batch b, m-tile of 64 output tokens, c-tile of 128 channels).
// Streams n in tiles of 64:
//   S[n,m] = K[n,:] . V[m,:]    (CR=64)
//   P = exp(S)   (no max subtraction needed: |S| bounded ~10)
//   den[m] += colsum(P);  Acc[c,m] += Q[n,c] * P[n,m]
// Epilogue: out[b,m,c] = gamma * Acc[c,m]/den[m] + x[b,m,c]
// ---------------------------------------------------------------------------
#define TM 64
#define TN 64
#define TC 128

// dynamic smem layout (floats)
#define SVT_OFF 0                       // [c][m]  64 x 68
#define SKT_OFF (SVT_OFF + 64 * 68)     // [c][n]  64 x 68
#define SP_OFF  (SKT_OFF + 64 * 68)     // [n][m]  64 x 68
#define SQ_OFF  (SP_OFF  + 64 * 68)     // [n][c]  64 x 132
#define SDEN_OFF (SQ_OFF + 64 * 132)    // [ty][m] 16 x 64
#define SMEM_FLOATS (SDEN_OFF + 16 * 64)
#define SMEM_BYTES  (SMEM_FLOATS * 4)   // 90112 B

__global__ __launch_bounds__(256, 2) void attn_kernel(
    const float* __restrict__ x, const float* __restrict__ gamma_p,
    float* __restrict__ out)
{
    extern __shared__ float sm[];
    float* sVT  = sm + SVT_OFF;
    float* sKT  = sm + SKT_OFF;
    float* sP   = sm + SP_OFF;
    float* sQ   = sm + SQ_OFF;
    float* sDen = sm + SDEN_OFF;

    const int mt = blockIdx.x, ct = blockIdx.y, b = blockIdx.z;
    const int tid = threadIdx.x;
    const int tx = tid & 15;            // m quad (both phases)
    const int ty = tid >> 4;            // n quad (S phase) / c oct (Acc phase)
    const size_t rb = (size_t)b * N_;
    const int m0 = mt * TM;

    // load V^T for this m-tile (cols [64,128) of g_P), once
    #pragma unroll
    for (int l = 0; l < 4; l++) {
        int idx = tid + l * 256;
        int r   = idx >> 4;
        int c4  = (idx & 15) << 2;
        float4 v = *(const float4*)&g_P[(rb + m0 + r) * PD_ + 64 + c4];
        sVT[(c4 + 0) * 68 + r] = v.x; sVT[(c4 + 1) * 68 + r] = v.y;
        sVT[(c4 + 2) * 68 + r] = v.z; sVT[(c4 + 3) * 68 + r] = v.w;
    }

    float acc[8][4];
    #pragma unroll
    for (int k = 0; k < 8; k++)
        #pragma unroll
        for (int j = 0; j < 4; j++) acc[k][j] = 0.f;
    float den[4] = {0.f, 0.f, 0.f, 0.f};

    const int qc0 = 128 + ct * TC;

    for (int nt = 0; nt < N_ / TN; nt++) {
        const int n0 = nt * TN;
        __syncthreads();   // previous Acc-phase reads done before overwrite

        // load K^T (cols [0,64))
        #pragma unroll
        for (int l = 0; l < 4; l++) {
            int idx = tid + l * 256;
            int r   = idx >> 4;
            int c4  = (idx & 15) << 2;
            float4 v = *(const float4*)&g_P[(rb + n0 + r) * PD_ + c4];
            sKT[(c4 + 0) * 68 + r] = v.x; sKT[(c4 + 1) * 68 + r] = v.y;
            sKT[(c4 + 2) * 68 + r] = v.z; sKT[(c4 + 3) * 68 + r] = v.w;
        }
        // load Q rows for this c-tile (row-major in smem)
        #pragma unroll
        for (int l = 0; l < 8; l++) {
            int idx = tid + l * 256;            // 0..2047
            int r   = idx >> 5;
            int c4  = (idx & 31) << 2;
            float4 v = *(const float4*)&g_P[(rb + n0 + r) * PD_ + qc0 + c4];
            *(float4*)&sQ[r * 132 + c4] = v;
        }
        __syncthreads();

        // --- S = K @ V^T, per thread 4n x 4m ---
        float s[4][4];
        #pragma unroll
        for (int i = 0; i < 4; i++)
            #pragma unroll
            for (int j = 0; j < 4; j++) s[i][j] = 0.f;

        #pragma unroll 8
        for (int k = 0; k < CR_; k++) {
            float4 k4 = *(const float4*)&sKT[k * 68 + (ty << 2)];
            float4 v4 = *(const float4*)&sVT[k * 68 + (tx << 2)];
            float ka[4] = {k4.x, k4.y, k4.z, k4.w};
            float va[4] = {v4.x, v4.y, v4.z, v4.w};
            #pragma unroll
            for (int i = 0; i < 4; i++)
                #pragma unroll
                for (int j = 0; j < 4; j++)
                    s[i][j] += ka[i] * va[j];
        }
        // exp + write P + accumulate den
        #pragma unroll
        for (int i = 0; i < 4; i++)
            #pragma unroll
            for (int j = 0; j < 4; j++) {
                float e = __expf(s[i][j]);
                sP[((ty << 2) + i) * 68 + (tx << 2) + j] = e;
                den[j] += e;
            }
        __syncthreads();

        // --- Acc[8c x 4m] += Q^T @ P ---
        #pragma unroll 4
        for (int n = 0; n < TN; n++) {
            float4 p4  = *(const float4*)&sP[n * 68 + (tx << 2)];
            float4 qa4 = *(const float4*)&sQ[n * 132 + (ty << 3)];
            float4 qb4 = *(const float4*)&sQ[n * 132 + (ty << 3) + 4];
            float pa[4] = {p4.x, p4.y, p4.z, p4.w};
            float qa[8] = {qa4.x, qa4.y, qa4.z, qa4.w, qb4.x, qb4.y, qb4.z, qb4.w};
            #pragma unroll
            for (int k = 0; k < 8; k++)
                #pragma unroll
                for (int j = 0; j < 4; j++)
                    acc[k][j] += qa[k] * pa[j];
        }
    }

    // --- den reduction across the 16 ty groups ---
    __syncthreads();
    #pragma unroll
    for (int j = 0; j < 4; j++) sDen[ty * 64 + (tx << 2) + j] = den[j];
    __syncthreads();
    float dinv[4];
    #pragma unroll
    for (int j = 0; j < 4; j++) {
        float s = 0.f;
        #pragma unroll
        for (int t = 0; t < 16; t++) s += sDen[t * 64 + (tx << 2) + j];
        dinv[j] = 1.0f / s;
    }

    // --- epilogue: out = gamma * Acc/den + x ---
    const float g = gamma_p[0];
    const int cg0 = ct * TC + (ty << 3);
    #pragma unroll
    for (int j = 0; j < 4; j++) {
        size_t orow = (rb + m0 + (tx << 2) + j) * C_ + cg0;
        float4 x0 = *(const float4*)&x[orow];
        float4 x1 = *(const float4*)&x[orow + 4];
        float4 o0, o1;
        o0.x = g * acc[0][j] * dinv[j] + x0.x;
        o0.y = g * acc[1][j] * dinv[j] + x0.y;
        o0.z = g * acc[2][j] * dinv[j] + x0.z;
        o0.w = g * acc[3][j] * dinv[j] + x0.w;
        o1.x = g * acc[4][j] * dinv[j] + x1.x;
        o1.y = g * acc[5][j] * dinv[j] + x1.y;
        o1.z = g * acc[6][j] * dinv[j] + x1.z;
        o1.w = g * acc[7][j] * dinv[j] + x1.w;
        *(float4*)&out[orow]     = o0;
        *(float4*)&out[orow + 4] = o1;
    }
}

// ---------------------------------------------------------------------------
extern "C" void kernel_launch(void* const* d_in, const int* in_sizes, int n_in,
                              void* d_out, int out_size)
{
    const float* x     = (const float*)d_in[0];
    const float* Wk    = (const float*)d_in[1];
    const float* bk    = (const float*)d_in[2];
    const float* Wv    = (const float*)d_in[3];
    const float* bv    = (const float*)d_in[4];
    const float* Wq    = (const float*)d_in[5];
    const float* bq    = (const float*)d_in[6];
    const float* gamma = (const float*)d_in[7];
    float* out = (float*)d_out;

    cudaFuncSetAttribute(attn_kernel,
                         cudaFuncAttributeMaxDynamicSharedMemorySize, SMEM_BYTES);

    proj_kernel<<<dim3(PD_ / 64, (B_ * N_) / 64), 256>>>(x, Wk, bk, Wv, bv, Wq, bq);
    attn_kernel<<<dim3(N_ / TM, C_ / TC, B_), 256, SMEM_BYTES>>>(x, gamma, out);
}

// round 3
// speedup vs baseline: 2.6087x; 2.6087x over previous
#include <cuda_runtime.h>
#include <cstdint>

#define B_  8
#define N_  2048
#define C_  512
#define CR_ 64

// Projection outputs (tf32-rounded fp32). No allocs allowed -> device globals.
__device__ float g_K [(size_t)B_ * N_ * CR_];   // [b*N+n][64]
__device__ float g_V [(size_t)B_ * N_ * CR_];   // [b*N+m][64]
__device__ float g_Qt[(size_t)B_ * C_ * N_];    // [b*C+c][n]

// round fp32 -> tf32 (round-to-nearest, unbiased)
__device__ __forceinline__ float f2tf(float x) {
    uint32_t u;
    asm("cvt.rna.tf32.f32 %0, %1;" : "=r"(u) : "f"(x));
    return __uint_as_float(u);
}

// warp mma: D(16x8) += A(16x8) * B(8x8), tf32 inputs, fp32 accum
__device__ __forceinline__ void mma8(float d[4], const float a[4], float b0, float b1) {
    asm volatile(
        "mma.sync.aligned.m16n8k8.row.col.f32.tf32.tf32.f32 "
        "{%0,%1,%2,%3}, {%4,%5,%6,%7}, {%8,%9}, {%0,%1,%2,%3};"
        : "+f"(d[0]), "+f"(d[1]), "+f"(d[2]), "+f"(d[3])
        : "r"(__float_as_uint(a[0])), "r"(__float_as_uint(a[1])),
          "r"(__float_as_uint(a[2])), "r"(__float_as_uint(a[3])),
          "r"(__float_as_uint(b0)),   "r"(__float_as_uint(b1)));
}

// =======================================================================
// Kernel 1: projection GEMM (tf32 HMMA).
// P[r,o] = sum_k x[r,k] * W[o,k] + bias[o]
// grid (10 o-tiles of 64, 128 row-tiles of 128), 256 threads (8 warps).
// o-tile 0 -> K, 1 -> V, 2..9 -> Q cols (ot-2)*64.. (written transposed).
// =======================================================================
#define PROJ_SMEM_FLOATS (128*68 + 64*68)
__global__ __launch_bounds__(256, 1) void proj_hmma(
    const float* __restrict__ x,
    const float* __restrict__ Wk, const float* __restrict__ bk,
    const float* __restrict__ Wv, const float* __restrict__ bv,
    const float* __restrict__ Wq, const float* __restrict__ bq)
{
    extern __shared__ float sm[];
    float* sA = sm;             // [128][68]  x tile, row-major
    float* sB = sA + 128 * 68;  // [64][68]   W tile, row-major
    float* sT = sm;             // reuse: [64][132] transpose staging (Q path)

    const int tid = threadIdx.x;
    const int wid = tid >> 5, lane = tid & 31;
    const int g = lane >> 2, t = lane & 3;
    const int wlo = wid & 3;    // row group (32 rows)
    const int whi = wid >> 2;   // o group (32 outs)

    const int ot = blockIdx.x;
    const int row0 = blockIdx.y * 128;

    const float* W; const float* bias;
    if (ot == 0)      { W = Wk; bias = bk; }
    else if (ot == 1) { W = Wv; bias = bv; }
    else              { W = Wq + (size_t)(ot - 2) * 64 * C_; bias = bq + (ot - 2) * 64; }

    float acc[8][4];            // [fi*4 + jf][4]
    #pragma unroll
    for (int i = 0; i < 8; i++)
        #pragma unroll
        for (int j = 0; j < 4; j++) acc[i][j] = 0.f;

    for (int kc = 0; kc < C_; kc += 64) {
        __syncthreads();
        #pragma unroll
        for (int l = 0; l < 8; l++) {
            int idx = tid + l * 256;
            int r = idx >> 4, c4 = (idx & 15) << 2;
            float4 v = *(const float4*)&x[(size_t)(row0 + r) * C_ + kc + c4];
            float* d = &sA[r * 68 + c4];
            d[0] = f2tf(v.x); d[1] = f2tf(v.y); d[2] = f2tf(v.z); d[3] = f2tf(v.w);
        }
        #pragma unroll
        for (int l = 0; l < 4; l++) {
            int idx = tid + l * 256;
            int r = idx >> 4, c4 = (idx & 15) << 2;
            float4 v = *(const float4*)&W[(size_t)r * C_ + kc + c4];
            float* d = &sB[r * 68 + c4];
            d[0] = f2tf(v.x); d[1] = f2tf(v.y); d[2] = f2tf(v.z); d[3] = f2tf(v.w);
        }
        __syncthreads();

        #pragma unroll
        for (int kk = 0; kk < 64; kk += 8) {
            float a0[4], a1[4];
            const float* Qa = &sA[(32 * wlo + g) * 68 + kk + t];
            a0[0] = Qa[0];        a0[1] = Qa[8 * 68];
            a0[2] = Qa[4];        a0[3] = Qa[8 * 68 + 4];
            a1[0] = Qa[16 * 68];  a1[1] = Qa[24 * 68];
            a1[2] = Qa[16 * 68 + 4]; a1[3] = Qa[24 * 68 + 4];
            #pragma unroll
            for (int jf = 0; jf < 4; jf++) {
                const float* Bb = &sB[(32 * whi + 8 * jf + g) * 68 + kk + t];
                float b0 = Bb[0], b1 = Bb[4];
                mma8(acc[jf],     a0, b0, b1);
                mma8(acc[4 + jf], a1, b0, b1);
            }
        }
    }

    __syncthreads();  // sT aliases sA: all reads of sA must be done

    #pragma unroll
    for (int jf = 0; jf < 4; jf++) {
        const int oc = 32 * whi + 8 * jf + 2 * t;
        const float b0v = __ldg(&bias[oc]);
        const float b1v = __ldg(&bias[oc + 1]);
        #pragma unroll
        for (int fi = 0; fi < 2; fi++) {
            const int r = 32 * wlo + 16 * fi + g;
            const float* d = acc[4 * fi + jf];
            float v00 = f2tf(d[0] + b0v);   // (r,   oc)
            float v01 = f2tf(d[1] + b1v);   // (r,   oc+1)
            float v10 = f2tf(d[2] + b0v);   // (r+8, oc)
            float v11 = f2tf(d[3] + b1v);   // (r+8, oc+1)
            if (ot == 0) {
                g_K[(size_t)(row0 + r) * CR_ + oc]         = v00;
                g_K[(size_t)(row0 + r) * CR_ + oc + 1]     = v01;
                g_K[(size_t)(row0 + r + 8) * CR_ + oc]     = v10;
                g_K[(size_t)(row0 + r + 8) * CR_ + oc + 1] = v11;
            } else if (ot == 1) {
                g_V[(size_t)(row0 + r) * CR_ + oc]         = v00;
                g_V[(size_t)(row0 + r) * CR_ + oc + 1]     = v01;
                g_V[(size_t)(row0 + r + 8) * CR_ + oc]     = v10;
                g_V[(size_t)(row0 + r + 8) * CR_ + oc + 1] = v11;
            } else {
                sT[oc * 132 + r]           = v00;
                sT[(oc + 1) * 132 + r]     = v01;
                sT[oc * 132 + r + 8]       = v10;
                sT[(oc + 1) * 132 + r + 8] = v11;
            }
        }
    }

    if (ot >= 2) {
        __syncthreads();
        const int b  = row0 >> 11;
        const int n0 = row0 & (N_ - 1);
        const size_t qrow0 = (size_t)b * C_ + (ot - 2) * 64;
        #pragma unroll
        for (int l = 0; l < 8; l++) {
            int idx = tid + l * 256;
            int o = idx >> 5, r4 = (idx & 31) << 2;
            float4 v = *(const float4*)&sT[o * 132 + r4];
            *(float4*)&g_Qt[(qrow0 + o) * N_ + n0 + r4] = v;
        }
    }
}

// =======================================================================
// Kernel 2: fused attention (tf32 HMMA).
// CTA: (m-tile 128, c-tile 128, batch). Streams n in tiles of 64:
//   S[n,m] = K @ V^T  (HMMA, M=64,N=128,K=64)
//   P = exp(S) -> smem transposed [m][n]; den[m] += colsum
//   Acc[c,m] += Qt @ P (HMMA, M=128,N=128,K=64)
// Epilogue: out = gamma*Acc/den + x
// =======================================================================
#define ATTN_SMEM_FLOATS (128*68 + 64*68 + 128*68 + 128*68 + 128)
__global__ __launch_bounds__(256, 1) void attn_hmma(
    const float* __restrict__ x, const float* __restrict__ gamma_p,
    float* __restrict__ out)
{
    extern __shared__ float sm[];
    float* sV   = sm;               // [128][68] V tile (m rows), persistent
    float* sK   = sV + 128 * 68;    // [64][68]  K tile (n rows)
    float* sQ   = sK + 64 * 68;     // [128][68] Qt tile (c rows, n cols)
    float* sPT  = sQ + 128 * 68;    // [128][68] P transposed: [m][n]
    float* sDen = sPT + 128 * 68;   // [128]

    const int tid = threadIdx.x;
    const int wid = tid >> 5, lane = tid & 31;
    const int g = lane >> 2, t = lane & 3;
    const int wlo = wid & 3;        // S: n-frag group / G2: c group
    const int whi = wid >> 2;       // m-col group (64 cols each)

    const int mt = blockIdx.x, ct = blockIdx.y, b = blockIdx.z;
    const int m0 = mt * 128, c0 = ct * 128;
    const size_t rb = (size_t)b * N_;
    const size_t qbase = ((size_t)b * C_ + c0) * N_;

    if (tid < 128) sDen[tid] = 0.f;

    // V tile for this m-tile (persistent)
    #pragma unroll
    for (int l = 0; l < 8; l++) {
        int idx = tid + l * 256;
        int r = idx >> 4, c4 = (idx & 15) << 2;
        *(float4*)&sV[r * 68 + c4] = *(const float4*)&g_V[(rb + m0 + r) * CR_ + c4];
    }

    float acc2[16][4];              // [fi*8 + jf][4]  c(32wlo+16fi+g{,+8}) x m(64whi+8jf+2t{,+1})
    #pragma unroll
    for (int i = 0; i < 16; i++)
        #pragma unroll
        for (int j = 0; j < 4; j++) acc2[i][j] = 0.f;
    float den[16];
    #pragma unroll
    for (int i = 0; i < 16; i++) den[i] = 0.f;

    for (int nt = 0; nt < N_ / 64; nt++) {
        const int n0 = nt * 64;
        __syncthreads();
        #pragma unroll
        for (int l = 0; l < 4; l++) {
            int idx = tid + l * 256;
            int r = idx >> 4, c4 = (idx & 15) << 2;
            *(float4*)&sK[r * 68 + c4] = *(const float4*)&g_K[(rb + n0 + r) * CR_ + c4];
        }
        #pragma unroll
        for (int l = 0; l < 8; l++) {
            int idx = tid + l * 256;
            int r = idx >> 4, c4 = (idx & 15) << 2;
            *(float4*)&sQ[r * 68 + c4] = *(const float4*)&g_Qt[qbase + (size_t)r * N_ + n0 + c4];
        }
        __syncthreads();

        // ---- S = K @ V^T ----
        float sacc[8][4];
        #pragma unroll
        for (int i = 0; i < 8; i++)
            #pragma unroll
            for (int j = 0; j < 4; j++) sacc[i][j] = 0.f;

        #pragma unroll
        for (int kk = 0; kk < 64; kk += 8) {
            float a[4];
            const float* Ka = &sK[(16 * wlo + g) * 68 + kk + t];
            a[0] = Ka[0]; a[1] = Ka[8 * 68]; a[2] = Ka[4]; a[3] = Ka[8 * 68 + 4];
            #pragma unroll
            for (int jf = 0; jf < 8; jf++) {
                const float* Vb = &sV[(64 * whi + 8 * jf + g) * 68 + kk + t];
                mma8(sacc[jf], a, Vb[0], Vb[4]);
            }
        }

        // ---- exp -> sPT[m][n], den accumulate ----
        const int nr = 16 * wlo + g;
        #pragma unroll
        for (int jf = 0; jf < 8; jf++) {
            const int mc = 64 * whi + 8 * jf + 2 * t;
            float e00 = f2tf(__expf(sacc[jf][0]));
            float e01 = f2tf(__expf(sacc[jf][1]));
            float e10 = f2tf(__expf(sacc[jf][2]));
            float e11 = f2tf(__expf(sacc[jf][3]));
            den[2 * jf]     += e00 + e10;
            den[2 * jf + 1] += e01 + e11;
            sPT[mc * 68 + nr]           = e00;
            sPT[(mc + 1) * 68 + nr]     = e01;
            sPT[mc * 68 + nr + 8]       = e10;
            sPT[(mc + 1) * 68 + nr + 8] = e11;
        }
        __syncthreads();

        // ---- Acc += Qt @ P ----
        #pragma unroll
        for (int kk = 0; kk < 64; kk += 8) {
            float a0[4], a1[4];
            const float* Qa = &sQ[(32 * wlo + g) * 68 + kk + t];
            a0[0] = Qa[0];           a0[1] = Qa[8 * 68];
            a0[2] = Qa[4];           a0[3] = Qa[8 * 68 + 4];
            a1[0] = Qa[16 * 68];     a1[1] = Qa[24 * 68];
            a1[2] = Qa[16 * 68 + 4]; a1[3] = Qa[24 * 68 + 4];
            #pragma unroll
            for (int jf = 0; jf < 8; jf++) {
                const float* Pb = &sPT[(64 * whi + 8 * jf + g) * 68 + kk + t];
                float b0 = Pb[0], b1 = Pb[4];
                mma8(acc2[jf],     a0, b0, b1);
                mma8(acc2[8 + jf], a1, b0, b1);
            }
        }
    }

    // ---- den reduction (columns owned by (whi, jf, t)) ----
    #pragma unroll
    for (int jf = 0; jf < 8; jf++) {
        const int mc = 64 * whi + 8 * jf + 2 * t;
        atomicAdd(&sDen[mc],     den[2 * jf]);
        atomicAdd(&sDen[mc + 1], den[2 * jf + 1]);
    }
    __syncthreads();

    // ---- epilogue ----
    const float gam = gamma_p[0];
    #pragma unroll
    for (int jf = 0; jf < 8; jf++) {
        const int mc = 64 * whi + 8 * jf + 2 * t;
        const float di0 = gam / sDen[mc];
        const float di1 = gam / sDen[mc + 1];
        #pragma unroll
        for (int fi = 0; fi < 2; fi++) {
            const int cc = c0 + 32 * wlo + 16 * fi + g;
            const size_t r0a = (rb + m0 + mc) * C_ + cc;
            const size_t r1a = (rb + m0 + mc + 1) * C_ + cc;
            const float* d = acc2[8 * fi + jf];
            out[r0a]     = d[0] * di0 + __ldg(&x[r0a]);
            out[r1a]     = d[1] * di1 + __ldg(&x[r1a]);
            out[r0a + 8] = d[2] * di0 + __ldg(&x[r0a + 8]);
            out[r1a + 8] = d[3] * di1 + __ldg(&x[r1a + 8]);
        }
    }
}

// =======================================================================
extern "C" void kernel_launch(void* const* d_in, const int* in_sizes, int n_in,
                              void* d_out, int out_size)
{
    const float* x     = (const float*)d_in[0];
    const float* Wk    = (const float*)d_in[1];
    const float* bk    = (const float*)d_in[2];
    const float* Wv    = (const float*)d_in[3];
    const float* bv    = (const float*)d_in[4];
    const float* Wq    = (const float*)d_in[5];
    const float* bq    = (const float*)d_in[6];
    const float* gamma = (const float*)d_in[7];
    float* out = (float*)d_out;

    const int PROJ_SMEM = PROJ_SMEM_FLOATS * 4;   // 52224 B
    const int ATTN_SMEM = ATTN_SMEM_FLOATS * 4;   // 122368 B
    cudaFuncSetAttribute(proj_hmma, cudaFuncAttributeMaxDynamicSharedMemorySize, PROJ_SMEM);
    cudaFuncSetAttribute(attn_hmma, cudaFuncAttributeMaxDynamicSharedMemorySize, ATTN_SMEM);

    proj_hmma<<<dim3(10, 128), 256, PROJ_SMEM>>>(x, Wk, bk, Wv, bv, Wq, bq);
    attn_hmma<<<dim3(N_ / 128, C_ / 128, B_), 256, ATTN_SMEM>>>(x, gamma, out);
}

// round 4
// speedup vs baseline: 3.0529x; 1.1703x over previous
#include <cuda_runtime.h>
#include <cstdint>

#define B_  8
#define N_  2048
#define C_  512
#define CR_ 64
#define NT_ (N_ / 64)

// Projection outputs. No allocs allowed -> device globals.
__device__ float g_K [(size_t)B_ * N_ * CR_];   // [b*N+n][64]
__device__ float g_V [(size_t)B_ * N_ * CR_];   // [b*N+m][64]
__device__ float g_Qt[(size_t)B_ * C_ * N_];    // [b*C+c][n]

__device__ __forceinline__ uint32_t smem_u32(const void* p) {
    uint32_t a;
    asm("{ .reg .u64 t; cvta.to.shared.u64 t, %1; cvt.u32.u64 %0, t; }" : "=r"(a) : "l"(p));
    return a;
}
__device__ __forceinline__ void cp16(uint32_t dst, const float* src) {
    asm volatile("cp.async.cg.shared.global [%0], [%1], 16;" :: "r"(dst), "l"(src));
}
#define CP_COMMIT() asm volatile("cp.async.commit_group;" ::: "memory")
#define CP_WAIT1()  asm volatile("cp.async.wait_group 1;"  ::: "memory")

// warp mma: D(16x8) += A(16x8) * B(8x8), tf32 inputs, fp32 accum
__device__ __forceinline__ void mma8(float d[4], const float a[4], float b0, float b1) {
    asm volatile(
        "mma.sync.aligned.m16n8k8.row.col.f32.tf32.tf32.f32 "
        "{%0,%1,%2,%3}, {%4,%5,%6,%7}, {%8,%9}, {%0,%1,%2,%3};"
        : "+f"(d[0]), "+f"(d[1]), "+f"(d[2]), "+f"(d[3])
        : "r"(__float_as_uint(a[0])), "r"(__float_as_uint(a[1])),
          "r"(__float_as_uint(a[2])), "r"(__float_as_uint(a[3])),
          "r"(__float_as_uint(b0)),   "r"(__float_as_uint(b1)));
}

// =======================================================================
// Kernel 1: projection GEMM (tf32 HMMA), cp.async depth-3 pipeline.
// grid (10 o-tiles of 64, 128 row-tiles of 128), 256 threads (8 warps).
// o-tile 0 -> K, 1 -> V, 2..9 -> Q cols (ot-2)*64.. (written transposed).
// =======================================================================
#define PA 8704   // 128*68 floats per A buffer
#define PB 4352   // 64*68  floats per B buffer
#define PROJ_SMEM_FLOATS (3*PA + 3*PB)
__global__ __launch_bounds__(256, 1) void proj_hmma(
    const float* __restrict__ x,
    const float* __restrict__ Wk, const float* __restrict__ bk,
    const float* __restrict__ Wv, const float* __restrict__ bv,
    const float* __restrict__ Wq, const float* __restrict__ bq)
{
    extern __shared__ float sm[];
    float* sA = sm;             // 3 x [128][68]
    float* sB = sm + 3 * PA;    // 3 x [64][68]
    float* sT = sm;             // reuse A-buf0: [64][132] transpose staging

    const uint32_t smu = smem_u32(sm);
    const uint32_t sAu = smu, sBu = smu + 3 * PA * 4;

    const int tid = threadIdx.x;
    const int wid = tid >> 5, lane = tid & 31;
    const int g = lane >> 2, t = lane & 3;
    const int wlo = wid & 3;    // row group (32 rows)
    const int whi = wid >> 2;   // o group (32 outs)

    const int ot = blockIdx.x;
    const int row0 = blockIdx.y * 128;

    const float* W; const float* bias;
    if (ot == 0)      { W = Wk; bias = bk; }
    else if (ot == 1) { W = Wv; bias = bv; }
    else              { W = Wq + (size_t)(ot - 2) * 64 * C_; bias = bq + (ot - 2) * 64; }

    // prefetch tiles 0 and 1
    #pragma unroll
    for (int pf = 0; pf < 2; pf++) {
        const int kc = pf * 64;
        const uint32_t ab = sAu + pf * PA * 4, bb = sBu + pf * PB * 4;
        #pragma unroll
        for (int l = 0; l < 8; l++) {
            int idx = tid + l * 256;
            int r = idx >> 4, c4 = (idx & 15) << 2;
            cp16(ab + (r * 68 + c4) * 4, &x[(size_t)(row0 + r) * C_ + kc + c4]);
        }
        #pragma unroll
        for (int l = 0; l < 4; l++) {
            int idx = tid + l * 256;
            int r = idx >> 4, c4 = (idx & 15) << 2;
            cp16(bb + (r * 68 + c4) * 4, &W[(size_t)r * C_ + kc + c4]);
        }
        CP_COMMIT();
    }

    float acc[8][4];
    #pragma unroll
    for (int i = 0; i < 8; i++)
        #pragma unroll
        for (int j = 0; j < 4; j++) acc[i][j] = 0.f;

    for (int it = 0; it < 8; it++) {
        CP_WAIT1();
        __syncthreads();

        if (it + 2 < 8) {
            const int kc = (it + 2) * 64;
            const int pb = (it + 2) % 3;
            const uint32_t ab = sAu + pb * PA * 4, bb = sBu + pb * PB * 4;
            #pragma unroll
            for (int l = 0; l < 8; l++) {
                int idx = tid + l * 256;
                int r = idx >> 4, c4 = (idx & 15) << 2;
                cp16(ab + (r * 68 + c4) * 4, &x[(size_t)(row0 + r) * C_ + kc + c4]);
            }
            #pragma unroll
            for (int l = 0; l < 4; l++) {
                int idx = tid + l * 256;
                int r = idx >> 4, c4 = (idx & 15) << 2;
                cp16(bb + (r * 68 + c4) * 4, &W[(size_t)r * C_ + kc + c4]);
            }
        }
        CP_COMMIT();

        const float* A = sA + (it % 3) * PA;
        const float* Bm = sB + (it % 3) * PB;
        #pragma unroll
        for (int kk = 0; kk < 64; kk += 8) {
            float a0[4], a1[4];
            const float* Qa = &A[(32 * wlo + g) * 68 + kk + t];
            a0[0] = Qa[0];           a0[1] = Qa[8 * 68];
            a0[2] = Qa[4];           a0[3] = Qa[8 * 68 + 4];
            a1[0] = Qa[16 * 68];     a1[1] = Qa[24 * 68];
            a1[2] = Qa[16 * 68 + 4]; a1[3] = Qa[24 * 68 + 4];
            #pragma unroll
            for (int jf = 0; jf < 4; jf++) {
                const float* Bb = &Bm[(32 * whi + 8 * jf + g) * 68 + kk + t];
                float b0 = Bb[0], b1 = Bb[4];
                mma8(acc[jf],     a0, b0, b1);
                mma8(acc[4 + jf], a1, b0, b1);
            }
        }
    }

    __syncthreads();  // sT aliases sA buf0

    #pragma unroll
    for (int jf = 0; jf < 4; jf++) {
        const int oc = 32 * whi + 8 * jf + 2 * t;
        const float b0v = __ldg(&bias[oc]);
        const float b1v = __ldg(&bias[oc + 1]);
        #pragma unroll
        for (int fi = 0; fi < 2; fi++) {
            const int r = 32 * wlo + 16 * fi + g;
            const float* d = acc[4 * fi + jf];
            float v00 = d[0] + b0v;
            float v01 = d[1] + b1v;
            float v10 = d[2] + b0v;
            float v11 = d[3] + b1v;
            if (ot == 0) {
                g_K[(size_t)(row0 + r) * CR_ + oc]         = v00;
                g_K[(size_t)(row0 + r) * CR_ + oc + 1]     = v01;
                g_K[(size_t)(row0 + r + 8) * CR_ + oc]     = v10;
                g_K[(size_t)(row0 + r + 8) * CR_ + oc + 1] = v11;
            } else if (ot == 1) {
                g_V[(size_t)(row0 + r) * CR_ + oc]         = v00;
                g_V[(size_t)(row0 + r) * CR_ + oc + 1]     = v01;
                g_V[(size_t)(row0 + r + 8) * CR_ + oc]     = v10;
                g_V[(size_t)(row0 + r + 8) * CR_ + oc + 1] = v11;
            } else {
                sT[oc * 132 + r]           = v00;
                sT[(oc + 1) * 132 + r]     = v01;
                sT[oc * 132 + r + 8]       = v10;
                sT[(oc + 1) * 132 + r + 8] = v11;
            }
        }
    }

    if (ot >= 2) {
        __syncthreads();
        const int b  = row0 >> 11;
        const int n0 = row0 & (N_ - 1);
        const size_t qrow0 = (size_t)b * C_ + (ot - 2) * 64;
        #pragma unroll
        for (int l = 0; l < 8; l++) {
            int idx = tid + l * 256;
            int o = idx >> 5, r4 = (idx & 31) << 2;
            float4 v = *(const float4*)&sT[o * 132 + r4];
            *(float4*)&g_Qt[(qrow0 + o) * N_ + n0 + r4] = v;
        }
    }
}

// =======================================================================
// Kernel 2: fused attention (tf32 HMMA), cp.async depth-3 pipeline.
// CTA: (m-tile 128, c-tile 128, batch). Streams n in tiles of 64.
// =======================================================================
#define AK 4352   // 64*68 floats per K buffer
#define AQ 8704   // 128*68 floats per Q buffer
#define SV_OFF  0
#define SK_OFF  (SV_OFF + 8704)
#define SQ_OFF  (SK_OFF + 3 * AK)
#define SPT_OFF (SQ_OFF + 3 * AQ)
#define SDEN_OFF (SPT_OFF + 8704)
#define ATTN_SMEM_FLOATS (SDEN_OFF + 128)
__global__ __launch_bounds__(256, 1) void attn_hmma(
    const float* __restrict__ x, const float* __restrict__ gamma_p,
    float* __restrict__ out)
{
    extern __shared__ float sm[];
    float* sV   = sm + SV_OFF;      // [128][68] persistent
    float* sK   = sm + SK_OFF;      // 3 x [64][68]
    float* sQ   = sm + SQ_OFF;      // 3 x [128][68]
    float* sPT  = sm + SPT_OFF;     // [128][68]  P^T [m][n]
    float* sDen = sm + SDEN_OFF;

    const uint32_t smu = smem_u32(sm);
    const uint32_t sVu = smu + SV_OFF * 4;
    const uint32_t sKu = smu + SK_OFF * 4;
    const uint32_t sQu = smu + SQ_OFF * 4;

    const int tid = threadIdx.x;
    const int wid = tid >> 5, lane = tid & 31;
    const int g = lane >> 2, t = lane & 3;
    const int wlo = wid & 3;
    const int whi = wid >> 2;

    const int mt = blockIdx.x, ct = blockIdx.y, b = blockIdx.z;
    const int m0 = mt * 128, c0 = ct * 128;
    const size_t rb = (size_t)b * N_;
    const size_t qbase = ((size_t)b * C_ + c0) * N_;

    if (tid < 128) sDen[tid] = 0.f;

    // ---- group 0: V + K0 + Q0 ----
    #pragma unroll
    for (int l = 0; l < 8; l++) {
        int idx = tid + l * 256;
        int r = idx >> 4, c4 = (idx & 15) << 2;
        cp16(sVu + (r * 68 + c4) * 4, &g_V[(rb + m0 + r) * CR_ + c4]);
    }
    #pragma unroll
    for (int l = 0; l < 4; l++) {
        int idx = tid + l * 256;
        int r = idx >> 4, c4 = (idx & 15) << 2;
        cp16(sKu + (r * 68 + c4) * 4, &g_K[(rb + r) * CR_ + c4]);
    }
    #pragma unroll
    for (int l = 0; l < 8; l++) {
        int idx = tid + l * 256;
        int r = idx >> 4, c4 = (idx & 15) << 2;
        cp16(sQu + (r * 68 + c4) * 4, &g_Qt[qbase + (size_t)r * N_ + c4]);
    }
    CP_COMMIT();
    // ---- group 1: K1 + Q1 ----
    #pragma unroll
    for (int l = 0; l < 4; l++) {
        int idx = tid + l * 256;
        int r = idx >> 4, c4 = (idx & 15) << 2;
        cp16(sKu + AK * 4 + (r * 68 + c4) * 4, &g_K[(rb + 64 + r) * CR_ + c4]);
    }
    #pragma unroll
    for (int l = 0; l < 8; l++) {
        int idx = tid + l * 256;
        int r = idx >> 4, c4 = (idx & 15) << 2;
        cp16(sQu + AQ * 4 + (r * 68 + c4) * 4, &g_Qt[qbase + (size_t)r * N_ + 64 + c4]);
    }
    CP_COMMIT();

    float acc2[16][4];
    #pragma unroll
    for (int i = 0; i < 16; i++)
        #pragma unroll
        for (int j = 0; j < 4; j++) acc2[i][j] = 0.f;
    float den[16];
    #pragma unroll
    for (int i = 0; i < 16; i++) den[i] = 0.f;

    for (int nt = 0; nt < NT_; nt++) {
        CP_WAIT1();
        __syncthreads();

        // prefetch nt+2 into ring buffer (nt+2)%3
        if (nt + 2 < NT_) {
            const int nn = (nt + 2) * 64;
            const int pb = (nt + 2) % 3;
            const uint32_t kb = sKu + pb * AK * 4;
            const uint32_t qb = sQu + pb * AQ * 4;
            #pragma unroll
            for (int l = 0; l < 4; l++) {
                int idx = tid + l * 256;
                int r = idx >> 4, c4 = (idx & 15) << 2;
                cp16(kb + (r * 68 + c4) * 4, &g_K[(rb + nn + r) * CR_ + c4]);
            }
            #pragma unroll
            for (int l = 0; l < 8; l++) {
                int idx = tid + l * 256;
                int r = idx >> 4, c4 = (idx & 15) << 2;
                cp16(qb + (r * 68 + c4) * 4, &g_Qt[qbase + (size_t)r * N_ + nn + c4]);
            }
        }
        CP_COMMIT();

        const float* K = sK + (nt % 3) * AK;
        const float* Q = sQ + (nt % 3) * AQ;

        // ---- S = K @ V^T ----
        float sacc[8][4];
        #pragma unroll
        for (int i = 0; i < 8; i++)
            #pragma unroll
            for (int j = 0; j < 4; j++) sacc[i][j] = 0.f;

        #pragma unroll
        for (int kk = 0; kk < 64; kk += 8) {
            float a[4];
            const float* Ka = &K[(16 * wlo + g) * 68 + kk + t];
            a[0] = Ka[0]; a[1] = Ka[8 * 68]; a[2] = Ka[4]; a[3] = Ka[8 * 68 + 4];
            #pragma unroll
            for (int jf = 0; jf < 8; jf++) {
                const float* Vb = &sV[(64 * whi + 8 * jf + g) * 68 + kk + t];
                mma8(sacc[jf], a, Vb[0], Vb[4]);
            }
        }

        // ---- exp -> sPT[m][n], den accumulate ----
        const int nr = 16 * wlo + g;
        #pragma unroll
        for (int jf = 0; jf < 8; jf++) {
            const int mc = 64 * whi + 8 * jf + 2 * t;
            float e00 = __expf(sacc[jf][0]);
            float e01 = __expf(sacc[jf][1]);
            float e10 = __expf(sacc[jf][2]);
            float e11 = __expf(sacc[jf][3]);
            den[2 * jf]     += e00 + e10;
            den[2 * jf + 1] += e01 + e11;
            sPT[mc * 68 + nr]           = e00;
            sPT[(mc + 1) * 68 + nr]     = e01;
            sPT[mc * 68 + nr + 8]       = e10;
            sPT[(mc + 1) * 68 + nr + 8] = e11;
        }
        __syncthreads();

        // ---- Acc += Qt @ P ----
        #pragma unroll
        for (int kk = 0; kk < 64; kk += 8) {
            float a0[4], a1[4];
            const float* Qa = &Q[(32 * wlo + g) * 68 + kk + t];
            a0[0] = Qa[0];           a0[1] = Qa[8 * 68];
            a0[2] = Qa[4];           a0[3] = Qa[8 * 68 + 4];
            a1[0] = Qa[16 * 68];     a1[1] = Qa[24 * 68];
            a1[2] = Qa[16 * 68 + 4]; a1[3] = Qa[24 * 68 + 4];
            #pragma unroll
            for (int jf = 0; jf < 8; jf++) {
                const float* Pb = &sPT[(64 * whi + 8 * jf + g) * 68 + kk + t];
                float b0 = Pb[0], b1 = Pb[4];
                mma8(acc2[jf],     a0, b0, b1);
                mma8(acc2[8 + jf], a1, b0, b1);
            }
        }
    }

    // ---- den reduction ----
    #pragma unroll
    for (int jf = 0; jf < 8; jf++) {
        const int mc = 64 * whi + 8 * jf + 2 * t;
        atomicAdd(&sDen[mc],     den[2 * jf]);
        atomicAdd(&sDen[mc + 1], den[2 * jf + 1]);
    }
    __syncthreads();

    // ---- epilogue ----
    const float gam = gamma_p[0];
    #pragma unroll
    for (int jf = 0; jf < 8; jf++) {
        const int mc = 64 * whi + 8 * jf + 2 * t;
        const float di0 = gam / sDen[mc];
        const float di1 = gam / sDen[mc + 1];
        #pragma unroll
        for (int fi = 0; fi < 2; fi++) {
            const int cc = c0 + 32 * wlo + 16 * fi + g;
            const size_t r0a = (rb + m0 + mc) * C_ + cc;
            const size_t r1a = (rb + m0 + mc + 1) * C_ + cc;
            const float* d = acc2[8 * fi + jf];
            out[r0a]     = d[0] * di0 + __ldg(&x[r0a]);
            out[r1a]     = d[1] * di1 + __ldg(&x[r1a]);
            out[r0a + 8] = d[2] * di0 + __ldg(&x[r0a + 8]);
            out[r1a + 8] = d[3] * di1 + __ldg(&x[r1a + 8]);
        }
    }
}

// =======================================================================
extern "C" void kernel_launch(void* const* d_in, const int* in_sizes, int n_in,
                              void* d_out, int out_size)
{
    const float* x     = (const float*)d_in[0];
    const float* Wk    = (const float*)d_in[1];
    const float* bk    = (const float*)d_in[2];
    const float* Wv    = (const float*)d_in[3];
    const float* bv    = (const float*)d_in[4];
    const float* Wq    = (const float*)d_in[5];
    const float* bq    = (const float*)d_in[6];
    const float* gamma = (const float*)d_in[7];
    float* out = (float*)d_out;

    const int PROJ_SMEM = PROJ_SMEM_FLOATS * 4;   // 156672 B
    const int ATTN_SMEM = ATTN_SMEM_FLOATS * 4;   // 226816 B
    cudaFuncSetAttribute(proj_hmma, cudaFuncAttributeMaxDynamicSharedMemorySize, PROJ_SMEM);
    cudaFuncSetAttribute(attn_hmma, cudaFuncAttributeMaxDynamicSharedMemorySize, ATTN_SMEM);

    proj_hmma<<<dim3(10, 128), 256, PROJ_SMEM>>>(x, Wk, bk, Wv, bv, Wq, bq);
    attn_hmma<<<dim3(N_ / 128, C_ / 128, B_), 256, ATTN_SMEM>>>(x, gamma, out);
}

// round 5
// speedup vs baseline: 3.3201x; 1.0875x over previous
#include <cuda_runtime.h>
#include <cstdint>

#define B_  8
#define N_  2048
#define C_  512
#define CR_ 64
#define NT_ (N_ / 64)

// Projection outputs. No allocs allowed -> device globals.
__device__ float g_K [(size_t)B_ * N_ * CR_];   // [b*N+n][64]
__device__ float g_V [(size_t)B_ * N_ * CR_];   // [b*N+m][64]
__device__ float g_Qt[(size_t)B_ * C_ * N_];    // [b*C+c][n]

__device__ __forceinline__ uint32_t smem_u32(const void* p) {
    uint32_t a;
    asm("{ .reg .u64 t; cvta.to.shared.u64 t, %1; cvt.u32.u64 %0, t; }" : "=r"(a) : "l"(p));
    return a;
}
__device__ __forceinline__ void cp16(uint32_t dst, const float* src) {
    asm volatile("cp.async.cg.shared.global [%0], [%1], 16;" :: "r"(dst), "l"(src));
}
#define CP_COMMIT() asm volatile("cp.async.commit_group;" ::: "memory")
#define CP_WAIT1()  asm volatile("cp.async.wait_group 1;"  ::: "memory")
#define CP_WAIT2()  asm volatile("cp.async.wait_group 2;"  ::: "memory")

// warp mma: D(16x8) += A(16x8) * B(8x8), tf32 inputs, fp32 accum
__device__ __forceinline__ void mma8(float d[4], const float a[4], float b0, float b1) {
    asm volatile(
        "mma.sync.aligned.m16n8k8.row.col.f32.tf32.tf32.f32 "
        "{%0,%1,%2,%3}, {%4,%5,%6,%7}, {%8,%9}, {%0,%1,%2,%3};"
        : "+f"(d[0]), "+f"(d[1]), "+f"(d[2]), "+f"(d[3])
        : "r"(__float_as_uint(a[0])), "r"(__float_as_uint(a[1])),
          "r"(__float_as_uint(a[2])), "r"(__float_as_uint(a[3])),
          "r"(__float_as_uint(b0)),   "r"(__float_as_uint(b1)));
}

// =======================================================================
// Kernel 1: projection GEMM (tf32 HMMA), cp.async depth-2 ring (occ 2).
// grid (10 o-tiles of 64, 128 row-tiles of 128), 256 threads (8 warps).
// =======================================================================
#define PA 8704   // 128*68 floats per A buffer
#define PB 4352   // 64*68  floats per B buffer
#define PROJ_SMEM_FLOATS (2*PA + 2*PB)
__global__ __launch_bounds__(256, 2) void proj_hmma(
    const float* __restrict__ x,
    const float* __restrict__ Wk, const float* __restrict__ bk,
    const float* __restrict__ Wv, const float* __restrict__ bv,
    const float* __restrict__ Wq, const float* __restrict__ bq)
{
    extern __shared__ float sm[];
    float* sA = sm;             // 2 x [128][68]
    float* sB = sm + 2 * PA;    // 2 x [64][68]
    float* sT = sm;             // reuse A-buf0: [64][132] transpose staging

    const uint32_t smu = smem_u32(sm);
    const uint32_t sAu = smu, sBu = smu + 2 * PA * 4;

    const int tid = threadIdx.x;
    const int wid = tid >> 5, lane = tid & 31;
    const int g = lane >> 2, t = lane & 3;
    const int wlo = wid & 3;
    const int whi = wid >> 2;

    const int ot = blockIdx.x;
    const int row0 = blockIdx.y * 128;

    const float* W; const float* bias;
    if (ot == 0)      { W = Wk; bias = bk; }
    else if (ot == 1) { W = Wv; bias = bv; }
    else              { W = Wq + (size_t)(ot - 2) * 64 * C_; bias = bq + (ot - 2) * 64; }

    // prefetch tiles 0 and 1
    #pragma unroll
    for (int pf = 0; pf < 2; pf++) {
        const int kc = pf * 64;
        const uint32_t ab = sAu + pf * PA * 4, bb = sBu + pf * PB * 4;
        #pragma unroll
        for (int l = 0; l < 8; l++) {
            int idx = tid + l * 256;
            int r = idx >> 4, c4 = (idx & 15) << 2;
            cp16(ab + (r * 68 + c4) * 4, &x[(size_t)(row0 + r) * C_ + kc + c4]);
        }
        #pragma unroll
        for (int l = 0; l < 4; l++) {
            int idx = tid + l * 256;
            int r = idx >> 4, c4 = (idx & 15) << 2;
            cp16(bb + (r * 68 + c4) * 4, &W[(size_t)r * C_ + kc + c4]);
        }
        CP_COMMIT();
    }

    float acc[8][4];
    #pragma unroll
    for (int i = 0; i < 8; i++)
        #pragma unroll
        for (int j = 0; j < 4; j++) acc[i][j] = 0.f;

    for (int it = 0; it < 8; it++) {
        CP_WAIT1();
        __syncthreads();

        const float* A  = sA + (it & 1) * PA;
        const float* Bm = sB + (it & 1) * PB;
        #pragma unroll
        for (int kk = 0; kk < 64; kk += 8) {
            float a0[4], a1[4];
            const float* Qa = &A[(32 * wlo + g) * 68 + kk + t];
            a0[0] = Qa[0];           a0[1] = Qa[8 * 68];
            a0[2] = Qa[4];           a0[3] = Qa[8 * 68 + 4];
            a1[0] = Qa[16 * 68];     a1[1] = Qa[24 * 68];
            a1[2] = Qa[16 * 68 + 4]; a1[3] = Qa[24 * 68 + 4];
            #pragma unroll
            for (int jf = 0; jf < 4; jf++) {
                const float* Bb = &Bm[(32 * whi + 8 * jf + g) * 68 + kk + t];
                float b0 = Bb[0], b1 = Bb[4];
                mma8(acc[jf],     a0, b0, b1);
                mma8(acc[4 + jf], a1, b0, b1);
            }
        }
        __syncthreads();   // all warps done with buffer it&1

        if (it + 2 < 8) {
            const int kc = (it + 2) * 64;
            const uint32_t ab = sAu + (it & 1) * PA * 4, bb = sBu + (it & 1) * PB * 4;
            #pragma unroll
            for (int l = 0; l < 8; l++) {
                int idx = tid + l * 256;
                int r = idx >> 4, c4 = (idx & 15) << 2;
                cp16(ab + (r * 68 + c4) * 4, &x[(size_t)(row0 + r) * C_ + kc + c4]);
            }
            #pragma unroll
            for (int l = 0; l < 4; l++) {
                int idx = tid + l * 256;
                int r = idx >> 4, c4 = (idx & 15) << 2;
                cp16(bb + (r * 68 + c4) * 4, &W[(size_t)r * C_ + kc + c4]);
            }
        }
        CP_COMMIT();
    }

    __syncthreads();  // sT aliases sA buf0

    #pragma unroll
    for (int jf = 0; jf < 4; jf++) {
        const int oc = 32 * whi + 8 * jf + 2 * t;
        const float b0v = __ldg(&bias[oc]);
        const float b1v = __ldg(&bias[oc + 1]);
        #pragma unroll
        for (int fi = 0; fi < 2; fi++) {
            const int r = 32 * wlo + 16 * fi + g;
            const float* d = acc[4 * fi + jf];
            float v00 = d[0] + b0v;
            float v01 = d[1] + b1v;
            float v10 = d[2] + b0v;
            float v11 = d[3] + b1v;
            if (ot == 0) {
                g_K[(size_t)(row0 + r) * CR_ + oc]         = v00;
                g_K[(size_t)(row0 + r) * CR_ + oc + 1]     = v01;
                g_K[(size_t)(row0 + r + 8) * CR_ + oc]     = v10;
                g_K[(size_t)(row0 + r + 8) * CR_ + oc + 1] = v11;
            } else if (ot == 1) {
                g_V[(size_t)(row0 + r) * CR_ + oc]         = v00;
                g_V[(size_t)(row0 + r) * CR_ + oc + 1]     = v01;
                g_V[(size_t)(row0 + r + 8) * CR_ + oc]     = v10;
                g_V[(size_t)(row0 + r + 8) * CR_ + oc + 1] = v11;
            } else {
                sT[oc * 132 + r]           = v00;
                sT[(oc + 1) * 132 + r]     = v01;
                sT[oc * 132 + r + 8]       = v10;
                sT[(oc + 1) * 132 + r + 8] = v11;
            }
        }
    }

    if (ot >= 2) {
        __syncthreads();
        const int b  = row0 >> 11;
        const int n0 = row0 & (N_ - 1);
        const size_t qrow0 = (size_t)b * C_ + (ot - 2) * 64;
        #pragma unroll
        for (int l = 0; l < 8; l++) {
            int idx = tid + l * 256;
            int o = idx >> 5, r4 = (idx & 31) << 2;
            float4 v = *(const float4*)&sT[o * 132 + r4];
            *(float4*)&g_Qt[(qrow0 + o) * N_ + n0 + r4] = v;
        }
    }
}

// =======================================================================
// Kernel 2: fused attention (tf32 HMMA), occupancy-2 design.
// CTA: (m-tile 64, c-tile 128, batch), 256 threads, 102 KB smem.
// K ring-2 via cp.async; Q single-buffered (loaded during MMA1+exp).
// =======================================================================
#define AK 4352   // 64*68 floats per K buffer
#define SV_OFF   0
#define SK_OFF   (SV_OFF + 4352)        // 2 x AK
#define SQ_OFF   (SK_OFF + 2 * AK)      // [128][68]
#define SPT_OFF  (SQ_OFF + 8704)        // [64][68]
#define SDEN_OFF (SPT_OFF + 4352)       // [64]
#define ATTN_SMEM_FLOATS (SDEN_OFF + 64)
__global__ __launch_bounds__(256, 2) void attn_hmma(
    const float* __restrict__ x, const float* __restrict__ gamma_p,
    float* __restrict__ out)
{
    extern __shared__ float sm[];
    float* sV   = sm + SV_OFF;      // [64][68] persistent
    float* sK   = sm + SK_OFF;      // 2 x [64][68]
    float* sQ   = sm + SQ_OFF;      // [128][68] single buffer
    float* sPT  = sm + SPT_OFF;     // [64][68]  P^T [m][n]
    float* sDen = sm + SDEN_OFF;

    const uint32_t smu = smem_u32(sm);
    const uint32_t sVu = smu + SV_OFF * 4;
    const uint32_t sKu = smu + SK_OFF * 4;
    const uint32_t sQu = smu + SQ_OFF * 4;

    const int tid = threadIdx.x;
    const int wid = tid >> 5, lane = tid & 31;
    const int g = lane >> 2, t = lane & 3;
    const int wlo = wid & 3;        // MMA1: n group (16) / MMA2: c group (32)
    const int whi = wid >> 2;       // m group (32)

    const int mt = blockIdx.x, ct = blockIdx.y, b = blockIdx.z;
    const int m0 = mt * 64, c0 = ct * 128;
    const size_t rb = (size_t)b * N_;
    const size_t qbase = ((size_t)b * C_ + c0) * N_;

    if (tid < 64) sDen[tid] = 0.f;

    // ---- group 0: V + K0; group 1: K1 ----
    #pragma unroll
    for (int l = 0; l < 4; l++) {
        int idx = tid + l * 256;
        int r = idx >> 4, c4 = (idx & 15) << 2;
        cp16(sVu + (r * 68 + c4) * 4, &g_V[(rb + m0 + r) * CR_ + c4]);
        cp16(sKu + (r * 68 + c4) * 4, &g_K[(rb + r) * CR_ + c4]);
    }
    CP_COMMIT();
    #pragma unroll
    for (int l = 0; l < 4; l++) {
        int idx = tid + l * 256;
        int r = idx >> 4, c4 = (idx & 15) << 2;
        cp16(sKu + AK * 4 + (r * 68 + c4) * 4, &g_K[(rb + 64 + r) * CR_ + c4]);
    }
    CP_COMMIT();

    float acc2[8][4];               // [fi*4+jf][4]
    #pragma unroll
    for (int i = 0; i < 8; i++)
        #pragma unroll
        for (int j = 0; j < 4; j++) acc2[i][j] = 0.f;
    float den[8];
    #pragma unroll
    for (int i = 0; i < 8; i++) den[i] = 0.f;

    for (int nt = 0; nt < NT_; nt++) {
        const int n0 = nt * 64;

        // issue Q(nt) into single buffer (prev MMA2 done: end-of-iter barrier)
        #pragma unroll
        for (int l = 0; l < 8; l++) {
            int idx = tid + l * 256;
            int r = idx >> 4, c4 = (idx & 15) << 2;
            cp16(sQu + (r * 68 + c4) * 4, &g_Qt[qbase + (size_t)r * N_ + n0 + c4]);
        }
        CP_COMMIT();

        // ensure K(nt) (+V) complete and visible
        CP_WAIT2();
        __syncthreads();

        const float* K = sK + (nt & 1) * AK;

        // ---- MMA1: S[n 64][m 64] = K @ V^T ----
        float sacc[4][4];
        #pragma unroll
        for (int i = 0; i < 4; i++)
            #pragma unroll
            for (int j = 0; j < 4; j++) sacc[i][j] = 0.f;

        #pragma unroll
        for (int kk = 0; kk < 64; kk += 8) {
            float a[4];
            const float* Ka = &K[(16 * wlo + g) * 68 + kk + t];
            a[0] = Ka[0]; a[1] = Ka[8 * 68]; a[2] = Ka[4]; a[3] = Ka[8 * 68 + 4];
            #pragma unroll
            for (int jf = 0; jf < 4; jf++) {
                const float* Vb = &sV[(32 * whi + 8 * jf + g) * 68 + kk + t];
                mma8(sacc[jf], a, Vb[0], Vb[4]);
            }
        }

        // ---- exp -> sPT[m][n], den accumulate ----
        const int nr = 16 * wlo + g;
        #pragma unroll
        for (int jf = 0; jf < 4; jf++) {
            const int mc = 32 * whi + 8 * jf + 2 * t;
            float e00 = __expf(sacc[jf][0]);
            float e01 = __expf(sacc[jf][1]);
            float e10 = __expf(sacc[jf][2]);
            float e11 = __expf(sacc[jf][3]);
            den[2 * jf]     += e00 + e10;
            den[2 * jf + 1] += e01 + e11;
            sPT[mc * 68 + nr]           = e00;
            sPT[(mc + 1) * 68 + nr]     = e01;
            sPT[mc * 68 + nr + 8]       = e10;
            sPT[(mc + 1) * 68 + nr + 8] = e11;
        }
        __syncthreads();   // sPT ready; all warps past MMA1 (K(nt) reads done)

        // prefetch K(nt+2) into buffer (nt&1) — just freed
        if (nt + 2 < NT_) {
            const int nn = (nt + 2) * 64;
            const uint32_t kb = sKu + (nt & 1) * AK * 4;
            #pragma unroll
            for (int l = 0; l < 4; l++) {
                int idx = tid + l * 256;
                int r = idx >> 4, c4 = (idx & 15) << 2;
                cp16(kb + (r * 68 + c4) * 4, &g_K[(rb + nn + r) * CR_ + c4]);
            }
        }
        CP_COMMIT();

        // Q(nt) and K(nt+1) complete + visible
        CP_WAIT1();
        __syncthreads();

        // ---- MMA2: Acc[c 128][m 64] += Qt @ P ----
        #pragma unroll
        for (int kk = 0; kk < 64; kk += 8) {
            float a0[4], a1[4];
            const float* Qa = &sQ[(32 * wlo + g) * 68 + kk + t];
            a0[0] = Qa[0];           a0[1] = Qa[8 * 68];
            a0[2] = Qa[4];           a0[3] = Qa[8 * 68 + 4];
            a1[0] = Qa[16 * 68];     a1[1] = Qa[24 * 68];
            a1[2] = Qa[16 * 68 + 4]; a1[3] = Qa[24 * 68 + 4];
            #pragma unroll
            for (int jf = 0; jf < 4; jf++) {
                const float* Pb = &sPT[(32 * whi + 8 * jf + g) * 68 + kk + t];
                float b0 = Pb[0], b1 = Pb[4];
                mma8(acc2[jf],     a0, b0, b1);
                mma8(acc2[4 + jf], a1, b0, b1);
            }
        }
        __syncthreads();   // protect Q & sPT for next iteration
    }

    // ---- den reduction ----
    #pragma unroll
    for (int jf = 0; jf < 4; jf++) {
        const int mc = 32 * whi + 8 * jf + 2 * t;
        atomicAdd(&sDen[mc],     den[2 * jf]);
        atomicAdd(&sDen[mc + 1], den[2 * jf + 1]);
    }
    __syncthreads();

    // ---- epilogue ----
    const float gam = gamma_p[0];
    #pragma unroll
    for (int jf = 0; jf < 4; jf++) {
        const int mc = 32 * whi + 8 * jf + 2 * t;
        const float di0 = gam / sDen[mc];
        const float di1 = gam / sDen[mc + 1];
        #pragma unroll
        for (int fi = 0; fi < 2; fi++) {
            const int cc = c0 + 32 * wlo + 16 * fi + g;
            const size_t r0a = (rb + m0 + mc) * C_ + cc;
            const size_t r1a = (rb + m0 + mc + 1) * C_ + cc;
            const float* d = acc2[4 * fi + jf];
            out[r0a]     = d[0] * di0 + __ldg(&x[r0a]);
            out[r1a]     = d[1] * di1 + __ldg(&x[r1a]);
            out[r0a + 8] = d[2] * di0 + __ldg(&x[r0a + 8]);
            out[r1a + 8] = d[3] * di1 + __ldg(&x[r1a + 8]);
        }
    }
}

// =======================================================================
extern "C" void kernel_launch(void* const* d_in, const int* in_sizes, int n_in,
                              void* d_out, int out_size)
{
    const float* x     = (const float*)d_in[0];
    const float* Wk    = (const float*)d_in[1];
    const float* bk    = (const float*)d_in[2];
    const float* Wv    = (const float*)d_in[3];
    const float* bv    = (const float*)d_in[4];
    const float* Wq    = (const float*)d_in[5];
    const float* bq    = (const float*)d_in[6];
    const float* gamma = (const float*)d_in[7];
    float* out = (float*)d_out;

    const int PROJ_SMEM = PROJ_SMEM_FLOATS * 4;   // 104448 B
    const int ATTN_SMEM = ATTN_SMEM_FLOATS * 4;   // 104960 B
    cudaFuncSetAttribute(proj_hmma, cudaFuncAttributeMaxDynamicSharedMemorySize, PROJ_SMEM);
    cudaFuncSetAttribute(attn_hmma, cudaFuncAttributeMaxDynamicSharedMemorySize, ATTN_SMEM);

    proj_hmma<<<dim3(10, 128), 256, PROJ_SMEM>>>(x, Wk, bk, Wv, bv, Wq, bq);
    attn_hmma<<<dim3(N_ / 64, C_ / 128, B_), 256, ATTN_SMEM>>>(x, gamma, out);
}

// round 6
// speedup vs baseline: 5.0230x; 1.5129x over previous
#include <cuda_runtime.h>
#include <cuda_bf16.h>
#include <cstdint>

#define B_  8
#define N_  2048
#define C_  512
#define CR_ 64
#define NT_ (N_ / 64)

// Projection outputs (bf16). No allocs allowed -> device globals.
__device__ __nv_bfloat16 g_K [(size_t)B_ * N_ * CR_];   // [b*N+n][64]
__device__ __nv_bfloat16 g_V [(size_t)B_ * N_ * CR_];   // [b*N+m][64]
__device__ __nv_bfloat16 g_Qt[(size_t)B_ * C_ * N_];    // [b*C+c][n]

__device__ __forceinline__ uint32_t smem_u32(const void* p) {
    uint32_t a;
    asm("{ .reg .u64 t; cvta.to.shared.u64 t, %1; cvt.u32.u64 %0, t; }" : "=r"(a) : "l"(p));
    return a;
}
__device__ __forceinline__ void cp16(uint32_t dst, const void* src) {
    asm volatile("cp.async.cg.shared.global [%0], [%1], 16;" :: "r"(dst), "l"(src));
}
#define CP_COMMIT() asm volatile("cp.async.commit_group;" ::: "memory")
#define CP_WAIT1()  asm volatile("cp.async.wait_group 1;"  ::: "memory")
#define CP_WAIT2()  asm volatile("cp.async.wait_group 2;"  ::: "memory")

// tf32 warp mma (projection): D(16x8) += A(16x8)*B(8x8)
__device__ __forceinline__ void mma8(float d[4], const float a[4], float b0, float b1) {
    asm volatile(
        "mma.sync.aligned.m16n8k8.row.col.f32.tf32.tf32.f32 "
        "{%0,%1,%2,%3}, {%4,%5,%6,%7}, {%8,%9}, {%0,%1,%2,%3};"
        : "+f"(d[0]), "+f"(d[1]), "+f"(d[2]), "+f"(d[3])
        : "r"(__float_as_uint(a[0])), "r"(__float_as_uint(a[1])),
          "r"(__float_as_uint(a[2])), "r"(__float_as_uint(a[3])),
          "r"(__float_as_uint(b0)),   "r"(__float_as_uint(b1)));
}
// bf16 warp mma: D(16x8) += A(16x16)*B(16x8)
__device__ __forceinline__ void mma16(float d[4], const uint32_t a[4], uint32_t b0, uint32_t b1) {
    asm volatile(
        "mma.sync.aligned.m16n8k16.row.col.f32.bf16.bf16.f32 "
        "{%0,%1,%2,%3}, {%4,%5,%6,%7}, {%8,%9}, {%0,%1,%2,%3};"
        : "+f"(d[0]), "+f"(d[1]), "+f"(d[2]), "+f"(d[3])
        : "r"(a[0]), "r"(a[1]), "r"(a[2]), "r"(a[3]), "r"(b0), "r"(b1));
}
__device__ __forceinline__ void ldm4(uint32_t r[4], uint32_t addr) {
    asm volatile("ldmatrix.sync.aligned.m8n8.x4.shared.b16 {%0,%1,%2,%3}, [%4];"
        : "=r"(r[0]), "=r"(r[1]), "=r"(r[2]), "=r"(r[3]) : "r"(addr));
}

// =======================================================================
// Kernel 1: projection GEMM (tf32 HMMA), cp.async depth-2 ring (occ 2).
// grid (10 o-tiles of 64, 128 row-tiles of 128), 256 threads.
// Outputs stored bf16: ot0->K, ot1->V, ot2..9 -> Qt (transposed).
// =======================================================================
#define PA 8704   // 128*68 floats per A buffer
#define PB 4352   // 64*68  floats per B buffer
#define PROJ_SMEM_FLOATS (2*PA + 2*PB)
__global__ __launch_bounds__(256, 2) void proj_hmma(
    const float* __restrict__ x,
    const float* __restrict__ Wk, const float* __restrict__ bk,
    const float* __restrict__ Wv, const float* __restrict__ bv,
    const float* __restrict__ Wq, const float* __restrict__ bq)
{
    extern __shared__ float sm[];
    float* sA = sm;             // 2 x [128][68]
    float* sB = sm + 2 * PA;    // 2 x [64][68]
    float* sT = sm;             // reuse A-buf0: [64][132] fp32 staging (Q path)

    const uint32_t smu = smem_u32(sm);
    const uint32_t sAu = smu, sBu = smu + 2 * PA * 4;

    const int tid = threadIdx.x;
    const int wid = tid >> 5, lane = tid & 31;
    const int g = lane >> 2, t = lane & 3;
    const int wlo = wid & 3;
    const int whi = wid >> 2;

    const int ot = blockIdx.x;
    const int row0 = blockIdx.y * 128;

    const float* W; const float* bias;
    if (ot == 0)      { W = Wk; bias = bk; }
    else if (ot == 1) { W = Wv; bias = bv; }
    else              { W = Wq + (size_t)(ot - 2) * 64 * C_; bias = bq + (ot - 2) * 64; }

    #pragma unroll
    for (int pf = 0; pf < 2; pf++) {
        const int kc = pf * 64;
        const uint32_t ab = sAu + pf * PA * 4, bb = sBu + pf * PB * 4;
        #pragma unroll
        for (int l = 0; l < 8; l++) {
            int idx = tid + l * 256;
            int r = idx >> 4, c4 = (idx & 15) << 2;
            cp16(ab + (r * 68 + c4) * 4, &x[(size_t)(row0 + r) * C_ + kc + c4]);
        }
        #pragma unroll
        for (int l = 0; l < 4; l++) {
            int idx = tid + l * 256;
            int r = idx >> 4, c4 = (idx & 15) << 2;
            cp16(bb + (r * 68 + c4) * 4, &W[(size_t)r * C_ + kc + c4]);
        }
        CP_COMMIT();
    }

    float acc[8][4];
    #pragma unroll
    for (int i = 0; i < 8; i++)
        #pragma unroll
        for (int j = 0; j < 4; j++) acc[i][j] = 0.f;

    for (int it = 0; it < 8; it++) {
        CP_WAIT1();
        __syncthreads();

        const float* A  = sA + (it & 1) * PA;
        const float* Bm = sB + (it & 1) * PB;
        #pragma unroll
        for (int kk = 0; kk < 64; kk += 8) {
            float a0[4], a1[4];
            const float* Qa = &A[(32 * wlo + g) * 68 + kk + t];
            a0[0] = Qa[0];           a0[1] = Qa[8 * 68];
            a0[2] = Qa[4];           a0[3] = Qa[8 * 68 + 4];
            a1[0] = Qa[16 * 68];     a1[1] = Qa[24 * 68];
            a1[2] = Qa[16 * 68 + 4]; a1[3] = Qa[24 * 68 + 4];
            #pragma unroll
            for (int jf = 0; jf < 4; jf++) {
                const float* Bb = &Bm[(32 * whi + 8 * jf + g) * 68 + kk + t];
                float b0 = Bb[0], b1 = Bb[4];
                mma8(acc[jf],     a0, b0, b1);
                mma8(acc[4 + jf], a1, b0, b1);
            }
        }
        __syncthreads();

        if (it + 2 < 8) {
            const int kc = (it + 2) * 64;
            const uint32_t ab = sAu + (it & 1) * PA * 4, bb = sBu + (it & 1) * PB * 4;
            #pragma unroll
            for (int l = 0; l < 8; l++) {
                int idx = tid + l * 256;
                int r = idx >> 4, c4 = (idx & 15) << 2;
                cp16(ab + (r * 68 + c4) * 4, &x[(size_t)(row0 + r) * C_ + kc + c4]);
            }
            #pragma unroll
            for (int l = 0; l < 4; l++) {
                int idx = tid + l * 256;
                int r = idx >> 4, c4 = (idx & 15) << 2;
                cp16(bb + (r * 68 + c4) * 4, &W[(size_t)r * C_ + kc + c4]);
            }
        }
        CP_COMMIT();
    }

    __syncthreads();  // sT aliases sA buf0

    #pragma unroll
    for (int jf = 0; jf < 4; jf++) {
        const int oc = 32 * whi + 8 * jf + 2 * t;
        const float b0v = __ldg(&bias[oc]);
        const float b1v = __ldg(&bias[oc + 1]);
        #pragma unroll
        for (int fi = 0; fi < 2; fi++) {
            const int r = 32 * wlo + 16 * fi + g;
            const float* d = acc[4 * fi + jf];
            float v00 = d[0] + b0v;
            float v01 = d[1] + b1v;
            float v10 = d[2] + b0v;
            float v11 = d[3] + b1v;
            if (ot == 0) {
                g_K[(size_t)(row0 + r) * CR_ + oc]         = __float2bfloat16_rn(v00);
                g_K[(size_t)(row0 + r) * CR_ + oc + 1]     = __float2bfloat16_rn(v01);
                g_K[(size_t)(row0 + r + 8) * CR_ + oc]     = __float2bfloat16_rn(v10);
                g_K[(size_t)(row0 + r + 8) * CR_ + oc + 1] = __float2bfloat16_rn(v11);
            } else if (ot == 1) {
                g_V[(size_t)(row0 + r) * CR_ + oc]         = __float2bfloat16_rn(v00);
                g_V[(size_t)(row0 + r) * CR_ + oc + 1]     = __float2bfloat16_rn(v01);
                g_V[(size_t)(row0 + r + 8) * CR_ + oc]     = __float2bfloat16_rn(v10);
                g_V[(size_t)(row0 + r + 8) * CR_ + oc + 1] = __float2bfloat16_rn(v11);
            } else {
                sT[oc * 132 + r]           = v00;
                sT[(oc + 1) * 132 + r]     = v01;
                sT[oc * 132 + r + 8]       = v10;
                sT[(oc + 1) * 132 + r + 8] = v11;
            }
        }
    }

    if (ot >= 2) {
        __syncthreads();
        const int b  = row0 >> 11;
        const int n0 = row0 & (N_ - 1);
        const size_t qrow0 = (size_t)b * C_ + (ot - 2) * 64;
        #pragma unroll
        for (int l = 0; l < 8; l++) {
            int idx = tid + l * 256;
            int o = idx >> 5, r4 = (idx & 31) << 2;
            float4 v = *(const float4*)&sT[o * 132 + r4];
            __nv_bfloat162 p0 = __floats2bfloat162_rn(v.x, v.y);
            __nv_bfloat162 p1 = __floats2bfloat162_rn(v.z, v.w);
            __nv_bfloat162* dst = (__nv_bfloat162*)&g_Qt[(qrow0 + o) * N_ + n0 + r4];
            dst[0] = p0; dst[1] = p1;
        }
    }
}

// =======================================================================
// Kernel 2: fused attention (bf16 HMMA + ldmatrix), occ 2.
// CTA: (m-tile 64, c-tile 128, batch), 256 threads, ~55 KB smem.
// Tile pitch: 72 bf16 (144 B) -> conflict-free ldmatrix.
// =======================================================================
#define PITCH 72
#define KVB   (64 * PITCH * 2)          // bytes per 64-row bf16 tile: 9216
#define SV_B   0
#define SK_B   (SV_B + KVB)             // 2 buffers
#define SQ_B   (SK_B + 2 * KVB)         // 128 rows: 18432 B
#define SPT_B  (SQ_B + 128 * PITCH * 2)
#define SDEN_B (SPT_B + KVB)
#define ATTN_SMEM_BYTES (SDEN_B + 256)
__global__ __launch_bounds__(256, 2) void attn_hmma(
    const float* __restrict__ x, const float* __restrict__ gamma_p,
    float* __restrict__ out)
{
    extern __shared__ char smc[];
    __nv_bfloat16* sPT16 = (__nv_bfloat16*)(smc + SPT_B);
    float* sDen = (float*)(smc + SDEN_B);

    const uint32_t smu = smem_u32(smc);
    const uint32_t sVu = smu + SV_B;
    const uint32_t sKu = smu + SK_B;
    const uint32_t sQu = smu + SQ_B;
    const uint32_t sPu = smu + SPT_B;

    const int tid = threadIdx.x;
    const int wid = tid >> 5, lane = tid & 31;
    const int g = lane >> 2, t = lane & 3;
    const int wlo = wid & 3;        // MMA1: n group(16) / MMA2: c group(32)
    const int whi = wid >> 2;       // m group (32)
    const int lrow = lane & 15;
    const int lcol = (lane >> 4) << 3;

    const int mt = blockIdx.x, ct = blockIdx.y, b = blockIdx.z;
    const int m0 = mt * 64, c0 = ct * 128;
    const size_t rb = (size_t)b * N_;
    const size_t qbase = ((size_t)b * C_ + c0) * N_;

    if (tid < 64) sDen[tid] = 0.f;

    // group 0: V + K0 ; group 1: K1   (64 rows x 8 16B-chunks each)
    #pragma unroll
    for (int l = 0; l < 2; l++) {
        int idx = tid + l * 256;
        int r = idx >> 3, ch = idx & 7;
        cp16(sVu + r * 144 + ch * 16, &g_V[(rb + m0 + r) * CR_ + ch * 8]);
        cp16(sKu + r * 144 + ch * 16, &g_K[(rb + r) * CR_ + ch * 8]);
    }
    CP_COMMIT();
    #pragma unroll
    for (int l = 0; l < 2; l++) {
        int idx = tid + l * 256;
        int r = idx >> 3, ch = idx & 7;
        cp16(sKu + KVB + r * 144 + ch * 16, &g_K[(rb + 64 + r) * CR_ + ch * 8]);
    }
    CP_COMMIT();

    float acc2[8][4];
    #pragma unroll
    for (int i = 0; i < 8; i++)
        #pragma unroll
        for (int j = 0; j < 4; j++) acc2[i][j] = 0.f;
    float den[8];
    #pragma unroll
    for (int i = 0; i < 8; i++) den[i] = 0.f;

    for (int nt = 0; nt < NT_; nt++) {
        const int n0 = nt * 64;

        // Q(nt) into single buffer (prev MMA2 done at end-of-iter barrier)
        #pragma unroll
        for (int l = 0; l < 4; l++) {
            int idx = tid + l * 256;
            int r = idx >> 3, ch = idx & 7;
            cp16(sQu + r * 144 + ch * 16, &g_Qt[qbase + (size_t)r * N_ + n0 + ch * 8]);
        }
        CP_COMMIT();

        CP_WAIT2();              // K(nt) (+V) complete
        __syncthreads();

        const uint32_t Kb = sKu + (nt & 1) * KVB;

        // ---- MMA1: S[n 64][m 64] = K @ V^T ----
        float sacc[4][4];
        #pragma unroll
        for (int i = 0; i < 4; i++)
            #pragma unroll
            for (int j = 0; j < 4; j++) sacc[i][j] = 0.f;

        #pragma unroll
        for (int kk = 0; kk < 64; kk += 16) {
            uint32_t a[4], bv0[4], bv1[4];
            ldm4(a,   Kb  + ((16 * wlo + lrow) * PITCH + kk + lcol) * 2);
            ldm4(bv0, sVu + ((32 * whi + lrow) * PITCH + kk + lcol) * 2);
            ldm4(bv1, sVu + ((32 * whi + 16 + lrow) * PITCH + kk + lcol) * 2);
            mma16(sacc[0], a, bv0[0], bv0[2]);
            mma16(sacc[1], a, bv0[1], bv0[3]);
            mma16(sacc[2], a, bv1[0], bv1[2]);
            mma16(sacc[3], a, bv1[1], bv1[3]);
        }

        // ---- exp -> sPT[m][n] (bf16), den accumulate ----
        const int nr = 16 * wlo + g;
        #pragma unroll
        for (int jf = 0; jf < 4; jf++) {
            const int mc = 32 * whi + 8 * jf + 2 * t;
            float e00 = __expf(sacc[jf][0]);
            float e01 = __expf(sacc[jf][1]);
            float e10 = __expf(sacc[jf][2]);
            float e11 = __expf(sacc[jf][3]);
            den[2 * jf]     += e00 + e10;
            den[2 * jf + 1] += e01 + e11;
            sPT16[mc * PITCH + nr]           = __float2bfloat16_rn(e00);
            sPT16[(mc + 1) * PITCH + nr]     = __float2bfloat16_rn(e01);
            sPT16[mc * PITCH + nr + 8]       = __float2bfloat16_rn(e10);
            sPT16[(mc + 1) * PITCH + nr + 8] = __float2bfloat16_rn(e11);
        }
        __syncthreads();   // sPT ready; K(nt) reads done

        // prefetch K(nt+2) into freed buffer
        if (nt + 2 < NT_) {
            const int nn = (nt + 2) * 64;
            const uint32_t kb = sKu + (nt & 1) * KVB;
            #pragma unroll
            for (int l = 0; l < 2; l++) {
                int idx = tid + l * 256;
                int r = idx >> 3, ch = idx & 7;
                cp16(kb + r * 144 + ch * 16, &g_K[(rb + nn + r) * CR_ + ch * 8]);
            }
        }
        CP_COMMIT();

        CP_WAIT1();              // Q(nt), K(nt+1) complete
        __syncthreads();

        // ---- MMA2: Acc[c 128][m 64] += Qt @ P ----
        #pragma unroll
        for (int kk = 0; kk < 64; kk += 16) {
            uint32_t a0[4], a1[4], p0[4], p1[4];
            ldm4(a0, sQu + ((32 * wlo + lrow) * PITCH + kk + lcol) * 2);
            ldm4(a1, sQu + ((32 * wlo + 16 + lrow) * PITCH + kk + lcol) * 2);
            ldm4(p0, sPu + ((32 * whi + lrow) * PITCH + kk + lcol) * 2);
            ldm4(p1, sPu + ((32 * whi + 16 + lrow) * PITCH + kk + lcol) * 2);
            mma16(acc2[0], a0, p0[0], p0[2]);
            mma16(acc2[1], a0, p0[1], p0[3]);
            mma16(acc2[2], a0, p1[0], p1[2]);
            mma16(acc2[3], a0, p1[1], p1[3]);
            mma16(acc2[4], a1, p0[0], p0[2]);
            mma16(acc2[5], a1, p0[1], p0[3]);
            mma16(acc2[6], a1, p1[0], p1[2]);
            mma16(acc2[7], a1, p1[1], p1[3]);
        }
        __syncthreads();   // protect Q & sPT for next iteration
    }

    // ---- den reduction ----
    #pragma unroll
    for (int jf = 0; jf < 4; jf++) {
        const int mc = 32 * whi + 8 * jf + 2 * t;
        atomicAdd(&sDen[mc],     den[2 * jf]);
        atomicAdd(&sDen[mc + 1], den[2 * jf + 1]);
    }
    __syncthreads();

    // ---- epilogue: out = gamma*Acc/den + x ----
    const float gam = gamma_p[0];
    #pragma unroll
    for (int jf = 0; jf < 4; jf++) {
        const int mc = 32 * whi + 8 * jf + 2 * t;
        const float di0 = gam / sDen[mc];
        const float di1 = gam / sDen[mc + 1];
        #pragma unroll
        for (int fi = 0; fi < 2; fi++) {
            const int cc = c0 + 32 * wlo + 16 * fi + g;
            const size_t r0a = (rb + m0 + mc) * C_ + cc;
            const size_t r1a = (rb + m0 + mc + 1) * C_ + cc;
            const float* d = acc2[4 * fi + jf];
            out[r0a]     = d[0] * di0 + __ldg(&x[r0a]);
            out[r1a]     = d[1] * di1 + __ldg(&x[r1a]);
            out[r0a + 8] = d[2] * di0 + __ldg(&x[r0a + 8]);
            out[r1a + 8] = d[3] * di1 + __ldg(&x[r1a + 8]);
        }
    }
}

// =======================================================================
extern "C" void kernel_launch(void* const* d_in, const int* in_sizes, int n_in,
                              void* d_out, int out_size)
{
    const float* x     = (const float*)d_in[0];
    const float* Wk    = (const float*)d_in[1];
    const float* bk    = (const float*)d_in[2];
    const float* Wv    = (const float*)d_in[3];
    const float* bv    = (const float*)d_in[4];
    const float* Wq    = (const float*)d_in[5];
    const float* bq    = (const float*)d_in[6];
    const float* gamma = (const float*)d_in[7];
    float* out = (float*)d_out;

    const int PROJ_SMEM = PROJ_SMEM_FLOATS * 4;   // 104448 B
    cudaFuncSetAttribute(proj_hmma, cudaFuncAttributeMaxDynamicSharedMemorySize, PROJ_SMEM);
    cudaFuncSetAttribute(attn_hmma, cudaFuncAttributeMaxDynamicSharedMemorySize, ATTN_SMEM_BYTES);

    proj_hmma<<<dim3(10, 128), 256, PROJ_SMEM>>>(x, Wk, bk, Wv, bv, Wq, bq);
    attn_hmma<<<dim3(N_ / 64, C_ / 128, B_), 256, ATTN_SMEM_BYTES>>>(x, gamma, out);
}

// round 7
// speedup vs baseline: 5.8278x; 1.1602x over previous
#include <cuda_runtime.h>
#include <cuda_bf16.h>
#include <cstdint>

#define B_  8
#define N_  2048
#define C_  512
#define CR_ 64

// Device-global scratch (no allocs allowed).
__device__ __nv_bfloat16 g_K [(size_t)B_ * N_ * CR_];   // [b*N+n][64]
__device__ __nv_bfloat16 g_V [(size_t)B_ * N_ * CR_];   // [b*N+m][64]
__device__ __nv_bfloat16 g_Qt[(size_t)B_ * C_ * N_];    // [b*C+c][n]
__device__ __nv_bfloat16 g_P [(size_t)B_ * N_ * N_];    // P^T: [b][m][n]  (64 MB)
__device__ float         g_denp[(size_t)B_ * 4 * N_];   // partial den: [b*4+nr][m]

__device__ __forceinline__ uint32_t smem_u32(const void* p) {
    uint32_t a;
    asm("{ .reg .u64 t; cvta.to.shared.u64 t, %1; cvt.u32.u64 %0, t; }" : "=r"(a) : "l"(p));
    return a;
}
__device__ __forceinline__ void cp16(uint32_t dst, const void* src) {
    asm volatile("cp.async.cg.shared.global [%0], [%1], 16;" :: "r"(dst), "l"(src));
}
#define CP_COMMIT() asm volatile("cp.async.commit_group;" ::: "memory")
#define CP_WAIT1()  asm volatile("cp.async.wait_group 1;"  ::: "memory")

// tf32 warp mma (projection): D(16x8) += A(16x8)*B(8x8)
__device__ __forceinline__ void mma8(float d[4], const float a[4], float b0, float b1) {
    asm volatile(
        "mma.sync.aligned.m16n8k8.row.col.f32.tf32.tf32.f32 "
        "{%0,%1,%2,%3}, {%4,%5,%6,%7}, {%8,%9}, {%0,%1,%2,%3};"
        : "+f"(d[0]), "+f"(d[1]), "+f"(d[2]), "+f"(d[3])
        : "r"(__float_as_uint(a[0])), "r"(__float_as_uint(a[1])),
          "r"(__float_as_uint(a[2])), "r"(__float_as_uint(a[3])),
          "r"(__float_as_uint(b0)),   "r"(__float_as_uint(b1)));
}
// bf16 warp mma: D(16x8) += A(16x16)*B(16x8)
__device__ __forceinline__ void mma16(float d[4], const uint32_t a[4], uint32_t b0, uint32_t b1) {
    asm volatile(
        "mma.sync.aligned.m16n8k16.row.col.f32.bf16.bf16.f32 "
        "{%0,%1,%2,%3}, {%4,%5,%6,%7}, {%8,%9}, {%0,%1,%2,%3};"
        : "+f"(d[0]), "+f"(d[1]), "+f"(d[2]), "+f"(d[3])
        : "r"(a[0]), "r"(a[1]), "r"(a[2]), "r"(a[3]), "r"(b0), "r"(b1));
}
__device__ __forceinline__ void ldm4(uint32_t r[4], uint32_t addr) {
    asm volatile("ldmatrix.sync.aligned.m8n8.x4.shared.b16 {%0,%1,%2,%3}, [%4];"
        : "=r"(r[0]), "=r"(r[1]), "=r"(r[2]), "=r"(r[3]) : "r"(addr));
}

// =======================================================================
// Kernel 1: projection GEMM (tf32 HMMA), cp.async depth-2 ring (occ 2).
// grid (10 o-tiles of 64, 128 row-tiles of 128), 256 threads.
// Outputs bf16: ot0->K, ot1->V, ot2..9 -> Qt (transposed).
// =======================================================================
#define PA 8704
#define PB 4352
#define PROJ_SMEM_FLOATS (2*PA + 2*PB)
__global__ __launch_bounds__(256, 2) void proj_hmma(
    const float* __restrict__ x,
    const float* __restrict__ Wk, const float* __restrict__ bk,
    const float* __restrict__ Wv, const float* __restrict__ bv,
    const float* __restrict__ Wq, const float* __restrict__ bq)
{
    extern __shared__ float sm[];
    float* sA = sm;
    float* sB = sm + 2 * PA;
    float* sT = sm;

    const uint32_t smu = smem_u32(sm);
    const uint32_t sAu = smu, sBu = smu + 2 * PA * 4;

    const int tid = threadIdx.x;
    const int wid = tid >> 5, lane = tid & 31;
    const int g = lane >> 2, t = lane & 3;
    const int wlo = wid & 3;
    const int whi = wid >> 2;

    const int ot = blockIdx.x;
    const int row0 = blockIdx.y * 128;

    const float* W; const float* bias;
    if (ot == 0)      { W = Wk; bias = bk; }
    else if (ot == 1) { W = Wv; bias = bv; }
    else              { W = Wq + (size_t)(ot - 2) * 64 * C_; bias = bq + (ot - 2) * 64; }

    #pragma unroll
    for (int pf = 0; pf < 2; pf++) {
        const int kc = pf * 64;
        const uint32_t ab = sAu + pf * PA * 4, bb = sBu + pf * PB * 4;
        #pragma unroll
        for (int l = 0; l < 8; l++) {
            int idx = tid + l * 256;
            int r = idx >> 4, c4 = (idx & 15) << 2;
            cp16(ab + (r * 68 + c4) * 4, &x[(size_t)(row0 + r) * C_ + kc + c4]);
        }
        #pragma unroll
        for (int l = 0; l < 4; l++) {
            int idx = tid + l * 256;
            int r = idx >> 4, c4 = (idx & 15) << 2;
            cp16(bb + (r * 68 + c4) * 4, &W[(size_t)r * C_ + kc + c4]);
        }
        CP_COMMIT();
    }

    float acc[8][4];
    #pragma unroll
    for (int i = 0; i < 8; i++)
        #pragma unroll
        for (int j = 0; j < 4; j++) acc[i][j] = 0.f;

    for (int it = 0; it < 8; it++) {
        CP_WAIT1();
        __syncthreads();

        const float* A  = sA + (it & 1) * PA;
        const float* Bm = sB + (it & 1) * PB;
        #pragma unroll
        for (int kk = 0; kk < 64; kk += 8) {
            float a0[4], a1[4];
            const float* Qa = &A[(32 * wlo + g) * 68 + kk + t];
            a0[0] = Qa[0];           a0[1] = Qa[8 * 68];
            a0[2] = Qa[4];           a0[3] = Qa[8 * 68 + 4];
            a1[0] = Qa[16 * 68];     a1[1] = Qa[24 * 68];
            a1[2] = Qa[16 * 68 + 4]; a1[3] = Qa[24 * 68 + 4];
            #pragma unroll
            for (int jf = 0; jf < 4; jf++) {
                const float* Bb = &Bm[(32 * whi + 8 * jf + g) * 68 + kk + t];
                float b0 = Bb[0], b1 = Bb[4];
                mma8(acc[jf],     a0, b0, b1);
                mma8(acc[4 + jf], a1, b0, b1);
            }
        }
        __syncthreads();

        if (it + 2 < 8) {
            const int kc = (it + 2) * 64;
            const uint32_t ab = sAu + (it & 1) * PA * 4, bb = sBu + (it & 1) * PB * 4;
            #pragma unroll
            for (int l = 0; l < 8; l++) {
                int idx = tid + l * 256;
                int r = idx >> 4, c4 = (idx & 15) << 2;
                cp16(ab + (r * 68 + c4) * 4, &x[(size_t)(row0 + r) * C_ + kc + c4]);
            }
            #pragma unroll
            for (int l = 0; l < 4; l++) {
                int idx = tid + l * 256;
                int r = idx >> 4, c4 = (idx & 15) << 2;
                cp16(bb + (r * 68 + c4) * 4, &W[(size_t)r * C_ + kc + c4]);
            }
        }
        CP_COMMIT();
    }

    __syncthreads();

    #pragma unroll
    for (int jf = 0; jf < 4; jf++) {
        const int oc = 32 * whi + 8 * jf + 2 * t;
        const float b0v = __ldg(&bias[oc]);
        const float b1v = __ldg(&bias[oc + 1]);
        #pragma unroll
        for (int fi = 0; fi < 2; fi++) {
            const int r = 32 * wlo + 16 * fi + g;
            const float* d = acc[4 * fi + jf];
            float v00 = d[0] + b0v;
            float v01 = d[1] + b1v;
            float v10 = d[2] + b0v;
            float v11 = d[3] + b1v;
            if (ot == 0) {
                g_K[(size_t)(row0 + r) * CR_ + oc]         = __float2bfloat16_rn(v00);
                g_K[(size_t)(row0 + r) * CR_ + oc + 1]     = __float2bfloat16_rn(v01);
                g_K[(size_t)(row0 + r + 8) * CR_ + oc]     = __float2bfloat16_rn(v10);
                g_K[(size_t)(row0 + r + 8) * CR_ + oc + 1] = __float2bfloat16_rn(v11);
            } else if (ot == 1) {
                g_V[(size_t)(row0 + r) * CR_ + oc]         = __float2bfloat16_rn(v00);
                g_V[(size_t)(row0 + r) * CR_ + oc + 1]     = __float2bfloat16_rn(v01);
                g_V[(size_t)(row0 + r + 8) * CR_ + oc]     = __float2bfloat16_rn(v10);
                g_V[(size_t)(row0 + r + 8) * CR_ + oc + 1] = __float2bfloat16_rn(v11);
            } else {
                sT[oc * 132 + r]           = v00;
                sT[(oc + 1) * 132 + r]     = v01;
                sT[oc * 132 + r + 8]       = v10;
                sT[(oc + 1) * 132 + r + 8] = v11;
            }
        }
    }

    if (ot >= 2) {
        __syncthreads();
        const int b  = row0 >> 11;
        const int n0 = row0 & (N_ - 1);
        const size_t qrow0 = (size_t)b * C_ + (ot - 2) * 64;
        #pragma unroll
        for (int l = 0; l < 8; l++) {
            int idx = tid + l * 256;
            int o = idx >> 5, r4 = (idx & 31) << 2;
            float4 v = *(const float4*)&sT[o * 132 + r4];
            __nv_bfloat162 p0 = __floats2bfloat162_rn(v.x, v.y);
            __nv_bfloat162 p1 = __floats2bfloat162_rn(v.z, v.w);
            __nv_bfloat162* dst = (__nv_bfloat162*)&g_Qt[(qrow0 + o) * N_ + n0 + r4];
            dst[0] = p0; dst[1] = p1;
        }
    }
}

// =======================================================================
// Kernel 2: S = K@V^T, P = exp(S), partial den.  (computed ONCE)
// grid (32 m-tiles of 64, 4 n-ranges of 512, 8 b), 256 threads.
// Writes P^T[b][m][n] bf16 and g_denp[b*4+nr][m].
// =======================================================================
#define PITCH 72
#define KVB   (64 * PITCH * 2)   // 9216 B
#define PX_SV  0
#define PX_SK  (PX_SV + KVB)     // 2 bufs
#define PX_SPT (PX_SK + 2 * KVB)
#define PX_DEN (PX_SPT + KVB)
#define PX_SMEM_BYTES (PX_DEN + 256)
__global__ __launch_bounds__(256, 2) void pexp_kernel()
{
    extern __shared__ char smc[];
    __nv_bfloat16* sPT16 = (__nv_bfloat16*)(smc + PX_SPT);
    float* sDen = (float*)(smc + PX_DEN);

    const uint32_t smu = smem_u32(smc);
    const uint32_t sVu = smu + PX_SV;
    const uint32_t sKu = smu + PX_SK;

    const int tid = threadIdx.x;
    const int wid = tid >> 5, lane = tid & 31;
    const int g = lane >> 2, t = lane & 3;
    const int wlo = wid & 3;        // n group (16)
    const int whi = wid >> 2;       // m group (32)
    const int lrow = lane & 15;
    const int lcol = (lane >> 4) << 3;

    const int mt = blockIdx.x, nr = blockIdx.y, b = blockIdx.z;
    const int m0 = mt * 64;
    const size_t rb = (size_t)b * N_;
    const size_t pbase = (size_t)b * N_ * N_;

    if (tid < 64) sDen[tid] = 0.f;

    // group 0: V + K(i=0); group 1: K(i=1)
    #pragma unroll
    for (int l = 0; l < 2; l++) {
        int idx = tid + l * 256;
        int r = idx >> 3, ch = idx & 7;
        cp16(sVu + r * 144 + ch * 16, &g_V[(rb + m0 + r) * CR_ + ch * 8]);
        cp16(sKu + r * 144 + ch * 16, &g_K[(rb + nr * 512 + r) * CR_ + ch * 8]);
    }
    CP_COMMIT();
    #pragma unroll
    for (int l = 0; l < 2; l++) {
        int idx = tid + l * 256;
        int r = idx >> 3, ch = idx & 7;
        cp16(sKu + KVB + r * 144 + ch * 16, &g_K[(rb + nr * 512 + 64 + r) * CR_ + ch * 8]);
    }
    CP_COMMIT();

    float den[8];
    #pragma unroll
    for (int i = 0; i < 8; i++) den[i] = 0.f;

    for (int i = 0; i < 8; i++) {
        const int n0 = nr * 512 + i * 64;

        CP_WAIT1();               // K(i) (+V) complete
        __syncthreads();          // also protects sPT from prev copy

        const uint32_t Kb = sKu + (i & 1) * KVB;

        // ---- MMA1: S[n 64][m 64] = K @ V^T ----
        float sacc[4][4];
        #pragma unroll
        for (int ii = 0; ii < 4; ii++)
            #pragma unroll
            for (int j = 0; j < 4; j++) sacc[ii][j] = 0.f;

        #pragma unroll
        for (int kk = 0; kk < 64; kk += 16) {
            uint32_t a[4], bv0[4], bv1[4];
            ldm4(a,   Kb  + ((16 * wlo + lrow) * PITCH + kk + lcol) * 2);
            ldm4(bv0, sVu + ((32 * whi + lrow) * PITCH + kk + lcol) * 2);
            ldm4(bv1, sVu + ((32 * whi + 16 + lrow) * PITCH + kk + lcol) * 2);
            mma16(sacc[0], a, bv0[0], bv0[2]);
            mma16(sacc[1], a, bv0[1], bv0[3]);
            mma16(sacc[2], a, bv1[0], bv1[2]);
            mma16(sacc[3], a, bv1[1], bv1[3]);
        }

        // ---- exp -> sPT[m][n] (bf16), den accumulate ----
        const int nloc = 16 * wlo + g;
        #pragma unroll
        for (int jf = 0; jf < 4; jf++) {
            const int mc = 32 * whi + 8 * jf + 2 * t;
            float e00 = __expf(sacc[jf][0]);
            float e01 = __expf(sacc[jf][1]);
            float e10 = __expf(sacc[jf][2]);
            float e11 = __expf(sacc[jf][3]);
            den[2 * jf]     += e00 + e10;
            den[2 * jf + 1] += e01 + e11;
            sPT16[mc * PITCH + nloc]           = __float2bfloat16_rn(e00);
            sPT16[(mc + 1) * PITCH + nloc]     = __float2bfloat16_rn(e01);
            sPT16[mc * PITCH + nloc + 8]       = __float2bfloat16_rn(e10);
            sPT16[(mc + 1) * PITCH + nloc + 8] = __float2bfloat16_rn(e11);
        }
        __syncthreads();  // sPT complete; MMA1 K reads done

        // copy sPT -> g_P[b][m0+r][n0 + ...]
        #pragma unroll
        for (int l = 0; l < 2; l++) {
            int idx = tid + l * 256;
            int r = idx >> 3, ch = idx & 7;
            float4 v = *(const float4*)((const char*)sPT16 + r * 144 + ch * 16);
            *(float4*)&g_P[pbase + (size_t)(m0 + r) * N_ + n0 + ch * 8] = v;
        }

        // prefetch K(i+2) into freed buffer
        if (i + 2 < 8) {
            const int nn = nr * 512 + (i + 2) * 64;
            const uint32_t kb = sKu + (i & 1) * KVB;
            #pragma unroll
            for (int l = 0; l < 2; l++) {
                int idx = tid + l * 256;
                int r = idx >> 3, ch = idx & 7;
                cp16(kb + r * 144 + ch * 16, &g_K[(rb + nn + r) * CR_ + ch * 8]);
            }
        }
        CP_COMMIT();
    }

    // ---- partial den to global ----
    #pragma unroll
    for (int jf = 0; jf < 4; jf++) {
        const int mc = 32 * whi + 8 * jf + 2 * t;
        atomicAdd(&sDen[mc],     den[2 * jf]);
        atomicAdd(&sDen[mc + 1], den[2 * jf + 1]);
    }
    __syncthreads();
    if (tid < 64)
        g_denp[(size_t)(b * 4 + nr) * N_ + m0 + tid] = sDen[tid];
}

// =======================================================================
// Kernel 3: attn2 — pure bf16 GEMM: Acc[c 128][m 64] = Qt @ P^T.
// grid (32 m-tiles, 4 c-tiles, 8 b), 256 threads, double-buffered n=128.
// =======================================================================
#define PITCH2 136
#define PB2 (64  * PITCH2 * 2)    // 17408
#define QB2 (128 * PITCH2 * 2)    // 34816
#define A2_P  0
#define A2_Q  (A2_P + 2 * PB2)
#define A2_SMEM_BYTES (A2_Q + 2 * QB2)   // 104448
#define NT2 16
__global__ __launch_bounds__(256, 2) void attn2_kernel(
    const float* __restrict__ x, const float* __restrict__ gamma_p,
    float* __restrict__ out)
{
    extern __shared__ char smc[];
    const uint32_t smu = smem_u32(smc);
    const uint32_t sPu = smu + A2_P;
    const uint32_t sQu = smu + A2_Q;

    const int tid = threadIdx.x;
    const int wid = tid >> 5, lane = tid & 31;
    const int g = lane >> 2, t = lane & 3;
    const int wlo = wid & 3;        // c group (32)
    const int whi = wid >> 2;       // m group (32)
    const int lrow = lane & 15;
    const int lcol = (lane >> 4) << 3;

    const int mt = blockIdx.x, ct = blockIdx.y, b = blockIdx.z;
    const int m0 = mt * 64, c0 = ct * 128;
    const size_t rb = (size_t)b * N_;
    const size_t qbase = ((size_t)b * C_ + c0) * N_;
    const size_t pbase = (size_t)b * N_ * N_ + (size_t)m0 * N_;

    // prefetch stage 0
    {
        const uint32_t pb = sPu, qb = sQu;
        #pragma unroll
        for (int l = 0; l < 4; l++) {
            int idx = tid + l * 256;
            int r = idx >> 4, ch = idx & 15;
            cp16(pb + r * 272 + ch * 16, &g_P[pbase + (size_t)r * N_ + ch * 8]);
        }
        #pragma unroll
        for (int l = 0; l < 8; l++) {
            int idx = tid + l * 256;
            int r = idx >> 4, ch = idx & 15;
            cp16(qb + r * 272 + ch * 16, &g_Qt[qbase + (size_t)r * N_ + ch * 8]);
        }
        CP_COMMIT();
    }

    float acc2[8][4];
    #pragma unroll
    for (int i = 0; i < 8; i++)
        #pragma unroll
        for (int j = 0; j < 4; j++) acc2[i][j] = 0.f;

    for (int nt = 0; nt < NT2; nt++) {
        if (nt + 1 < NT2) {
            const int n1 = (nt + 1) * 128;
            const uint32_t pb = sPu + ((nt + 1) & 1) * PB2;
            const uint32_t qb = sQu + ((nt + 1) & 1) * QB2;
            #pragma unroll
            for (int l = 0; l < 4; l++) {
                int idx = tid + l * 256;
                int r = idx >> 4, ch = idx & 15;
                cp16(pb + r * 272 + ch * 16, &g_P[pbase + (size_t)r * N_ + n1 + ch * 8]);
            }
            #pragma unroll
            for (int l = 0; l < 8; l++) {
                int idx = tid + l * 256;
                int r = idx >> 4, ch = idx & 15;
                cp16(qb + r * 272 + ch * 16, &g_Qt[qbase + (size_t)r * N_ + n1 + ch * 8]);
            }
        }
        CP_COMMIT();
        CP_WAIT1();
        __syncthreads();

        const uint32_t Pb = sPu + (nt & 1) * PB2;
        const uint32_t Qb = sQu + (nt & 1) * QB2;

        #pragma unroll
        for (int kk = 0; kk < 128; kk += 16) {
            uint32_t a0[4], a1[4], p0[4], p1[4];
            ldm4(a0, Qb + ((32 * wlo + lrow) * PITCH2 + kk + lcol) * 2);
            ldm4(a1, Qb + ((32 * wlo + 16 + lrow) * PITCH2 + kk + lcol) * 2);
            ldm4(p0, Pb + ((32 * whi + lrow) * PITCH2 + kk + lcol) * 2);
            ldm4(p1, Pb + ((32 * whi + 16 + lrow) * PITCH2 + kk + lcol) * 2);
            mma16(acc2[0], a0, p0[0], p0[2]);
            mma16(acc2[1], a0, p0[1], p0[3]);
            mma16(acc2[2], a0, p1[0], p1[2]);
            mma16(acc2[3], a0, p1[1], p1[3]);
            mma16(acc2[4], a1, p0[0], p0[2]);
            mma16(acc2[5], a1, p0[1], p0[3]);
            mma16(acc2[6], a1, p1[0], p1[2]);
            mma16(acc2[7], a1, p1[1], p1[3]);
        }
        __syncthreads();   // protect buffers before next prefetch overwrites
    }

    // ---- epilogue: out = gamma*Acc/den + x ----
    const float gam = gamma_p[0];
    #pragma unroll
    for (int jf = 0; jf < 4; jf++) {
        const int mc = 32 * whi + 8 * jf + 2 * t;
        float d0 = 0.f, d1 = 0.f;
        #pragma unroll
        for (int nr = 0; nr < 4; nr++) {
            d0 += __ldg(&g_denp[(size_t)(b * 4 + nr) * N_ + m0 + mc]);
            d1 += __ldg(&g_denp[(size_t)(b * 4 + nr) * N_ + m0 + mc + 1]);
        }
        const float di0 = gam / d0;
        const float di1 = gam / d1;
        #pragma unroll
        for (int fi = 0; fi < 2; fi++) {
            const int cc = c0 + 32 * wlo + 16 * fi + g;
            const size_t r0a = (rb + m0 + mc) * C_ + cc;
            const size_t r1a = (rb + m0 + mc + 1) * C_ + cc;
            const float* d = acc2[4 * fi + jf];
            out[r0a]     = d[0] * di0 + __ldg(&x[r0a]);
            out[r1a]     = d[1] * di1 + __ldg(&x[r1a]);
            out[r0a + 8] = d[2] * di0 + __ldg(&x[r0a + 8]);
            out[r1a + 8] = d[3] * di1 + __ldg(&x[r1a + 8]);
        }
    }
}

// =======================================================================
extern "C" void kernel_launch(void* const* d_in, const int* in_sizes, int n_in,
                              void* d_out, int out_size)
{
    const float* x     = (const float*)d_in[0];
    const float* Wk    = (const float*)d_in[1];
    const float* bk    = (const float*)d_in[2];
    const float* Wv    = (const float*)d_in[3];
    const float* bv    = (const float*)d_in[4];
    const float* Wq    = (const float*)d_in[5];
    const float* bq    = (const float*)d_in[6];
    const float* gamma = (const float*)d_in[7];
    float* out = (float*)d_out;

    const int PROJ_SMEM = PROJ_SMEM_FLOATS * 4;   // 104448 B
    cudaFuncSetAttribute(proj_hmma,    cudaFuncAttributeMaxDynamicSharedMemorySize, PROJ_SMEM);
    cudaFuncSetAttribute(pexp_kernel,  cudaFuncAttributeMaxDynamicSharedMemorySize, PX_SMEM_BYTES);
    cudaFuncSetAttribute(attn2_kernel, cudaFuncAttributeMaxDynamicSharedMemorySize, A2_SMEM_BYTES);

    proj_hmma<<<dim3(10, 128), 256, PROJ_SMEM>>>(x, Wk, bk, Wv, bv, Wq, bq);
    pexp_kernel<<<dim3(32, 4, B_), 256, PX_SMEM_BYTES>>>();
    attn2_kernel<<<dim3(32, 4, B_), 256, A2_SMEM_BYTES>>>(x, gamma, out);
}

// round 8
// speedup vs baseline: 6.5878x; 1.1304x over previous
#include <cuda_runtime.h>
#include <cuda_bf16.h>
#include <cstdint>

#define B_  8
#define N_  2048
#define C_  512
#define CR_ 64

// Device-global scratch (no allocs allowed).
__device__ __nv_bfloat16 g_xb[(size_t)B_ * N_ * C_];    // x in bf16
__device__ __nv_bfloat16 g_Wb[(size_t)640 * C_];        // [Wk;Wv;Wq] bf16
__device__ __nv_bfloat16 g_K [(size_t)B_ * N_ * CR_];   // [b*N+n][64]
__device__ __nv_bfloat16 g_V [(size_t)B_ * N_ * CR_];   // [b*N+m][64]
__device__ __nv_bfloat16 g_Qt[(size_t)B_ * C_ * N_];    // [b*C+c][n]
__device__ __nv_bfloat16 g_P [(size_t)B_ * N_ * N_];    // P^T: [b][m][n]
__device__ float         g_denp[(size_t)B_ * 4 * N_];   // partial den

__device__ __forceinline__ uint32_t smem_u32(const void* p) {
    uint32_t a;
    asm("{ .reg .u64 t; cvta.to.shared.u64 t, %1; cvt.u32.u64 %0, t; }" : "=r"(a) : "l"(p));
    return a;
}
__device__ __forceinline__ void cp16(uint32_t dst, const void* src) {
    asm volatile("cp.async.cg.shared.global [%0], [%1], 16;" :: "r"(dst), "l"(src));
}
#define CP_COMMIT() asm volatile("cp.async.commit_group;" ::: "memory")
#define CP_WAIT1()  asm volatile("cp.async.wait_group 1;"  ::: "memory")

// bf16 warp mma: D(16x8) += A(16x16)*B(16x8)
__device__ __forceinline__ void mma16(float d[4], const uint32_t a[4], uint32_t b0, uint32_t b1) {
    asm volatile(
        "mma.sync.aligned.m16n8k16.row.col.f32.bf16.bf16.f32 "
        "{%0,%1,%2,%3}, {%4,%5,%6,%7}, {%8,%9}, {%0,%1,%2,%3};"
        : "+f"(d[0]), "+f"(d[1]), "+f"(d[2]), "+f"(d[3])
        : "r"(a[0]), "r"(a[1]), "r"(a[2]), "r"(a[3]), "r"(b0), "r"(b1));
}
__device__ __forceinline__ void ldm4(uint32_t r[4], uint32_t addr) {
    asm volatile("ldmatrix.sync.aligned.m8n8.x4.shared.b16 {%0,%1,%2,%3}, [%4];"
        : "=r"(r[0]), "=r"(r[1]), "=r"(r[2]), "=r"(r[3]) : "r"(addr));
}

// =======================================================================
// Kernel 0: fp32 -> bf16 conversion of x and [Wk;Wv;Wq].
// =======================================================================
__global__ __launch_bounds__(256) void cvt_kernel(
    const float* __restrict__ x,
    const float* __restrict__ Wk, const float* __restrict__ Wv,
    const float* __restrict__ Wq)
{
    const int NX = (B_ * N_ * C_) / 4;      // float4 units for x
    const int NW = (640 * C_) / 4;
    for (int i = blockIdx.x * blockDim.x + threadIdx.x; i < NX + NW;
         i += gridDim.x * blockDim.x) {
        float4 v;
        __nv_bfloat16* dst;
        if (i < NX) {
            v = ((const float4*)x)[i];
            dst = &g_xb[(size_t)i * 4];
        } else {
            int j = i - NX;                 // float4 index into W block
            const int row = (j * 4) / C_;   // 0..639
            const float* src;
            if (row < 64)        src = Wk;
            else if (row < 128)  src = Wv - 64 * C_;
            else                 src = Wq - 128 * C_;
            v = ((const float4*)src)[j];
            dst = &g_Wb[(size_t)j * 4];
        }
        __nv_bfloat162 p0 = __floats2bfloat162_rn(v.x, v.y);
        __nv_bfloat162 p1 = __floats2bfloat162_rn(v.z, v.w);
        ((__nv_bfloat162*)dst)[0] = p0;
        ((__nv_bfloat162*)dst)[1] = p1;
    }
}

// =======================================================================
// Kernel 1: projection GEMM (bf16 HMMA + ldmatrix), cp.async ring-2.
// grid (10 o-tiles of 64, 128 row-tiles of 128), 256 threads.
// Outputs bf16: ot0->K, ot1->V, ot2..9 -> Qt (transposed).
// =======================================================================
#define PITCH 72
#define PAB (128 * PITCH * 2)   // 18432 B per A buffer
#define PBB (64  * PITCH * 2)   //  9216 B per B buffer
#define PJ_A 0
#define PJ_B (PJ_A + 2 * PAB)
#define PJ_SMEM_BYTES (PJ_B + 2 * PBB)   // 55296
__global__ __launch_bounds__(256, 2) void proj_hmma(
    const float* __restrict__ bk, const float* __restrict__ bv,
    const float* __restrict__ bq)
{
    extern __shared__ char smc[];
    float* sT = (float*)smc;     // reuse A buffers: [64][132] fp32 staging

    const uint32_t smu = smem_u32(smc);
    const uint32_t sAu = smu + PJ_A, sBu = smu + PJ_B;

    const int tid = threadIdx.x;
    const int wid = tid >> 5, lane = tid & 31;
    const int g = lane >> 2, t = lane & 3;
    const int wlo = wid & 3;        // row group (32 of 128)
    const int whi = wid >> 2;       // o group (32 of 64)
    const int lrow = lane & 15;
    const int lcol = (lane >> 4) << 3;

    const int ot = blockIdx.x;
    const int row0 = blockIdx.y * 128;
    const int wrow0 = ot * 64;      // row offset in g_Wb

    const float* bias;
    if (ot == 0)      bias = bk;
    else if (ot == 1) bias = bv;
    else              bias = bq + (ot - 2) * 64;

    // prefetch k-chunks 0,1
    #pragma unroll
    for (int pf = 0; pf < 2; pf++) {
        const int kc = pf * 64;
        const uint32_t ab = sAu + pf * PAB, bb = sBu + pf * PBB;
        #pragma unroll
        for (int l = 0; l < 4; l++) {
            int idx = tid + l * 256;
            int r = idx >> 3, ch = idx & 7;
            cp16(ab + r * 144 + ch * 16, &g_xb[(size_t)(row0 + r) * C_ + kc + ch * 8]);
        }
        #pragma unroll
        for (int l = 0; l < 2; l++) {
            int idx = tid + l * 256;
            int r = idx >> 3, ch = idx & 7;
            cp16(bb + r * 144 + ch * 16, &g_Wb[(size_t)(wrow0 + r) * C_ + kc + ch * 8]);
        }
        CP_COMMIT();
    }

    float acc[8][4];   // [fi*4+jf][4]
    #pragma unroll
    for (int i = 0; i < 8; i++)
        #pragma unroll
        for (int j = 0; j < 4; j++) acc[i][j] = 0.f;

    for (int it = 0; it < 8; it++) {
        CP_WAIT1();
        __syncthreads();

        const uint32_t Ab = sAu + (it & 1) * PAB;
        const uint32_t Bb = sBu + (it & 1) * PBB;

        #pragma unroll
        for (int kk = 0; kk < 64; kk += 16) {
            uint32_t a0[4], a1[4], b0[4], b1[4];
            ldm4(a0, Ab + ((32 * wlo + lrow) * PITCH + kk + lcol) * 2);
            ldm4(a1, Ab + ((32 * wlo + 16 + lrow) * PITCH + kk + lcol) * 2);
            ldm4(b0, Bb + ((32 * whi + lrow) * PITCH + kk + lcol) * 2);
            ldm4(b1, Bb + ((32 * whi + 16 + lrow) * PITCH + kk + lcol) * 2);
            mma16(acc[0], a0, b0[0], b0[2]);
            mma16(acc[1], a0, b0[1], b0[3]);
            mma16(acc[2], a0, b1[0], b1[2]);
            mma16(acc[3], a0, b1[1], b1[3]);
            mma16(acc[4], a1, b0[0], b0[2]);
            mma16(acc[5], a1, b0[1], b0[3]);
            mma16(acc[6], a1, b1[0], b1[2]);
            mma16(acc[7], a1, b1[1], b1[3]);
        }
        __syncthreads();   // buffer (it&1) free

        if (it + 2 < 8) {
            const int kc = (it + 2) * 64;
            const uint32_t ab = sAu + (it & 1) * PAB, bb = sBu + (it & 1) * PBB;
            #pragma unroll
            for (int l = 0; l < 4; l++) {
                int idx = tid + l * 256;
                int r = idx >> 3, ch = idx & 7;
                cp16(ab + r * 144 + ch * 16, &g_xb[(size_t)(row0 + r) * C_ + kc + ch * 8]);
            }
            #pragma unroll
            for (int l = 0; l < 2; l++) {
                int idx = tid + l * 256;
                int r = idx >> 3, ch = idx & 7;
                cp16(bb + r * 144 + ch * 16, &g_Wb[(size_t)(wrow0 + r) * C_ + kc + ch * 8]);
            }
        }
        CP_COMMIT();
    }

    __syncthreads();  // sT aliases A buffers

    #pragma unroll
    for (int jf = 0; jf < 4; jf++) {
        const int oc = 32 * whi + 8 * jf + 2 * t;
        const float b0v = __ldg(&bias[oc]);
        const float b1v = __ldg(&bias[oc + 1]);
        #pragma unroll
        for (int fi = 0; fi < 2; fi++) {
            const int r = 32 * wlo + 16 * fi + g;
            const float* d = acc[4 * fi + jf];
            float v00 = d[0] + b0v;
            float v01 = d[1] + b1v;
            float v10 = d[2] + b0v;
            float v11 = d[3] + b1v;
            if (ot == 0) {
                g_K[(size_t)(row0 + r) * CR_ + oc]         = __float2bfloat16_rn(v00);
                g_K[(size_t)(row0 + r) * CR_ + oc + 1]     = __float2bfloat16_rn(v01);
                g_K[(size_t)(row0 + r + 8) * CR_ + oc]     = __float2bfloat16_rn(v10);
                g_K[(size_t)(row0 + r + 8) * CR_ + oc + 1] = __float2bfloat16_rn(v11);
            } else if (ot == 1) {
                g_V[(size_t)(row0 + r) * CR_ + oc]         = __float2bfloat16_rn(v00);
                g_V[(size_t)(row0 + r) * CR_ + oc + 1]     = __float2bfloat16_rn(v01);
                g_V[(size_t)(row0 + r + 8) * CR_ + oc]     = __float2bfloat16_rn(v10);
                g_V[(size_t)(row0 + r + 8) * CR_ + oc + 1] = __float2bfloat16_rn(v11);
            } else {
                sT[oc * 132 + r]           = v00;
                sT[(oc + 1) * 132 + r]     = v01;
                sT[oc * 132 + r + 8]       = v10;
                sT[(oc + 1) * 132 + r + 8] = v11;
            }
        }
    }

    if (ot >= 2) {
        __syncthreads();
        const int b  = row0 >> 11;
        const int n0 = row0 & (N_ - 1);
        const size_t qrow0 = (size_t)b * C_ + (ot - 2) * 64;
        #pragma unroll
        for (int l = 0; l < 8; l++) {
            int idx = tid + l * 256;
            int o = idx >> 5, r4 = (idx & 31) << 2;
            float4 v = *(const float4*)&sT[o * 132 + r4];
            __nv_bfloat162 p0 = __floats2bfloat162_rn(v.x, v.y);
            __nv_bfloat162 p1 = __floats2bfloat162_rn(v.z, v.w);
            __nv_bfloat162* dst = (__nv_bfloat162*)&g_Qt[(qrow0 + o) * N_ + n0 + r4];
            dst[0] = p0; dst[1] = p1;
        }
    }
}

// =======================================================================
// Kernel 2: S = K@V^T, P = exp(S), partial den.  (computed ONCE)
// grid (32 m-tiles of 64, 4 n-ranges of 512, 8 b), 256 threads.
// =======================================================================
#define KVB   (64 * PITCH * 2)   // 9216 B
#define PX_SV  0
#define PX_SK  (PX_SV + KVB)     // 2 bufs
#define PX_SPT (PX_SK + 2 * KVB)
#define PX_DEN (PX_SPT + KVB)
#define PX_SMEM_BYTES (PX_DEN + 256)
__global__ __launch_bounds__(256, 2) void pexp_kernel()
{
    extern __shared__ char smc[];
    __nv_bfloat16* sPT16 = (__nv_bfloat16*)(smc + PX_SPT);
    float* sDen = (float*)(smc + PX_DEN);

    const uint32_t smu = smem_u32(smc);
    const uint32_t sVu = smu + PX_SV;
    const uint32_t sKu = smu + PX_SK;

    const int tid = threadIdx.x;
    const int wid = tid >> 5, lane = tid & 31;
    const int g = lane >> 2, t = lane & 3;
    const int wlo = wid & 3;
    const int whi = wid >> 2;
    const int lrow = lane & 15;
    const int lcol = (lane >> 4) << 3;

    const int mt = blockIdx.x, nr = blockIdx.y, b = blockIdx.z;
    const int m0 = mt * 64;
    const size_t rb = (size_t)b * N_;
    const size_t pbase = (size_t)b * N_ * N_;

    if (tid < 64) sDen[tid] = 0.f;

    #pragma unroll
    for (int l = 0; l < 2; l++) {
        int idx = tid + l * 256;
        int r = idx >> 3, ch = idx & 7;
        cp16(sVu + r * 144 + ch * 16, &g_V[(rb + m0 + r) * CR_ + ch * 8]);
        cp16(sKu + r * 144 + ch * 16, &g_K[(rb + nr * 512 + r) * CR_ + ch * 8]);
    }
    CP_COMMIT();
    #pragma unroll
    for (int l = 0; l < 2; l++) {
        int idx = tid + l * 256;
        int r = idx >> 3, ch = idx & 7;
        cp16(sKu + KVB + r * 144 + ch * 16, &g_K[(rb + nr * 512 + 64 + r) * CR_ + ch * 8]);
    }
    CP_COMMIT();

    float den[8];
    #pragma unroll
    for (int i = 0; i < 8; i++) den[i] = 0.f;

    for (int i = 0; i < 8; i++) {
        const int n0 = nr * 512 + i * 64;

        CP_WAIT1();
        __syncthreads();

        const uint32_t Kb = sKu + (i & 1) * KVB;

        float sacc[4][4];
        #pragma unroll
        for (int ii = 0; ii < 4; ii++)
            #pragma unroll
            for (int j = 0; j < 4; j++) sacc[ii][j] = 0.f;

        #pragma unroll
        for (int kk = 0; kk < 64; kk += 16) {
            uint32_t a[4], bv0[4], bv1[4];
            ldm4(a,   Kb  + ((16 * wlo + lrow) * PITCH + kk + lcol) * 2);
            ldm4(bv0, sVu + ((32 * whi + lrow) * PITCH + kk + lcol) * 2);
            ldm4(bv1, sVu + ((32 * whi + 16 + lrow) * PITCH + kk + lcol) * 2);
            mma16(sacc[0], a, bv0[0], bv0[2]);
            mma16(sacc[1], a, bv0[1], bv0[3]);
            mma16(sacc[2], a, bv1[0], bv1[2]);
            mma16(sacc[3], a, bv1[1], bv1[3]);
        }

        const int nloc = 16 * wlo + g;
        #pragma unroll
        for (int jf = 0; jf < 4; jf++) {
            const int mc = 32 * whi + 8 * jf + 2 * t;
            float e00 = __expf(sacc[jf][0]);
            float e01 = __expf(sacc[jf][1]);
            float e10 = __expf(sacc[jf][2]);
            float e11 = __expf(sacc[jf][3]);
            den[2 * jf]     += e00 + e10;
            den[2 * jf + 1] += e01 + e11;
            sPT16[mc * PITCH + nloc]           = __float2bfloat16_rn(e00);
            sPT16[(mc + 1) * PITCH + nloc]     = __float2bfloat16_rn(e01);
            sPT16[mc * PITCH + nloc + 8]       = __float2bfloat16_rn(e10);
            sPT16[(mc + 1) * PITCH + nloc + 8] = __float2bfloat16_rn(e11);
        }
        __syncthreads();

        #pragma unroll
        for (int l = 0; l < 2; l++) {
            int idx = tid + l * 256;
            int r = idx >> 3, ch = idx & 7;
            float4 v = *(const float4*)((const char*)sPT16 + r * 144 + ch * 16);
            *(float4*)&g_P[pbase + (size_t)(m0 + r) * N_ + n0 + ch * 8] = v;
        }

        if (i + 2 < 8) {
            const int nn = nr * 512 + (i + 2) * 64;
            const uint32_t kb = sKu + (i & 1) * KVB;
            #pragma unroll
            for (int l = 0; l < 2; l++) {
                int idx = tid + l * 256;
                int r = idx >> 3, ch = idx & 7;
                cp16(kb + r * 144 + ch * 16, &g_K[(rb + nn + r) * CR_ + ch * 8]);
            }
        }
        CP_COMMIT();
    }

    #pragma unroll
    for (int jf = 0; jf < 4; jf++) {
        const int mc = 32 * whi + 8 * jf + 2 * t;
        atomicAdd(&sDen[mc],     den[2 * jf]);
        atomicAdd(&sDen[mc + 1], den[2 * jf + 1]);
    }
    __syncthreads();
    if (tid < 64)
        g_denp[(size_t)(b * 4 + nr) * N_ + m0 + tid] = sDen[tid];
}

// =======================================================================
// Kernel 3: attn2 — pure bf16 GEMM: Acc[c 128][m 64] = Qt @ P^T.
// grid (32 m-tiles, 4 c-tiles, 8 b), 256 threads, double-buffered n=128.
// =======================================================================
#define PITCH2 136
#define PB2 (64  * PITCH2 * 2)
#define QB2 (128 * PITCH2 * 2)
#define A2_P  0
#define A2_Q  (A2_P + 2 * PB2)
#define A2_SMEM_BYTES (A2_Q + 2 * QB2)
#define NT2 16
__global__ __launch_bounds__(256, 2) void attn2_kernel(
    const float* __restrict__ x, const float* __restrict__ gamma_p,
    float* __restrict__ out)
{
    extern __shared__ char smc[];
    const uint32_t smu = smem_u32(smc);
    const uint32_t sPu = smu + A2_P;
    const uint32_t sQu = smu + A2_Q;

    const int tid = threadIdx.x;
    const int wid = tid >> 5, lane = tid & 31;
    const int g = lane >> 2, t = lane & 3;
    const int wlo = wid & 3;
    const int whi = wid >> 2;
    const int lrow = lane & 15;
    const int lcol = (lane >> 4) << 3;

    const int mt = blockIdx.x, ct = blockIdx.y, b = blockIdx.z;
    const int m0 = mt * 64, c0 = ct * 128;
    const size_t rb = (size_t)b * N_;
    const size_t qbase = ((size_t)b * C_ + c0) * N_;
    const size_t pbase = (size_t)b * N_ * N_ + (size_t)m0 * N_;

    {
        const uint32_t pb = sPu, qb = sQu;
        #pragma unroll
        for (int l = 0; l < 4; l++) {
            int idx = tid + l * 256;
            int r = idx >> 4, ch = idx & 15;
            cp16(pb + r * 272 + ch * 16, &g_P[pbase + (size_t)r * N_ + ch * 8]);
        }
        #pragma unroll
        for (int l = 0; l < 8; l++) {
            int idx = tid + l * 256;
            int r = idx >> 4, ch = idx & 15;
            cp16(qb + r * 272 + ch * 16, &g_Qt[qbase + (size_t)r * N_ + ch * 8]);
        }
        CP_COMMIT();
    }

    float acc2[8][4];
    #pragma unroll
    for (int i = 0; i < 8; i++)
        #pragma unroll
        for (int j = 0; j < 4; j++) acc2[i][j] = 0.f;

    for (int nt = 0; nt < NT2; nt++) {
        if (nt + 1 < NT2) {
            const int n1 = (nt + 1) * 128;
            const uint32_t pb = sPu + ((nt + 1) & 1) * PB2;
            const uint32_t qb = sQu + ((nt + 1) & 1) * QB2;
            #pragma unroll
            for (int l = 0; l < 4; l++) {
                int idx = tid + l * 256;
                int r = idx >> 4, ch = idx & 15;
                cp16(pb + r * 272 + ch * 16, &g_P[pbase + (size_t)r * N_ + n1 + ch * 8]);
            }
            #pragma unroll
            for (int l = 0; l < 8; l++) {
                int idx = tid + l * 256;
                int r = idx >> 4, ch = idx & 15;
                cp16(qb + r * 272 + ch * 16, &g_Qt[qbase + (size_t)r * N_ + n1 + ch * 8]);
            }
        }
        CP_COMMIT();
        CP_WAIT1();
        __syncthreads();

        const uint32_t Pb = sPu + (nt & 1) * PB2;
        const uint32_t Qb = sQu + (nt & 1) * QB2;

        #pragma unroll
        for (int kk = 0; kk < 128; kk += 16) {
            uint32_t a0[4], a1[4], p0[4], p1[4];
            ldm4(a0, Qb + ((32 * wlo + lrow) * PITCH2 + kk + lcol) * 2);
            ldm4(a1, Qb + ((32 * wlo + 16 + lrow) * PITCH2 + kk + lcol) * 2);
            ldm4(p0, Pb + ((32 * whi + lrow) * PITCH2 + kk + lcol) * 2);
            ldm4(p1, Pb + ((32 * whi + 16 + lrow) * PITCH2 + kk + lcol) * 2);
            mma16(acc2[0], a0, p0[0], p0[2]);
            mma16(acc2[1], a0, p0[1], p0[3]);
            mma16(acc2[2], a0, p1[0], p1[2]);
            mma16(acc2[3], a0, p1[1], p1[3]);
            mma16(acc2[4], a1, p0[0], p0[2]);
            mma16(acc2[5], a1, p0[1], p0[3]);
            mma16(acc2[6], a1, p1[0], p1[2]);
            mma16(acc2[7], a1, p1[1], p1[3]);
        }
        __syncthreads();
    }

    const float gam = gamma_p[0];
    #pragma unroll
    for (int jf = 0; jf < 4; jf++) {
        const int mc = 32 * whi + 8 * jf + 2 * t;
        float d0 = 0.f, d1 = 0.f;
        #pragma unroll
        for (int nr = 0; nr < 4; nr++) {
            d0 += __ldg(&g_denp[(size_t)(b * 4 + nr) * N_ + m0 + mc]);
            d1 += __ldg(&g_denp[(size_t)(b * 4 + nr) * N_ + m0 + mc + 1]);
        }
        const float di0 = gam / d0;
        const float di1 = gam / d1;
        #pragma unroll
        for (int fi = 0; fi < 2; fi++) {
            const int cc = c0 + 32 * wlo + 16 * fi + g;
            const size_t r0a = (rb + m0 + mc) * C_ + cc;
            const size_t r1a = (rb + m0 + mc + 1) * C_ + cc;
            const float* d = acc2[4 * fi + jf];
            out[r0a]     = d[0] * di0 + __ldg(&x[r0a]);
            out[r1a]     = d[1] * di1 + __ldg(&x[r1a]);
            out[r0a + 8] = d[2] * di0 + __ldg(&x[r0a + 8]);
            out[r1a + 8] = d[3] * di1 + __ldg(&x[r1a + 8]);
        }
    }
}

// =======================================================================
extern "C" void kernel_launch(void* const* d_in, const int* in_sizes, int n_in,
                              void* d_out, int out_size)
{
    const float* x     = (const float*)d_in[0];
    const float* Wk    = (const float*)d_in[1];
    const float* bk    = (const float*)d_in[2];
    const float* Wv    = (const float*)d_in[3];
    const float* bv    = (const float*)d_in[4];
    const float* Wq    = (const float*)d_in[5];
    const float* bq    = (const float*)d_in[6];
    const float* gamma = (const float*)d_in[7];
    float* out = (float*)d_out;

    cudaFuncSetAttribute(proj_hmma,    cudaFuncAttributeMaxDynamicSharedMemorySize, PJ_SMEM_BYTES);
    cudaFuncSetAttribute(pexp_kernel,  cudaFuncAttributeMaxDynamicSharedMemorySize, PX_SMEM_BYTES);
    cudaFuncSetAttribute(attn2_kernel, cudaFuncAttributeMaxDynamicSharedMemorySize, A2_SMEM_BYTES);

    cvt_kernel<<<1184, 256>>>(x, Wk, Wv, Wq);
    proj_hmma<<<dim3(10, 128), 256, PJ_SMEM_BYTES>>>(bk, bv, bq);
    pexp_kernel<<<dim3(32, 4, B_), 256, PX_SMEM_BYTES>>>();
    attn2_kernel<<<dim3(32, 4, B_), 256, A2_SMEM_BYTES>>>(x, gamma, out);
}

// round 9
// speedup vs baseline: 6.6603x; 1.0110x over previous
#include <cuda_runtime.h>
#include <cuda_bf16.h>
#include <cstdint>

#define B_  8
#define N_  2048
#define C_  512
#define CR_ 64

// Device-global scratch (no allocs allowed).
__device__ __nv_bfloat16 g_xb[(size_t)B_ * N_ * C_];    // x in bf16
__device__ __nv_bfloat16 g_Wb[(size_t)640 * C_];        // [Wk;Wv;Wq] bf16
__device__ __nv_bfloat16 g_K [(size_t)B_ * N_ * CR_];   // [b*N+n][64]
__device__ __nv_bfloat16 g_V [(size_t)B_ * N_ * CR_];   // [b*N+m][64]
__device__ __nv_bfloat16 g_Qt[(size_t)B_ * C_ * N_];    // [b*C+c][n]
__device__ __nv_bfloat16 g_P [(size_t)B_ * N_ * N_];    // P^T: [b][m][n]
__device__ float         g_denp[(size_t)B_ * 4 * N_];   // partial den

__device__ __forceinline__ uint32_t smem_u32(const void* p) {
    uint32_t a;
    asm("{ .reg .u64 t; cvta.to.shared.u64 t, %1; cvt.u32.u64 %0, t; }" : "=r"(a) : "l"(p));
    return a;
}
__device__ __forceinline__ void cp16(uint32_t dst, const void* src) {
    asm volatile("cp.async.cg.shared.global [%0], [%1], 16;" :: "r"(dst), "l"(src));
}
#define CP_COMMIT() asm volatile("cp.async.commit_group;" ::: "memory")
#define CP_WAIT1()  asm volatile("cp.async.wait_group 1;"  ::: "memory")
#define CP_WAIT2()  asm volatile("cp.async.wait_group 2;"  ::: "memory")

// bf16 warp mma: D(16x8) += A(16x16)*B(16x8)
__device__ __forceinline__ void mma16(float d[4], const uint32_t a[4], uint32_t b0, uint32_t b1) {
    asm volatile(
        "mma.sync.aligned.m16n8k16.row.col.f32.bf16.bf16.f32 "
        "{%0,%1,%2,%3}, {%4,%5,%6,%7}, {%8,%9}, {%0,%1,%2,%3};"
        : "+f"(d[0]), "+f"(d[1]), "+f"(d[2]), "+f"(d[3])
        : "r"(a[0]), "r"(a[1]), "r"(a[2]), "r"(a[3]), "r"(b0), "r"(b1));
}
__device__ __forceinline__ void ldm4(uint32_t r[4], uint32_t addr) {
    asm volatile("ldmatrix.sync.aligned.m8n8.x4.shared.b16 {%0,%1,%2,%3}, [%4];"
        : "=r"(r[0]), "=r"(r[1]), "=r"(r[2]), "=r"(r[3]) : "r"(addr));
}

// =======================================================================
// Kernel 0: fp32 -> bf16 conversion of x and [Wk;Wv;Wq].
// =======================================================================
__global__ __launch_bounds__(256) void cvt_kernel(
    const float* __restrict__ x,
    const float* __restrict__ Wk, const float* __restrict__ Wv,
    const float* __restrict__ Wq)
{
    const int NX = (B_ * N_ * C_) / 4;
    const int NW = (640 * C_) / 4;
    for (int i = blockIdx.x * blockDim.x + threadIdx.x; i < NX + NW;
         i += gridDim.x * blockDim.x) {
        float4 v;
        __nv_bfloat16* dst;
        if (i < NX) {
            v = ((const float4*)x)[i];
            dst = &g_xb[(size_t)i * 4];
        } else {
            int j = i - NX;
            const int row = (j * 4) / C_;
            const float* src;
            if (row < 64)        src = Wk;
            else if (row < 128)  src = Wv - 64 * C_;
            else                 src = Wq - 128 * C_;
            v = ((const float4*)src)[j];
            dst = &g_Wb[(size_t)j * 4];
        }
        __nv_bfloat162 p0 = __floats2bfloat162_rn(v.x, v.y);
        __nv_bfloat162 p1 = __floats2bfloat162_rn(v.z, v.w);
        ((__nv_bfloat162*)dst)[0] = p0;
        ((__nv_bfloat162*)dst)[1] = p1;
    }
}

// =======================================================================
// Kernel 1: projection GEMM (bf16 HMMA + ldmatrix), cp.async ring-2.
// =======================================================================
#define PITCH 72
#define PAB (128 * PITCH * 2)
#define PBB (64  * PITCH * 2)
#define PJ_A 0
#define PJ_B (PJ_A + 2 * PAB)
#define PJ_SMEM_BYTES (PJ_B + 2 * PBB)
__global__ __launch_bounds__(256, 2) void proj_hmma(
    const float* __restrict__ bk, const float* __restrict__ bv,
    const float* __restrict__ bq)
{
    extern __shared__ char smc[];
    float* sT = (float*)smc;

    const uint32_t smu = smem_u32(smc);
    const uint32_t sAu = smu + PJ_A, sBu = smu + PJ_B;

    const int tid = threadIdx.x;
    const int wid = tid >> 5, lane = tid & 31;
    const int g = lane >> 2, t = lane & 3;
    const int wlo = wid & 3;
    const int whi = wid >> 2;
    const int lrow = lane & 15;
    const int lcol = (lane >> 4) << 3;

    const int ot = blockIdx.x;
    const int row0 = blockIdx.y * 128;
    const int wrow0 = ot * 64;

    const float* bias;
    if (ot == 0)      bias = bk;
    else if (ot == 1) bias = bv;
    else              bias = bq + (ot - 2) * 64;

    #pragma unroll
    for (int pf = 0; pf < 2; pf++) {
        const int kc = pf * 64;
        const uint32_t ab = sAu + pf * PAB, bb = sBu + pf * PBB;
        #pragma unroll
        for (int l = 0; l < 4; l++) {
            int idx = tid + l * 256;
            int r = idx >> 3, ch = idx & 7;
            cp16(ab + r * 144 + ch * 16, &g_xb[(size_t)(row0 + r) * C_ + kc + ch * 8]);
        }
        #pragma unroll
        for (int l = 0; l < 2; l++) {
            int idx = tid + l * 256;
            int r = idx >> 3, ch = idx & 7;
            cp16(bb + r * 144 + ch * 16, &g_Wb[(size_t)(wrow0 + r) * C_ + kc + ch * 8]);
        }
        CP_COMMIT();
    }

    float acc[8][4];
    #pragma unroll
    for (int i = 0; i < 8; i++)
        #pragma unroll
        for (int j = 0; j < 4; j++) acc[i][j] = 0.f;

    for (int it = 0; it < 8; it++) {
        CP_WAIT1();
        __syncthreads();

        const uint32_t Ab = sAu + (it & 1) * PAB;
        const uint32_t Bb = sBu + (it & 1) * PBB;

        #pragma unroll
        for (int kk = 0; kk < 64; kk += 16) {
            uint32_t a0[4], a1[4], b0[4], b1[4];
            ldm4(a0, Ab + ((32 * wlo + lrow) * PITCH + kk + lcol) * 2);
            ldm4(a1, Ab + ((32 * wlo + 16 + lrow) * PITCH + kk + lcol) * 2);
            ldm4(b0, Bb + ((32 * whi + lrow) * PITCH + kk + lcol) * 2);
            ldm4(b1, Bb + ((32 * whi + 16 + lrow) * PITCH + kk + lcol) * 2);
            mma16(acc[0], a0, b0[0], b0[2]);
            mma16(acc[1], a0, b0[1], b0[3]);
            mma16(acc[2], a0, b1[0], b1[2]);
            mma16(acc[3], a0, b1[1], b1[3]);
            mma16(acc[4], a1, b0[0], b0[2]);
            mma16(acc[5], a1, b0[1], b0[3]);
            mma16(acc[6], a1, b1[0], b1[2]);
            mma16(acc[7], a1, b1[1], b1[3]);
        }
        __syncthreads();

        if (it + 2 < 8) {
            const int kc = (it + 2) * 64;
            const uint32_t ab = sAu + (it & 1) * PAB, bb = sBu + (it & 1) * PBB;
            #pragma unroll
            for (int l = 0; l < 4; l++) {
                int idx = tid + l * 256;
                int r = idx >> 3, ch = idx & 7;
                cp16(ab + r * 144 + ch * 16, &g_xb[(size_t)(row0 + r) * C_ + kc + ch * 8]);
            }
            #pragma unroll
            for (int l = 0; l < 2; l++) {
                int idx = tid + l * 256;
                int r = idx >> 3, ch = idx & 7;
                cp16(bb + r * 144 + ch * 16, &g_Wb[(size_t)(wrow0 + r) * C_ + kc + ch * 8]);
            }
        }
        CP_COMMIT();
    }

    __syncthreads();

    #pragma unroll
    for (int jf = 0; jf < 4; jf++) {
        const int oc = 32 * whi + 8 * jf + 2 * t;
        const float b0v = __ldg(&bias[oc]);
        const float b1v = __ldg(&bias[oc + 1]);
        #pragma unroll
        for (int fi = 0; fi < 2; fi++) {
            const int r = 32 * wlo + 16 * fi + g;
            const float* d = acc[4 * fi + jf];
            float v00 = d[0] + b0v;
            float v01 = d[1] + b1v;
            float v10 = d[2] + b0v;
            float v11 = d[3] + b1v;
            if (ot == 0) {
                g_K[(size_t)(row0 + r) * CR_ + oc]         = __float2bfloat16_rn(v00);
                g_K[(size_t)(row0 + r) * CR_ + oc + 1]     = __float2bfloat16_rn(v01);
                g_K[(size_t)(row0 + r + 8) * CR_ + oc]     = __float2bfloat16_rn(v10);
                g_K[(size_t)(row0 + r + 8) * CR_ + oc + 1] = __float2bfloat16_rn(v11);
            } else if (ot == 1) {
                g_V[(size_t)(row0 + r) * CR_ + oc]         = __float2bfloat16_rn(v00);
                g_V[(size_t)(row0 + r) * CR_ + oc + 1]     = __float2bfloat16_rn(v01);
                g_V[(size_t)(row0 + r + 8) * CR_ + oc]     = __float2bfloat16_rn(v10);
                g_V[(size_t)(row0 + r + 8) * CR_ + oc + 1] = __float2bfloat16_rn(v11);
            } else {
                sT[oc * 132 + r]           = v00;
                sT[(oc + 1) * 132 + r]     = v01;
                sT[oc * 132 + r + 8]       = v10;
                sT[(oc + 1) * 132 + r + 8] = v11;
            }
        }
    }

    if (ot >= 2) {
        __syncthreads();
        const int b  = row0 >> 11;
        const int n0 = row0 & (N_ - 1);
        const size_t qrow0 = (size_t)b * C_ + (ot - 2) * 64;
        #pragma unroll
        for (int l = 0; l < 8; l++) {
            int idx = tid + l * 256;
            int o = idx >> 5, r4 = (idx & 31) << 2;
            float4 v = *(const float4*)&sT[o * 132 + r4];
            __nv_bfloat162 p0 = __floats2bfloat162_rn(v.x, v.y);
            __nv_bfloat162 p1 = __floats2bfloat162_rn(v.z, v.w);
            __nv_bfloat162* dst = (__nv_bfloat162*)&g_Qt[(qrow0 + o) * N_ + n0 + r4];
            dst[0] = p0; dst[1] = p1;
        }
    }
}

// =======================================================================
// Kernel 2: S = K@V^T, P = exp(S), partial den.  (computed ONCE)
// =======================================================================
#define KVB   (64 * PITCH * 2)
#define PX_SV  0
#define PX_SK  (PX_SV + KVB)
#define PX_SPT (PX_SK + 2 * KVB)
#define PX_DEN (PX_SPT + KVB)
#define PX_SMEM_BYTES (PX_DEN + 256)
__global__ __launch_bounds__(256, 2) void pexp_kernel()
{
    extern __shared__ char smc[];
    __nv_bfloat16* sPT16 = (__nv_bfloat16*)(smc + PX_SPT);
    float* sDen = (float*)(smc + PX_DEN);

    const uint32_t smu = smem_u32(smc);
    const uint32_t sVu = smu + PX_SV;
    const uint32_t sKu = smu + PX_SK;

    const int tid = threadIdx.x;
    const int wid = tid >> 5, lane = tid & 31;
    const int g = lane >> 2, t = lane & 3;
    const int wlo = wid & 3;
    const int whi = wid >> 2;
    const int lrow = lane & 15;
    const int lcol = (lane >> 4) << 3;

    const int mt = blockIdx.x, nr = blockIdx.y, b = blockIdx.z;
    const int m0 = mt * 64;
    const size_t rb = (size_t)b * N_;
    const size_t pbase = (size_t)b * N_ * N_;

    if (tid < 64) sDen[tid] = 0.f;

    #pragma unroll
    for (int l = 0; l < 2; l++) {
        int idx = tid + l * 256;
        int r = idx >> 3, ch = idx & 7;
        cp16(sVu + r * 144 + ch * 16, &g_V[(rb + m0 + r) * CR_ + ch * 8]);
        cp16(sKu + r * 144 + ch * 16, &g_K[(rb + nr * 512 + r) * CR_ + ch * 8]);
    }
    CP_COMMIT();
    #pragma unroll
    for (int l = 0; l < 2; l++) {
        int idx = tid + l * 256;
        int r = idx >> 3, ch = idx & 7;
        cp16(sKu + KVB + r * 144 + ch * 16, &g_K[(rb + nr * 512 + 64 + r) * CR_ + ch * 8]);
    }
    CP_COMMIT();

    float den[8];
    #pragma unroll
    for (int i = 0; i < 8; i++) den[i] = 0.f;

    for (int i = 0; i < 8; i++) {
        const int n0 = nr * 512 + i * 64;

        CP_WAIT1();
        __syncthreads();

        const uint32_t Kb = sKu + (i & 1) * KVB;

        float sacc[4][4];
        #pragma unroll
        for (int ii = 0; ii < 4; ii++)
            #pragma unroll
            for (int j = 0; j < 4; j++) sacc[ii][j] = 0.f;

        #pragma unroll
        for (int kk = 0; kk < 64; kk += 16) {
            uint32_t a[4], bv0[4], bv1[4];
            ldm4(a,   Kb  + ((16 * wlo + lrow) * PITCH + kk + lcol) * 2);
            ldm4(bv0, sVu + ((32 * whi + lrow) * PITCH + kk + lcol) * 2);
            ldm4(bv1, sVu + ((32 * whi + 16 + lrow) * PITCH + kk + lcol) * 2);
            mma16(sacc[0], a, bv0[0], bv0[2]);
            mma16(sacc[1], a, bv0[1], bv0[3]);
            mma16(sacc[2], a, bv1[0], bv1[2]);
            mma16(sacc[3], a, bv1[1], bv1[3]);
        }

        const int nloc = 16 * wlo + g;
        #pragma unroll
        for (int jf = 0; jf < 4; jf++) {
            const int mc = 32 * whi + 8 * jf + 2 * t;
            float e00 = __expf(sacc[jf][0]);
            float e01 = __expf(sacc[jf][1]);
            float e10 = __expf(sacc[jf][2]);
            float e11 = __expf(sacc[jf][3]);
            den[2 * jf]     += e00 + e10;
            den[2 * jf + 1] += e01 + e11;
            sPT16[mc * PITCH + nloc]           = __float2bfloat16_rn(e00);
            sPT16[(mc + 1) * PITCH + nloc]     = __float2bfloat16_rn(e01);
            sPT16[mc * PITCH + nloc + 8]       = __float2bfloat16_rn(e10);
            sPT16[(mc + 1) * PITCH + nloc + 8] = __float2bfloat16_rn(e11);
        }
        __syncthreads();

        #pragma unroll
        for (int l = 0; l < 2; l++) {
            int idx = tid + l * 256;
            int r = idx >> 3, ch = idx & 7;
            float4 v = *(const float4*)((const char*)sPT16 + r * 144 + ch * 16);
            *(float4*)&g_P[pbase + (size_t)(m0 + r) * N_ + n0 + ch * 8] = v;
        }

        if (i + 2 < 8) {
            const int nn = nr * 512 + (i + 2) * 64;
            const uint32_t kb = sKu + (i & 1) * KVB;
            #pragma unroll
            for (int l = 0; l < 2; l++) {
                int idx = tid + l * 256;
                int r = idx >> 3, ch = idx & 7;
                cp16(kb + r * 144 + ch * 16, &g_K[(rb + nn + r) * CR_ + ch * 8]);
            }
        }
        CP_COMMIT();
    }

    #pragma unroll
    for (int jf = 0; jf < 4; jf++) {
        const int mc = 32 * whi + 8 * jf + 2 * t;
        atomicAdd(&sDen[mc],     den[2 * jf]);
        atomicAdd(&sDen[mc + 1], den[2 * jf + 1]);
    }
    __syncthreads();
    if (tid < 64)
        g_denp[(size_t)(b * 4 + nr) * N_ + m0 + tid] = sDen[tid];
}

// =======================================================================
// Kernel 3: attn2 — bf16 GEMM: Acc[c 128][m 128] = Qt @ P^T.
// grid (16 m-tiles, 4 c-tiles, 8 b), 256 threads.
// k-chunk 64, ring-3 cp.async. Warp tile: 32c x 64m (6 ldm : 16 mma).
// =======================================================================
#define TB2 (128 * PITCH * 2)     // 18432 B per 128-row x 64-k tile
#define A2_P  0
#define A2_Q  (A2_P + 3 * TB2)
#define A2_SMEM_BYTES (A2_Q + 3 * TB2)   // 110592
#define NT2 32
__global__ __launch_bounds__(256, 2) void attn2_kernel(
    const float* __restrict__ x, const float* __restrict__ gamma_p,
    float* __restrict__ out)
{
    extern __shared__ char smc[];
    const uint32_t smu = smem_u32(smc);
    const uint32_t sPu = smu + A2_P;
    const uint32_t sQu = smu + A2_Q;

    const int tid = threadIdx.x;
    const int wid = tid >> 5, lane = tid & 31;
    const int g = lane >> 2, t = lane & 3;
    const int wlo = wid & 3;        // c group (32): 4 x 32 = 128c
    const int whi = wid >> 2;       // m group (64): 2 x 64 = 128m
    const int lrow = lane & 15;
    const int lcol = (lane >> 4) << 3;

    const int mt = blockIdx.x, ct = blockIdx.y, b = blockIdx.z;
    const int m0 = mt * 128, c0 = ct * 128;
    const size_t rb = (size_t)b * N_;
    const size_t qbase = ((size_t)b * C_ + c0) * N_;
    const size_t pbase = (size_t)b * N_ * N_ + (size_t)m0 * N_;

    // prefetch stages 0,1,2
    #pragma unroll
    for (int s = 0; s < 3; s++) {
        const int n0 = s * 64;
        const uint32_t pb = sPu + s * TB2;
        const uint32_t qb = sQu + s * TB2;
        #pragma unroll
        for (int l = 0; l < 4; l++) {
            int idx = tid + l * 256;
            int r = idx >> 3, ch = idx & 7;
            cp16(pb + r * 144 + ch * 16, &g_P[pbase + (size_t)r * N_ + n0 + ch * 8]);
            cp16(qb + r * 144 + ch * 16, &g_Qt[qbase + (size_t)r * N_ + n0 + ch * 8]);
        }
        CP_COMMIT();
    }

    float acc[16][4];   // [fi*8 + pj*2 + h]
    #pragma unroll
    for (int i = 0; i < 16; i++)
        #pragma unroll
        for (int j = 0; j < 4; j++) acc[i][j] = 0.f;

    for (int nt = 0; nt < NT2; nt++) {
        CP_WAIT2();          // stage nt complete (<=2 groups pending)
        __syncthreads();

        const uint32_t Pb = sPu + (nt % 3) * TB2;
        const uint32_t Qb = sQu + (nt % 3) * TB2;

        #pragma unroll
        for (int kk = 0; kk < 64; kk += 16) {
            uint32_t a0[4], a1[4], p0[4], p1[4], p2[4], p3[4];
            ldm4(a0, Qb + ((32 * wlo + lrow) * PITCH + kk + lcol) * 2);
            ldm4(a1, Qb + ((32 * wlo + 16 + lrow) * PITCH + kk + lcol) * 2);
            ldm4(p0, Pb + ((64 * whi + lrow) * PITCH + kk + lcol) * 2);
            ldm4(p1, Pb + ((64 * whi + 16 + lrow) * PITCH + kk + lcol) * 2);
            ldm4(p2, Pb + ((64 * whi + 32 + lrow) * PITCH + kk + lcol) * 2);
            ldm4(p3, Pb + ((64 * whi + 48 + lrow) * PITCH + kk + lcol) * 2);
            mma16(acc[0],  a0, p0[0], p0[2]);
            mma16(acc[1],  a0, p0[1], p0[3]);
            mma16(acc[2],  a0, p1[0], p1[2]);
            mma16(acc[3],  a0, p1[1], p1[3]);
            mma16(acc[4],  a0, p2[0], p2[2]);
            mma16(acc[5],  a0, p2[1], p2[3]);
            mma16(acc[6],  a0, p3[0], p3[2]);
            mma16(acc[7],  a0, p3[1], p3[3]);
            mma16(acc[8],  a1, p0[0], p0[2]);
            mma16(acc[9],  a1, p0[1], p0[3]);
            mma16(acc[10], a1, p1[0], p1[2]);
            mma16(acc[11], a1, p1[1], p1[3]);
            mma16(acc[12], a1, p2[0], p2[2]);
            mma16(acc[13], a1, p2[1], p2[3]);
            mma16(acc[14], a1, p3[0], p3[2]);
            mma16(acc[15], a1, p3[1], p3[3]);
        }
        __syncthreads();     // buffer nt%3 free

        if (nt + 3 < NT2) {
            const int n1 = (nt + 3) * 64;
            const uint32_t pb = sPu + (nt % 3) * TB2;
            const uint32_t qb = sQu + (nt % 3) * TB2;
            #pragma unroll
            for (int l = 0; l < 4; l++) {
                int idx = tid + l * 256;
                int r = idx >> 3, ch = idx & 7;
                cp16(pb + r * 144 + ch * 16, &g_P[pbase + (size_t)r * N_ + n1 + ch * 8]);
                cp16(qb + r * 144 + ch * 16, &g_Qt[qbase + (size_t)r * N_ + n1 + ch * 8]);
            }
        }
        CP_COMMIT();
    }

    // ---- epilogue: out = gamma*Acc/den + x ----
    const float gam = gamma_p[0];
    #pragma unroll
    for (int pj = 0; pj < 4; pj++) {
        #pragma unroll
        for (int h = 0; h < 2; h++) {
            const int mc = 64 * whi + 16 * pj + 8 * h + 2 * t;
            float d0 = 0.f, d1 = 0.f;
            #pragma unroll
            for (int nr = 0; nr < 4; nr++) {
                d0 += __ldg(&g_denp[(size_t)(b * 4 + nr) * N_ + m0 + mc]);
                d1 += __ldg(&g_denp[(size_t)(b * 4 + nr) * N_ + m0 + mc + 1]);
            }
            const float di0 = gam / d0;
            const float di1 = gam / d1;
            #pragma unroll
            for (int fi = 0; fi < 2; fi++) {
                const int cc = c0 + 32 * wlo + 16 * fi + g;
                const size_t r0a = (rb + m0 + mc) * C_ + cc;
                const size_t r1a = (rb + m0 + mc + 1) * C_ + cc;
                const float* d = acc[fi * 8 + pj * 2 + h];
                out[r0a]     = d[0] * di0 + __ldg(&x[r0a]);
                out[r1a]     = d[1] * di1 + __ldg(&x[r1a]);
                out[r0a + 8] = d[2] * di0 + __ldg(&x[r0a + 8]);
                out[r1a + 8] = d[3] * di1 + __ldg(&x[r1a + 8]);
            }
        }
    }
}

// =======================================================================
extern "C" void kernel_launch(void* const* d_in, const int* in_sizes, int n_in,
                              void* d_out, int out_size)
{
    const float* x     = (const float*)d_in[0];
    const float* Wk    = (const float*)d_in[1];
    const float* bk    = (const float*)d_in[2];
    const float* Wv    = (const float*)d_in[3];
    const float* bv    = (const float*)d_in[4];
    const float* Wq    = (const float*)d_in[5];
    const float* bq    = (const float*)d_in[6];
    const float* gamma = (const float*)d_in[7];
    float* out = (float*)d_out;

    cudaFuncSetAttribute(proj_hmma,    cudaFuncAttributeMaxDynamicSharedMemorySize, PJ_SMEM_BYTES);
    cudaFuncSetAttribute(pexp_kernel,  cudaFuncAttributeMaxDynamicSharedMemorySize, PX_SMEM_BYTES);
    cudaFuncSetAttribute(attn2_kernel, cudaFuncAttributeMaxDynamicSharedMemorySize, A2_SMEM_BYTES);

    cvt_kernel<<<1184, 256>>>(x, Wk, Wv, Wq);
    proj_hmma<<<dim3(10, 128), 256, PJ_SMEM_BYTES>>>(bk, bv, bq);
    pexp_kernel<<<dim3(32, 4, B_), 256, PX_SMEM_BYTES>>>();
    attn2_kernel<<<dim3(16, 4, B_), 256, A2_SMEM_BYTES>>>(x, gamma, out);
}

// round 10
// speedup vs baseline: 6.6795x; 1.0029x over previous
#include <cuda_runtime.h>
#include <cuda_bf16.h>
#include <cstdint>

#define B_  8
#define N_  2048
#define C_  512
#define CR_ 64

// Device-global scratch (no allocs allowed).
__device__ __nv_bfloat16 g_xb[(size_t)B_ * N_ * C_];    // x in bf16
__device__ __nv_bfloat16 g_Wb[(size_t)640 * C_];        // [Wk;Wv;Wq] bf16
__device__ __nv_bfloat16 g_K [(size_t)B_ * N_ * CR_];   // [b*N+n][64]
__device__ __nv_bfloat16 g_V [(size_t)B_ * N_ * CR_];   // [b*N+m][64]
__device__ __nv_bfloat16 g_Qt[(size_t)B_ * C_ * N_];    // [b*C+c][n]
__device__ __nv_bfloat16 g_P [(size_t)B_ * N_ * N_];    // P^T: [b][m][n]
__device__ float         g_denp[(size_t)B_ * 4 * N_];   // partial den

__device__ __forceinline__ uint32_t smem_u32(const void* p) {
    uint32_t a;
    asm("{ .reg .u64 t; cvta.to.shared.u64 t, %1; cvt.u32.u64 %0, t; }" : "=r"(a) : "l"(p));
    return a;
}
__device__ __forceinline__ void cp16(uint32_t dst, const void* src) {
    asm volatile("cp.async.cg.shared.global [%0], [%1], 16;" :: "r"(dst), "l"(src));
}
#define CP_COMMIT() asm volatile("cp.async.commit_group;" ::: "memory")
#define CP_WAIT0()  asm volatile("cp.async.wait_group 0;"  ::: "memory")
#define CP_WAIT1()  asm volatile("cp.async.wait_group 1;"  ::: "memory")

// bf16 warp mma: D(16x8) += A(16x16)*B(16x8)
__device__ __forceinline__ void mma16(float d[4], const uint32_t a[4], uint32_t b0, uint32_t b1) {
    asm volatile(
        "mma.sync.aligned.m16n8k16.row.col.f32.bf16.bf16.f32 "
        "{%0,%1,%2,%3}, {%4,%5,%6,%7}, {%8,%9}, {%0,%1,%2,%3};"
        : "+f"(d[0]), "+f"(d[1]), "+f"(d[2]), "+f"(d[3])
        : "r"(a[0]), "r"(a[1]), "r"(a[2]), "r"(a[3]), "r"(b0), "r"(b1));
}
__device__ __forceinline__ void ldm4(uint32_t r[4], uint32_t addr) {
    asm volatile("ldmatrix.sync.aligned.m8n8.x4.shared.b16 {%0,%1,%2,%3}, [%4];"
        : "=r"(r[0]), "=r"(r[1]), "=r"(r[2]), "=r"(r[3]) : "r"(addr));
}

// =======================================================================
// Kernel 0: fp32 -> bf16 conversion of x and [Wk;Wv;Wq].
// =======================================================================
__global__ __launch_bounds__(256) void cvt_kernel(
    const float* __restrict__ x,
    const float* __restrict__ Wk, const float* __restrict__ Wv,
    const float* __restrict__ Wq)
{
    const int NX = (B_ * N_ * C_) / 4;
    const int NW = (640 * C_) / 4;
    for (int i = blockIdx.x * blockDim.x + threadIdx.x; i < NX + NW;
         i += gridDim.x * blockDim.x) {
        float4 v;
        __nv_bfloat16* dst;
        if (i < NX) {
            v = ((const float4*)x)[i];
            dst = &g_xb[(size_t)i * 4];
        } else {
            int j = i - NX;
            const int row = (j * 4) / C_;
            const float* src;
            if (row < 64)        src = Wk;
            else if (row < 128)  src = Wv - 64 * C_;
            else                 src = Wq - 128 * C_;
            v = ((const float4*)src)[j];
            dst = &g_Wb[(size_t)j * 4];
        }
        __nv_bfloat162 p0 = __floats2bfloat162_rn(v.x, v.y);
        __nv_bfloat162 p1 = __floats2bfloat162_rn(v.z, v.w);
        ((__nv_bfloat162*)dst)[0] = p0;
        ((__nv_bfloat162*)dst)[1] = p1;
    }
}

// =======================================================================
// Kernel 1: projection GEMM (bf16 HMMA + ldmatrix), ring-3, 1 barrier/iter.
// =======================================================================
#define PITCH 72
#define PAB (128 * PITCH * 2)
#define PBB (64  * PITCH * 2)
#define PJ_A 0
#define PJ_B (PJ_A + 3 * PAB)
#define PJ_SMEM_BYTES (PJ_B + 3 * PBB)   // 82944
__global__ __launch_bounds__(256, 2) void proj_hmma(
    const float* __restrict__ bk, const float* __restrict__ bv,
    const float* __restrict__ bq)
{
    extern __shared__ char smc[];
    float* sT = (float*)smc;

    const uint32_t smu = smem_u32(smc);
    const uint32_t sAu = smu + PJ_A, sBu = smu + PJ_B;

    const int tid = threadIdx.x;
    const int wid = tid >> 5, lane = tid & 31;
    const int g = lane >> 2, t = lane & 3;
    const int wlo = wid & 3;
    const int whi = wid >> 2;
    const int lrow = lane & 15;
    const int lcol = (lane >> 4) << 3;

    const int ot = blockIdx.x;
    const int row0 = blockIdx.y * 128;
    const int wrow0 = ot * 64;

    const float* bias;
    if (ot == 0)      bias = bk;
    else if (ot == 1) bias = bv;
    else              bias = bq + (ot - 2) * 64;

    // prologue: stages 0,1
    #pragma unroll
    for (int pf = 0; pf < 2; pf++) {
        const int kc = pf * 64;
        const uint32_t ab = sAu + pf * PAB, bb = sBu + pf * PBB;
        #pragma unroll
        for (int l = 0; l < 4; l++) {
            int idx = tid + l * 256;
            int r = idx >> 3, ch = idx & 7;
            cp16(ab + r * 144 + ch * 16, &g_xb[(size_t)(row0 + r) * C_ + kc + ch * 8]);
        }
        #pragma unroll
        for (int l = 0; l < 2; l++) {
            int idx = tid + l * 256;
            int r = idx >> 3, ch = idx & 7;
            cp16(bb + r * 144 + ch * 16, &g_Wb[(size_t)(wrow0 + r) * C_ + kc + ch * 8]);
        }
        CP_COMMIT();
    }

    float acc[8][4];
    #pragma unroll
    for (int i = 0; i < 8; i++)
        #pragma unroll
        for (int j = 0; j < 4; j++) acc[i][j] = 0.f;

    uint32_t sl0 = 0, sl1 = 1, sl2 = 2;   // slot ring (consume sl0, prefetch sl2)
    for (int it = 0; it < 8; it++) {
        CP_WAIT1();
        __syncthreads();

        // prefetch stage it+2 into slot sl2 (freed at it-1)
        if (it + 2 < 8) {
            const int kc = (it + 2) * 64;
            const uint32_t ab = sAu + sl2 * PAB, bb = sBu + sl2 * PBB;
            #pragma unroll
            for (int l = 0; l < 4; l++) {
                int idx = tid + l * 256;
                int r = idx >> 3, ch = idx & 7;
                cp16(ab + r * 144 + ch * 16, &g_xb[(size_t)(row0 + r) * C_ + kc + ch * 8]);
            }
            #pragma unroll
            for (int l = 0; l < 2; l++) {
                int idx = tid + l * 256;
                int r = idx >> 3, ch = idx & 7;
                cp16(bb + r * 144 + ch * 16, &g_Wb[(size_t)(wrow0 + r) * C_ + kc + ch * 8]);
            }
        }
        CP_COMMIT();

        const uint32_t Ab = sAu + sl0 * PAB;
        const uint32_t Bb = sBu + sl0 * PBB;

        #pragma unroll
        for (int kk = 0; kk < 64; kk += 16) {
            uint32_t a0[4], a1[4], b0[4], b1[4];
            ldm4(a0, Ab + ((32 * wlo + lrow) * PITCH + kk + lcol) * 2);
            ldm4(a1, Ab + ((32 * wlo + 16 + lrow) * PITCH + kk + lcol) * 2);
            ldm4(b0, Bb + ((32 * whi + lrow) * PITCH + kk + lcol) * 2);
            ldm4(b1, Bb + ((32 * whi + 16 + lrow) * PITCH + kk + lcol) * 2);
            mma16(acc[0], a0, b0[0], b0[2]);
            mma16(acc[1], a0, b0[1], b0[3]);
            mma16(acc[2], a0, b1[0], b1[2]);
            mma16(acc[3], a0, b1[1], b1[3]);
            mma16(acc[4], a1, b0[0], b0[2]);
            mma16(acc[5], a1, b0[1], b0[3]);
            mma16(acc[6], a1, b1[0], b1[2]);
            mma16(acc[7], a1, b1[1], b1[3]);
        }

        uint32_t tmp = sl0; sl0 = sl1; sl1 = sl2; sl2 = tmp;
    }

    CP_WAIT0();
    __syncthreads();  // sT aliases A buffers; all mma done (program order)

    #pragma unroll
    for (int jf = 0; jf < 4; jf++) {
        const int oc = 32 * whi + 8 * jf + 2 * t;
        const float b0v = __ldg(&bias[oc]);
        const float b1v = __ldg(&bias[oc + 1]);
        #pragma unroll
        for (int fi = 0; fi < 2; fi++) {
            const int r = 32 * wlo + 16 * fi + g;
            const float* d = acc[4 * fi + jf];
            float v00 = d[0] + b0v;
            float v01 = d[1] + b1v;
            float v10 = d[2] + b0v;
            float v11 = d[3] + b1v;
            if (ot == 0) {
                g_K[(size_t)(row0 + r) * CR_ + oc]         = __float2bfloat16_rn(v00);
                g_K[(size_t)(row0 + r) * CR_ + oc + 1]     = __float2bfloat16_rn(v01);
                g_K[(size_t)(row0 + r + 8) * CR_ + oc]     = __float2bfloat16_rn(v10);
                g_K[(size_t)(row0 + r + 8) * CR_ + oc + 1] = __float2bfloat16_rn(v11);
            } else if (ot == 1) {
                g_V[(size_t)(row0 + r) * CR_ + oc]         = __float2bfloat16_rn(v00);
                g_V[(size_t)(row0 + r) * CR_ + oc + 1]     = __float2bfloat16_rn(v01);
                g_V[(size_t)(row0 + r + 8) * CR_ + oc]     = __float2bfloat16_rn(v10);
                g_V[(size_t)(row0 + r + 8) * CR_ + oc + 1] = __float2bfloat16_rn(v11);
            } else {
                sT[oc * 132 + r]           = v00;
                sT[(oc + 1) * 132 + r]     = v01;
                sT[oc * 132 + r + 8]       = v10;
                sT[(oc + 1) * 132 + r + 8] = v11;
            }
        }
    }

    if (ot >= 2) {
        __syncthreads();
        const int b  = row0 >> 11;
        const int n0 = row0 & (N_ - 1);
        const size_t qrow0 = (size_t)b * C_ + (ot - 2) * 64;
        #pragma unroll
        for (int l = 0; l < 8; l++) {
            int idx = tid + l * 256;
            int o = idx >> 5, r4 = (idx & 31) << 2;
            float4 v = *(const float4*)&sT[o * 132 + r4];
            __nv_bfloat162 p0 = __floats2bfloat162_rn(v.x, v.y);
            __nv_bfloat162 p1 = __floats2bfloat162_rn(v.z, v.w);
            __nv_bfloat162* dst = (__nv_bfloat162*)&g_Qt[(qrow0 + o) * N_ + n0 + r4];
            dst[0] = p0; dst[1] = p1;
        }
    }
}

// =======================================================================
// Kernel 2: S = K@V^T, P = exp(S), partial den.  K ring-3, sPT x2,
// copy-out pipelined one iter behind -> 1 barrier/iter.
// =======================================================================
#define KVB   (64 * PITCH * 2)   // 9216 B
#define PX_SV  0
#define PX_SK  (PX_SV + KVB)            // 3 K slots
#define PX_SPT (PX_SK + 3 * KVB)        // 2 sPT buffers
#define PX_DEN (PX_SPT + 2 * KVB)
#define PX_SMEM_BYTES (PX_DEN + 256)    // 55552
__global__ __launch_bounds__(256, 2) void pexp_kernel()
{
    extern __shared__ char smc[];
    float* sDen = (float*)(smc + PX_DEN);

    const uint32_t smu = smem_u32(smc);
    const uint32_t sVu = smu + PX_SV;
    const uint32_t sKu = smu + PX_SK;
    const uint32_t sPu = smu + PX_SPT;

    const int tid = threadIdx.x;
    const int wid = tid >> 5, lane = tid & 31;
    const int g = lane >> 2, t = lane & 3;
    const int wlo = wid & 3;
    const int whi = wid >> 2;
    const int lrow = lane & 15;
    const int lcol = (lane >> 4) << 3;

    const int mt = blockIdx.x, nr = blockIdx.y, b = blockIdx.z;
    const int m0 = mt * 64;
    const size_t rb = (size_t)b * N_;
    const size_t pbase = (size_t)b * N_ * N_;

    if (tid < 64) sDen[tid] = 0.f;

    // prologue: group0 = V + K0, group1 = K1
    #pragma unroll
    for (int l = 0; l < 2; l++) {
        int idx = tid + l * 256;
        int r = idx >> 3, ch = idx & 7;
        cp16(sVu + r * 144 + ch * 16, &g_V[(rb + m0 + r) * CR_ + ch * 8]);
        cp16(sKu + r * 144 + ch * 16, &g_K[(rb + nr * 512 + r) * CR_ + ch * 8]);
    }
    CP_COMMIT();
    #pragma unroll
    for (int l = 0; l < 2; l++) {
        int idx = tid + l * 256;
        int r = idx >> 3, ch = idx & 7;
        cp16(sKu + KVB + r * 144 + ch * 16, &g_K[(rb + nr * 512 + 64 + r) * CR_ + ch * 8]);
    }
    CP_COMMIT();

    float den[8];
    #pragma unroll
    for (int i = 0; i < 8; i++) den[i] = 0.f;

    uint32_t k0 = 0, k1 = 1, k2 = 2;   // K slot ring
    for (int i = 0; i < 8; i++) {
        CP_WAIT1();
        __syncthreads();   // all warps done exp(i-1) + mma(i-1); K(i) visible

        // copy-out sPT from iter i-1 (pipelined)
        if (i > 0) {
            const uint32_t spOld = sPu + ((i - 1) & 1) * KVB;
            const int nOld = nr * 512 + (i - 1) * 64;
            #pragma unroll
            for (int l = 0; l < 2; l++) {
                int idx = tid + l * 256;
                int r = idx >> 3, ch = idx & 7;
                float4 v = *(const float4*)(smc + (spOld - smu) + r * 144 + ch * 16);
                *(float4*)&g_P[pbase + (size_t)(m0 + r) * N_ + nOld + ch * 8] = v;
            }
        }

        // prefetch K(i+2) into slot k2 (freed at i-1)
        if (i + 2 < 8) {
            const int nn = nr * 512 + (i + 2) * 64;
            const uint32_t kb = sKu + k2 * KVB;
            #pragma unroll
            for (int l = 0; l < 2; l++) {
                int idx = tid + l * 256;
                int r = idx >> 3, ch = idx & 7;
                cp16(kb + r * 144 + ch * 16, &g_K[(rb + nn + r) * CR_ + ch * 8]);
            }
        }
        CP_COMMIT();

        const uint32_t Kb = sKu + k0 * KVB;

        float sacc[4][4];
        #pragma unroll
        for (int ii = 0; ii < 4; ii++)
            #pragma unroll
            for (int j = 0; j < 4; j++) sacc[ii][j] = 0.f;

        #pragma unroll
        for (int kk = 0; kk < 64; kk += 16) {
            uint32_t a[4], bv0[4], bv1[4];
            ldm4(a,   Kb  + ((16 * wlo + lrow) * PITCH + kk + lcol) * 2);
            ldm4(bv0, sVu + ((32 * whi + lrow) * PITCH + kk + lcol) * 2);
            ldm4(bv1, sVu + ((32 * whi + 16 + lrow) * PITCH + kk + lcol) * 2);
            mma16(sacc[0], a, bv0[0], bv0[2]);
            mma16(sacc[1], a, bv0[1], bv0[3]);
            mma16(sacc[2], a, bv1[0], bv1[2]);
            mma16(sacc[3], a, bv1[1], bv1[3]);
        }

        // exp -> sPT[i&1]
        __nv_bfloat16* sPT16 = (__nv_bfloat16*)(smc + PX_SPT + (i & 1) * KVB);
        const int nloc = 16 * wlo + g;
        #pragma unroll
        for (int jf = 0; jf < 4; jf++) {
            const int mc = 32 * whi + 8 * jf + 2 * t;
            float e00 = __expf(sacc[jf][0]);
            float e01 = __expf(sacc[jf][1]);
            float e10 = __expf(sacc[jf][2]);
            float e11 = __expf(sacc[jf][3]);
            den[2 * jf]     += e00 + e10;
            den[2 * jf + 1] += e01 + e11;
            sPT16[mc * PITCH + nloc]           = __float2bfloat16_rn(e00);
            sPT16[(mc + 1) * PITCH + nloc]     = __float2bfloat16_rn(e01);
            sPT16[mc * PITCH + nloc + 8]       = __float2bfloat16_rn(e10);
            sPT16[(mc + 1) * PITCH + nloc + 8] = __float2bfloat16_rn(e11);
        }

        uint32_t tmp = k0; k0 = k1; k1 = k2; k2 = tmp;
    }

    __syncthreads();   // all warps' exp(7) done
    {   // final copy-out (i = 7, buffer 1)
        const uint32_t spOld = sPu + KVB;
        const int nOld = nr * 512 + 7 * 64;
        #pragma unroll
        for (int l = 0; l < 2; l++) {
            int idx = tid + l * 256;
            int r = idx >> 3, ch = idx & 7;
            float4 v = *(const float4*)(smc + (spOld - smu) + r * 144 + ch * 16);
            *(float4*)&g_P[pbase + (size_t)(m0 + r) * N_ + nOld + ch * 8] = v;
        }
    }

    #pragma unroll
    for (int jf = 0; jf < 4; jf++) {
        const int mc = 32 * whi + 8 * jf + 2 * t;
        atomicAdd(&sDen[mc],     den[2 * jf]);
        atomicAdd(&sDen[mc + 1], den[2 * jf + 1]);
    }
    __syncthreads();
    if (tid < 64)
        g_denp[(size_t)(b * 4 + nr) * N_ + m0 + tid] = sDen[tid];
}

// =======================================================================
// Kernel 3: attn2 — bf16 GEMM: Acc[c 128][m 128] = Qt @ P^T.
// grid (16 m-tiles, 4 c-tiles, 8 b), ring-3, 1 barrier/iter.
// =======================================================================
#define TB2 (128 * PITCH * 2)     // 18432 B per 128-row x 64-k tile
#define A2_P  0
#define A2_Q  (A2_P + 3 * TB2)
#define A2_SMEM_BYTES (A2_Q + 3 * TB2)   // 110592
#define NT2 32
__global__ __launch_bounds__(256, 2) void attn2_kernel(
    const float* __restrict__ x, const float* __restrict__ gamma_p,
    float* __restrict__ out)
{
    extern __shared__ char smc[];
    const uint32_t smu = smem_u32(smc);
    const uint32_t sPu = smu + A2_P;
    const uint32_t sQu = smu + A2_Q;

    const int tid = threadIdx.x;
    const int wid = tid >> 5, lane = tid & 31;
    const int g = lane >> 2, t = lane & 3;
    const int wlo = wid & 3;        // c group (32): 4 x 32 = 128c
    const int whi = wid >> 2;       // m group (64): 2 x 64 = 128m
    const int lrow = lane & 15;
    const int lcol = (lane >> 4) << 3;

    const int mt = blockIdx.x, ct = blockIdx.y, b = blockIdx.z;
    const int m0 = mt * 128, c0 = ct * 128;
    const size_t rb = (size_t)b * N_;
    const size_t qbase = ((size_t)b * C_ + c0) * N_;
    const size_t pbase = (size_t)b * N_ * N_ + (size_t)m0 * N_;

    // prologue: stages 0,1
    #pragma unroll
    for (int s = 0; s < 2; s++) {
        const int n0 = s * 64;
        const uint32_t pb = sPu + s * TB2;
        const uint32_t qb = sQu + s * TB2;
        #pragma unroll
        for (int l = 0; l < 4; l++) {
            int idx = tid + l * 256;
            int r = idx >> 3, ch = idx & 7;
            cp16(pb + r * 144 + ch * 16, &g_P[pbase + (size_t)r * N_ + n0 + ch * 8]);
            cp16(qb + r * 144 + ch * 16, &g_Qt[qbase + (size_t)r * N_ + n0 + ch * 8]);
        }
        CP_COMMIT();
    }

    float acc[16][4];   // [fi*8 + pj*2 + h]
    #pragma unroll
    for (int i = 0; i < 16; i++)
        #pragma unroll
        for (int j = 0; j < 4; j++) acc[i][j] = 0.f;

    uint32_t sl0 = 0, sl1 = 1, sl2 = 2;   // consume sl0, prefetch into sl2
    for (int nt = 0; nt < NT2; nt++) {
        CP_WAIT1();          // stage nt complete
        __syncthreads();     // all warps done mma(nt-1); slot sl2 free

        if (nt + 2 < NT2) {
            const int n1 = (nt + 2) * 64;
            const uint32_t pb = sPu + sl2 * TB2;
            const uint32_t qb = sQu + sl2 * TB2;
            #pragma unroll
            for (int l = 0; l < 4; l++) {
                int idx = tid + l * 256;
                int r = idx >> 3, ch = idx & 7;
                cp16(pb + r * 144 + ch * 16, &g_P[pbase + (size_t)r * N_ + n1 + ch * 8]);
                cp16(qb + r * 144 + ch * 16, &g_Qt[qbase + (size_t)r * N_ + n1 + ch * 8]);
            }
        }
        CP_COMMIT();

        const uint32_t Pb = sPu + sl0 * TB2;
        const uint32_t Qb = sQu + sl0 * TB2;

        #pragma unroll
        for (int kk = 0; kk < 64; kk += 16) {
            uint32_t a0[4], a1[4], p0[4], p1[4], p2[4], p3[4];
            ldm4(a0, Qb + ((32 * wlo + lrow) * PITCH + kk + lcol) * 2);
            ldm4(a1, Qb + ((32 * wlo + 16 + lrow) * PITCH + kk + lcol) * 2);
            ldm4(p0, Pb + ((64 * whi + lrow) * PITCH + kk + lcol) * 2);
            ldm4(p1, Pb + ((64 * whi + 16 + lrow) * PITCH + kk + lcol) * 2);
            ldm4(p2, Pb + ((64 * whi + 32 + lrow) * PITCH + kk + lcol) * 2);
            ldm4(p3, Pb + ((64 * whi + 48 + lrow) * PITCH + kk + lcol) * 2);
            mma16(acc[0],  a0, p0[0], p0[2]);
            mma16(acc[1],  a0, p0[1], p0[3]);
            mma16(acc[2],  a0, p1[0], p1[2]);
            mma16(acc[3],  a0, p1[1], p1[3]);
            mma16(acc[4],  a0, p2[0], p2[2]);
            mma16(acc[5],  a0, p2[1], p2[3]);
            mma16(acc[6],  a0, p3[0], p3[2]);
            mma16(acc[7],  a0, p3[1], p3[3]);
            mma16(acc[8],  a1, p0[0], p0[2]);
            mma16(acc[9],  a1, p0[1], p0[3]);
            mma16(acc[10], a1, p1[0], p1[2]);
            mma16(acc[11], a1, p1[1], p1[3]);
            mma16(acc[12], a1, p2[0], p2[2]);
            mme_dummy_:;
            mma16(acc[13], a1, p2[1], p2[3]);
            mma16(acc[14], a1, p3[0], p3[2]);
            mma16(acc[15], a1, p3[1], p3[3]);
        }

        uint32_t tmp = sl0; sl0 = sl1; sl1 = sl2; sl2 = tmp;
    }

    // ---- epilogue: out = gamma*Acc/den + x ----
    const float gam = gamma_p[0];
    #pragma unroll
    for (int pj = 0; pj < 4; pj++) {
        #pragma unroll
        for (int h = 0; h < 2; h++) {
            const int mc = 64 * whi + 16 * pj + 8 * h + 2 * t;
            float d0 = 0.f, d1 = 0.f;
            #pragma unroll
            for (int nr = 0; nr < 4; nr++) {
                d0 += __ldg(&g_denp[(size_t)(b * 4 + nr) * N_ + m0 + mc]);
                d1 += __ldg(&g_denp[(size_t)(b * 4 + nr) * N_ + m0 + mc + 1]);
            }
            const float di0 = gam / d0;
            const float di1 = gam / d1;
            #pragma unroll
            for (int fi = 0; fi < 2; fi++) {
                const int cc = c0 + 32 * wlo + 16 * fi + g;
                const size_t r0a = (rb + m0 + mc) * C_ + cc;
                const size_t r1a = (rb + m0 + mc + 1) * C_ + cc;
                const float* d = acc[fi * 8 + pj * 2 + h];
                out[r0a]     = d[0] * di0 + __ldg(&x[r0a]);
                out[r1a]     = d[1] * di1 + __ldg(&x[r1a]);
                out[r0a + 8] = d[2] * di0 + __ldg(&x[r0a + 8]);
                out[r1a + 8] = d[3] * di1 + __ldg(&x[r1a + 8]);
            }
        }
    }
}

// =======================================================================
extern "C" void kernel_launch(void* const* d_in, const int* in_sizes, int n_in,
                              void* d_out, int out_size)
{
    const float* x     = (const float*)d_in[0];
    const float* Wk    = (const float*)d_in[1];
    const float* bk    = (const float*)d_in[2];
    const float* Wv    = (const float*)d_in[3];
    const float* bv    = (const float*)d_in[4];
    const float* Wq    = (const float*)d_in[5];
    const float* bq    = (const float*)d_in[6];
    const float* gamma = (const float*)d_in[7];
    float* out = (float*)d_out;

    cudaFuncSetAttribute(proj_hmma,    cudaFuncAttributeMaxDynamicSharedMemorySize, PJ_SMEM_BYTES);
    cudaFuncSetAttribute(pexp_kernel,  cudaFuncAttributeMaxDynamicSharedMemorySize, PX_SMEM_BYTES);
    cudaFuncSetAttribute(attn2_kernel, cudaFuncAttributeMaxDynamicSharedMemorySize, A2_SMEM_BYTES);

    cvt_kernel<<<1184, 256>>>(x, Wk, Wv, Wq);
    proj_hmma<<<dim3(10, 128), 256, PJ_SMEM_BYTES>>>(bk, bv, bq);
    pexp_kernel<<<dim3(32, 4, B_), 256, PX_SMEM_BYTES>>>();
    attn2_kernel<<<dim3(16, 4, B_), 256, A2_SMEM_BYTES>>>(x, gamma, out);
}

// round 11
// speedup vs baseline: 6.9121x; 1.0348x over previous
#include <cuda_runtime.h>
#include <cuda_bf16.h>
#include <cuda_fp8.h>
#include <cstdint>

#define B_  8
#define N_  2048
#define C_  512
#define CR_ 64

// Device-global scratch (no allocs allowed).
__device__ __nv_bfloat16 g_xb[(size_t)B_ * N_ * C_];    // x in bf16
__device__ __nv_bfloat16 g_Wb[(size_t)640 * C_];        // [Wk;Wv;Wq] bf16
__device__ __nv_bfloat16 g_K [(size_t)B_ * N_ * CR_];   // [b*N+n][64]
__device__ __nv_bfloat16 g_V [(size_t)B_ * N_ * CR_];   // [b*N+m][64]
__device__ unsigned char g_Q8[(size_t)B_ * C_ * N_];    // Qt e4m3: [b*C+c][n]
__device__ unsigned char g_P8[(size_t)B_ * N_ * N_];    // P^T e4m3: [b][m][n]
__device__ float         g_denp[(size_t)B_ * 4 * N_];   // partial den

__device__ __forceinline__ uint32_t smem_u32(const void* p) {
    uint32_t a;
    asm("{ .reg .u64 t; cvta.to.shared.u64 t, %1; cvt.u32.u64 %0, t; }" : "=r"(a) : "l"(p));
    return a;
}
__device__ __forceinline__ void cp16(uint32_t dst, const void* src) {
    asm volatile("cp.async.cg.shared.global [%0], [%1], 16;" :: "r"(dst), "l"(src));
}
#define CP_COMMIT() asm volatile("cp.async.commit_group;" ::: "memory")
#define CP_WAIT0()  asm volatile("cp.async.wait_group 0;"  ::: "memory")
#define CP_WAIT1()  asm volatile("cp.async.wait_group 1;"  ::: "memory")

__device__ __forceinline__ unsigned char f2e4m3(float f) {
    return (unsigned char)__nv_cvt_float_to_fp8(f, __NV_SATFINITE, __NV_E4M3);
}

// bf16 warp mma: D(16x8) += A(16x16)*B(16x8)
__device__ __forceinline__ void mma16(float d[4], const uint32_t a[4], uint32_t b0, uint32_t b1) {
    asm volatile(
        "mma.sync.aligned.m16n8k16.row.col.f32.bf16.bf16.f32 "
        "{%0,%1,%2,%3}, {%4,%5,%6,%7}, {%8,%9}, {%0,%1,%2,%3};"
        : "+f"(d[0]), "+f"(d[1]), "+f"(d[2]), "+f"(d[3])
        : "r"(a[0]), "r"(a[1]), "r"(a[2]), "r"(a[3]), "r"(b0), "r"(b1));
}
// fp8 warp mma: D(16x8) += A(16x32)*B(32x8), e4m3
__device__ __forceinline__ void mma32(float d[4], const uint32_t a[4], uint32_t b0, uint32_t b1) {
    asm volatile(
        "mma.sync.aligned.m16n8k32.row.col.f32.e4m3.e4m3.f32 "
        "{%0,%1,%2,%3}, {%4,%5,%6,%7}, {%8,%9}, {%0,%1,%2,%3};"
        : "+f"(d[0]), "+f"(d[1]), "+f"(d[2]), "+f"(d[3])
        : "r"(a[0]), "r"(a[1]), "r"(a[2]), "r"(a[3]), "r"(b0), "r"(b1));
}
__device__ __forceinline__ void ldm4(uint32_t r[4], uint32_t addr) {
    asm volatile("ldmatrix.sync.aligned.m8n8.x4.shared.b16 {%0,%1,%2,%3}, [%4];"
        : "=r"(r[0]), "=r"(r[1]), "=r"(r[2]), "=r"(r[3]) : "r"(addr));
}

// =======================================================================
// Kernel 0: fp32 -> bf16 conversion of x and [Wk;Wv;Wq].
// =======================================================================
__global__ __launch_bounds__(256) void cvt_kernel(
    const float* __restrict__ x,
    const float* __restrict__ Wk, const float* __restrict__ Wv,
    const float* __restrict__ Wq)
{
    const int NX = (B_ * N_ * C_) / 4;
    const int NW = (640 * C_) / 4;
    for (int i = blockIdx.x * blockDim.x + threadIdx.x; i < NX + NW;
         i += gridDim.x * blockDim.x) {
        float4 v;
        __nv_bfloat16* dst;
        if (i < NX) {
            v = ((const float4*)x)[i];
            dst = &g_xb[(size_t)i * 4];
        } else {
            int j = i - NX;
            const int row = (j * 4) / C_;
            const float* src;
            if (row < 64)        src = Wk;
            else if (row < 128)  src = Wv - 64 * C_;
            else                 src = Wq - 128 * C_;
            v = ((const float4*)src)[j];
            dst = &g_Wb[(size_t)j * 4];
        }
        __nv_bfloat162 p0 = __floats2bfloat162_rn(v.x, v.y);
        __nv_bfloat162 p1 = __floats2bfloat162_rn(v.z, v.w);
        ((__nv_bfloat162*)dst)[0] = p0;
        ((__nv_bfloat162*)dst)[1] = p1;
    }
}

// =======================================================================
// Kernel 1: projection GEMM (bf16 HMMA + ldmatrix), ring-3, 1 barrier/iter.
// Outputs: K,V bf16 ; Qt e4m3 (transposed).
// =======================================================================
#define PITCH 72
#define PAB (128 * PITCH * 2)
#define PBB (64  * PITCH * 2)
#define PJ_A 0
#define PJ_B (PJ_A + 3 * PAB)
#define PJ_SMEM_BYTES (PJ_B + 3 * PBB)   // 82944
__global__ __launch_bounds__(256, 2) void proj_hmma(
    const float* __restrict__ bk, const float* __restrict__ bv,
    const float* __restrict__ bq)
{
    extern __shared__ char smc[];
    float* sT = (float*)smc;

    const uint32_t smu = smem_u32(smc);
    const uint32_t sAu = smu + PJ_A, sBu = smu + PJ_B;

    const int tid = threadIdx.x;
    const int wid = tid >> 5, lane = tid & 31;
    const int g = lane >> 2, t = lane & 3;
    const int wlo = wid & 3;
    const int whi = wid >> 2;
    const int lrow = lane & 15;
    const int lcol = (lane >> 4) << 3;

    const int ot = blockIdx.x;
    const int row0 = blockIdx.y * 128;
    const int wrow0 = ot * 64;

    const float* bias;
    if (ot == 0)      bias = bk;
    else if (ot == 1) bias = bv;
    else              bias = bq + (ot - 2) * 64;

    #pragma unroll
    for (int pf = 0; pf < 2; pf++) {
        const int kc = pf * 64;
        const uint32_t ab = sAu + pf * PAB, bb = sBu + pf * PBB;
        #pragma unroll
        for (int l = 0; l < 4; l++) {
            int idx = tid + l * 256;
            int r = idx >> 3, ch = idx & 7;
            cp16(ab + r * 144 + ch * 16, &g_xb[(size_t)(row0 + r) * C_ + kc + ch * 8]);
        }
        #pragma unroll
        for (int l = 0; l < 2; l++) {
            int idx = tid + l * 256;
            int r = idx >> 3, ch = idx & 7;
            cp16(bb + r * 144 + ch * 16, &g_Wb[(size_t)(wrow0 + r) * C_ + kc + ch * 8]);
        }
        CP_COMMIT();
    }

    float acc[8][4];
    #pragma unroll
    for (int i = 0; i < 8; i++)
        #pragma unroll
        for (int j = 0; j < 4; j++) acc[i][j] = 0.f;

    uint32_t sl0 = 0, sl1 = 1, sl2 = 2;
    for (int it = 0; it < 8; it++) {
        CP_WAIT1();
        __syncthreads();

        if (it + 2 < 8) {
            const int kc = (it + 2) * 64;
            const uint32_t ab = sAu + sl2 * PAB, bb = sBu + sl2 * PBB;
            #pragma unroll
            for (int l = 0; l < 4; l++) {
                int idx = tid + l * 256;
                int r = idx >> 3, ch = idx & 7;
                cp16(ab + r * 144 + ch * 16, &g_xb[(size_t)(row0 + r) * C_ + kc + ch * 8]);
            }
            #pragma unroll
            for (int l = 0; l < 2; l++) {
                int idx = tid + l * 256;
                int r = idx >> 3, ch = idx & 7;
                cp16(bb + r * 144 + ch * 16, &g_Wb[(size_t)(wrow0 + r) * C_ + kc + ch * 8]);
            }
        }
        CP_COMMIT();

        const uint32_t Ab = sAu + sl0 * PAB;
        const uint32_t Bb = sBu + sl0 * PBB;

        #pragma unroll
        for (int kk = 0; kk < 64; kk += 16) {
            uint32_t a0[4], a1[4], b0[4], b1[4];
            ldm4(a0, Ab + ((32 * wlo + lrow) * PITCH + kk + lcol) * 2);
            ldm4(a1, Ab + ((32 * wlo + 16 + lrow) * PITCH + kk + lcol) * 2);
            ldm4(b0, Bb + ((32 * whi + lrow) * PITCH + kk + lcol) * 2);
            ldm4(b1, Bb + ((32 * whi + 16 + lrow) * PITCH + kk + lcol) * 2);
            mma16(acc[0], a0, b0[0], b0[2]);
            mma16(acc[1], a0, b0[1], b0[3]);
            mma16(acc[2], a0, b1[0], b1[2]);
            mma16(acc[3], a0, b1[1], b1[3]);
            mma16(acc[4], a1, b0[0], b0[2]);
            mma16(acc[5], a1, b0[1], b0[3]);
            mma16(acc[6], a1, b1[0], b1[2]);
            mma16(acc[7], a1, b1[1], b1[3]);
        }

        uint32_t tmp = sl0; sl0 = sl1; sl1 = sl2; sl2 = tmp;
    }

    CP_WAIT0();
    __syncthreads();  // sT aliases A buffers

    #pragma unroll
    for (int jf = 0; jf < 4; jf++) {
        const int oc = 32 * whi + 8 * jf + 2 * t;
        const float b0v = __ldg(&bias[oc]);
        const float b1v = __ldg(&bias[oc + 1]);
        #pragma unroll
        for (int fi = 0; fi < 2; fi++) {
            const int r = 32 * wlo + 16 * fi + g;
            const float* d = acc[4 * fi + jf];
            float v00 = d[0] + b0v;
            float v01 = d[1] + b1v;
            float v10 = d[2] + b0v;
            float v11 = d[3] + b1v;
            if (ot == 0) {
                g_K[(size_t)(row0 + r) * CR_ + oc]         = __float2bfloat16_rn(v00);
                g_K[(size_t)(row0 + r) * CR_ + oc + 1]     = __float2bfloat16_rn(v01);
                g_K[(size_t)(row0 + r + 8) * CR_ + oc]     = __float2bfloat16_rn(v10);
                g_K[(size_t)(row0 + r + 8) * CR_ + oc + 1] = __float2bfloat16_rn(v11);
            } else if (ot == 1) {
                g_V[(size_t)(row0 + r) * CR_ + oc]         = __float2bfloat16_rn(v00);
                g_V[(size_t)(row0 + r) * CR_ + oc + 1]     = __float2bfloat16_rn(v01);
                g_V[(size_t)(row0 + r + 8) * CR_ + oc]     = __float2bfloat16_rn(v10);
                g_V[(size_t)(row0 + r + 8) * CR_ + oc + 1] = __float2bfloat16_rn(v11);
            } else {
                sT[oc * 132 + r]           = v00;
                sT[(oc + 1) * 132 + r]     = v01;
                sT[oc * 132 + r + 8]       = v10;
                sT[(oc + 1) * 132 + r + 8] = v11;
            }
        }
    }

    if (ot >= 2) {
        __syncthreads();
        const int b  = row0 >> 11;
        const int n0 = row0 & (N_ - 1);
        const size_t qrow0 = (size_t)b * C_ + (ot - 2) * 64;
        #pragma unroll
        for (int l = 0; l < 8; l++) {
            int idx = tid + l * 256;
            int o = idx >> 5, r4 = (idx & 31) << 2;
            float4 v = *(const float4*)&sT[o * 132 + r4];
            uchar4 u;
            u.x = f2e4m3(v.x); u.y = f2e4m3(v.y);
            u.z = f2e4m3(v.z); u.w = f2e4m3(v.w);
            *(uchar4*)&g_Q8[(qrow0 + o) * N_ + n0 + r4] = u;
        }
    }
}

// =======================================================================
// Kernel 2: S = K@V^T (bf16), P = exp(S) -> e4m3, partial den.
// K ring-3, sPT8 x2, copy-out pipelined one iter behind.
// =======================================================================
#define KVB   (64 * PITCH * 2)   // 9216 B
#define P8B   (64 * 80)          // 5120 B: 64 m-rows x 64 fp8 (pitch 80)
#define PX_SV  0
#define PX_SK  (PX_SV + KVB)            // 3 K slots
#define PX_SPT (PX_SK + 3 * KVB)        // 2 sPT8 buffers
#define PX_DEN (PX_SPT + 2 * P8B)
#define PX_SMEM_BYTES (PX_DEN + 256)
__global__ __launch_bounds__(256, 2) void pexp_kernel()
{
    extern __shared__ char smc[];
    float* sDen = (float*)(smc + PX_DEN);

    const uint32_t smu = smem_u32(smc);
    const uint32_t sVu = smu + PX_SV;
    const uint32_t sKu = smu + PX_SK;

    const int tid = threadIdx.x;
    const int wid = tid >> 5, lane = tid & 31;
    const int g = lane >> 2, t = lane & 3;
    const int wlo = wid & 3;
    const int whi = wid >> 2;
    const int lrow = lane & 15;
    const int lcol = (lane >> 4) << 3;

    const int mt = blockIdx.x, nr = blockIdx.y, b = blockIdx.z;
    const int m0 = mt * 64;
    const size_t rb = (size_t)b * N_;
    const size_t pbase = (size_t)b * N_ * N_;

    if (tid < 64) sDen[tid] = 0.f;

    #pragma unroll
    for (int l = 0; l < 2; l++) {
        int idx = tid + l * 256;
        int r = idx >> 3, ch = idx & 7;
        cp16(sVu + r * 144 + ch * 16, &g_V[(rb + m0 + r) * CR_ + ch * 8]);
        cp16(sKu + r * 144 + ch * 16, &g_K[(rb + nr * 512 + r) * CR_ + ch * 8]);
    }
    CP_COMMIT();
    #pragma unroll
    for (int l = 0; l < 2; l++) {
        int idx = tid + l * 256;
        int r = idx >> 3, ch = idx & 7;
        cp16(sKu + KVB + r * 144 + ch * 16, &g_K[(rb + nr * 512 + 64 + r) * CR_ + ch * 8]);
    }
    CP_COMMIT();

    float den[8];
    #pragma unroll
    for (int i = 0; i < 8; i++) den[i] = 0.f;

    uint32_t k0 = 0, k1 = 1, k2 = 2;
    for (int i = 0; i < 8; i++) {
        CP_WAIT1();
        __syncthreads();

        // copy-out sPT8 from iter i-1
        if (i > 0) {
            const unsigned char* spOld =
                (const unsigned char*)(smc + PX_SPT + ((i - 1) & 1) * P8B);
            const int nOld = nr * 512 + (i - 1) * 64;
            int r = tid >> 2, ch = tid & 3;
            float4 v = *(const float4*)(spOld + r * 80 + ch * 16);
            *(float4*)&g_P8[pbase + (size_t)(m0 + r) * N_ + nOld + ch * 16] = v;
        }

        if (i + 2 < 8) {
            const int nn = nr * 512 + (i + 2) * 64;
            const uint32_t kb = sKu + k2 * KVB;
            #pragma unroll
            for (int l = 0; l < 2; l++) {
                int idx = tid + l * 256;
                int r = idx >> 3, ch = idx & 7;
                cp16(kb + r * 144 + ch * 16, &g_K[(rb + nn + r) * CR_ + ch * 8]);
            }
        }
        CP_COMMIT();

        const uint32_t Kb = sKu + k0 * KVB;

        float sacc[4][4];
        #pragma unroll
        for (int ii = 0; ii < 4; ii++)
            #pragma unroll
            for (int j = 0; j < 4; j++) sacc[ii][j] = 0.f;

        #pragma unroll
        for (int kk = 0; kk < 64; kk += 16) {
            uint32_t a[4], bv0[4], bv1[4];
            ldm4(a,   Kb  + ((16 * wlo + lrow) * PITCH + kk + lcol) * 2);
            ldm4(bv0, sVu + ((32 * whi + lrow) * PITCH + kk + lcol) * 2);
            ldm4(bv1, sVu + ((32 * whi + 16 + lrow) * PITCH + kk + lcol) * 2);
            mma16(sacc[0], a, bv0[0], bv0[2]);
            mma16(sacc[1], a, bv0[1], bv0[3]);
            mma16(sacc[2], a, bv1[0], bv1[2]);
            mma16(sacc[3], a, bv1[1], bv1[3]);
        }

        // exp -> sPT8[i&1] (e4m3)
        unsigned char* sPT8 = (unsigned char*)(smc + PX_SPT + (i & 1) * P8B);
        const int nloc = 16 * wlo + g;
        #pragma unroll
        for (int jf = 0; jf < 4; jf++) {
            const int mc = 32 * whi + 8 * jf + 2 * t;
            float e00 = __expf(sacc[jf][0]);
            float e01 = __expf(sacc[jf][1]);
            float e10 = __expf(sacc[jf][2]);
            float e11 = __expf(sacc[jf][3]);
            den[2 * jf]     += e00 + e10;
            den[2 * jf + 1] += e01 + e11;
            sPT8[mc * 80 + nloc]           = f2e4m3(e00);
            sPT8[(mc + 1) * 80 + nloc]     = f2e4m3(e01);
            sPT8[mc * 80 + nloc + 8]       = f2e4m3(e10);
            sPT8[(mc + 1) * 80 + nloc + 8] = f2e4m3(e11);
        }

        uint32_t tmp = k0; k0 = k1; k1 = k2; k2 = tmp;
    }

    __syncthreads();
    {   // final copy-out (i = 7, buffer 1)
        const unsigned char* spOld = (const unsigned char*)(smc + PX_SPT + P8B);
        const int nOld = nr * 512 + 7 * 64;
        int r = tid >> 2, ch = tid & 3;
        float4 v = *(const float4*)(spOld + r * 80 + ch * 16);
        *(float4*)&g_P8[pbase + (size_t)(m0 + r) * N_ + nOld + ch * 16] = v;
    }

    #pragma unroll
    for (int jf = 0; jf < 4; jf++) {
        const int mc = 32 * whi + 8 * jf + 2 * t;
        atomicAdd(&sDen[mc],     den[2 * jf]);
        atomicAdd(&sDen[mc + 1], den[2 * jf + 1]);
    }
    __syncthreads();
    if (tid < 64)
        g_denp[(size_t)(b * 4 + nr) * N_ + m0 + tid] = sDen[tid];
}

// =======================================================================
// Kernel 3: attn2 — fp8 e4m3 GEMM: Acc[c 128][m 128] = Qt @ P^T.
// grid (16 m-tiles, 4 c-tiles, 8 b), ring-3, 1 barrier/iter.
// k-chunk 64 n (2 x k32 mma steps). Pitch 80 B.
// =======================================================================
#define P8PITCH 80
#define TB8 (128 * P8PITCH)       // 10240 B per 128-row x 64-n fp8 tile
#define A2_P  0
#define A2_Q  (A2_P + 3 * TB8)
#define A2_SMEM_BYTES (A2_Q + 3 * TB8)   // 61440
#define NT2 32
__global__ __launch_bounds__(256, 2) void attn2_kernel(
    const float* __restrict__ x, const float* __restrict__ gamma_p,
    float* __restrict__ out)
{
    extern __shared__ char smc[];
    const uint32_t smu = smem_u32(smc);
    const uint32_t sPu = smu + A2_P;
    const uint32_t sQu = smu + A2_Q;

    const int tid = threadIdx.x;
    const int wid = tid >> 5, lane = tid & 31;
    const int g = lane >> 2, t = lane & 3;
    const int wlo = wid & 3;        // c group (32): 4 x 32 = 128c
    const int whi = wid >> 2;       // m group (64): 2 x 64 = 128m

    // fp8 A-fragment addressing (16 rows x 32B per ldm.x4)
    const int arow = lane & 15;
    const int acol = (lane >> 4) << 4;              // 0 or 16 bytes
    // fp8 B-fragment addressing (16 n-rows x 32B per ldm.x4, halves interleaved)
    const int brow = (lane & 7) | ((lane >> 4) << 3);
    const int bcol = ((lane >> 3) & 1) << 4;        // 0 or 16 bytes

    const int mt = blockIdx.x, ct = blockIdx.y, b = blockIdx.z;
    const int m0 = mt * 128, c0 = ct * 128;
    const size_t rb = (size_t)b * N_;
    const size_t qbase = ((size_t)b * C_ + c0) * N_;
    const size_t pbase = (size_t)b * N_ * N_ + (size_t)m0 * N_;

    // prologue: stages 0,1  (128 rows x 4 16B-chunks each tile)
    #pragma unroll
    for (int s = 0; s < 2; s++) {
        const int n0 = s * 64;
        const uint32_t pb = sPu + s * TB8;
        const uint32_t qb = sQu + s * TB8;
        #pragma unroll
        for (int l = 0; l < 2; l++) {
            int idx = tid + l * 256;
            int r = idx >> 2, ch = idx & 3;
            cp16(pb + r * P8PITCH + ch * 16, &g_P8[pbase + (size_t)r * N_ + n0 + ch * 16]);
            cp16(qb + r * P8PITCH + ch * 16, &g_Q8[qbase + (size_t)r * N_ + n0 + ch * 16]);
        }
        CP_COMMIT();
    }

    float acc[16][4];   // [fi*8 + mj*2 + h]
    #pragma unroll
    for (int i = 0; i < 16; i++)
        #pragma unroll
        for (int j = 0; j < 4; j++) acc[i][j] = 0.f;

    uint32_t sl0 = 0, sl1 = 1, sl2 = 2;
    for (int nt = 0; nt < NT2; nt++) {
        CP_WAIT1();
        __syncthreads();

        if (nt + 2 < NT2) {
            const int n1 = (nt + 2) * 64;
            const uint32_t pb = sPu + sl2 * TB8;
            const uint32_t qb = sQu + sl2 * TB8;
            #pragma unroll
            for (int l = 0; l < 2; l++) {
                int idx = tid + l * 256;
                int r = idx >> 2, ch = idx & 3;
                cp16(pb + r * P8PITCH + ch * 16, &g_P8[pbase + (size_t)r * N_ + n1 + ch * 16]);
                cp16(qb + r * P8PITCH + ch * 16, &g_Q8[qbase + (size_t)r * N_ + n1 + ch * 16]);
            }
        }
        CP_COMMIT();

        const uint32_t Pb = sPu + sl0 * TB8;
        const uint32_t Qb = sQu + sl0 * TB8;

        #pragma unroll
        for (int kk = 0; kk < 64; kk += 32) {   // 2 k32 steps per stage
            uint32_t a0[4], a1[4], p0[4], p1[4], p2[4], p3[4];
            ldm4(a0, Qb + (32 * wlo + arow) * P8PITCH + kk + acol);
            ldm4(a1, Qb + (32 * wlo + 16 + arow) * P8PITCH + kk + acol);
            ldm4(p0, Pb + (64 * whi + brow) * P8PITCH + kk + bcol);
            ldm4(p1, Pb + (64 * whi + 16 + brow) * P8PITCH + kk + bcol);
            ldm4(p2, Pb + (64 * whi + 32 + brow) * P8PITCH + kk + bcol);
            ldm4(p3, Pb + (64 * whi + 48 + brow) * P8PITCH + kk + bcol);
            mma32(acc[0],  a0, p0[0], p0[1]);
            mma32(acc[1],  a0, p0[2], p0[3]);
            mma32(acc[2],  a0, p1[0], p1[1]);
            mma32(acc[3],  a0, p1[2], p1[3]);
            mma32(acc[4],  a0, p2[0], p2[1]);
            mma32(acc[5],  a0, p2[2], p2[3]);
            mma32(acc[6],  a0, p3[0], p3[1]);
            mma32(acc[7],  a0, p3[2], p3[3]);
            mma32(acc[8],  a1, p0[0], p0[1]);
            mma32(acc[9],  a1, p0[2], p0[3]);
            mma32(acc[10], a1, p1[0], p1[1]);
            mma32(acc[11], a1, p1[2], p1[3]);
            mma32(acc[12], a1, p2[0], p2[1]);
            mma32(acc[13], a1, p2[2], p2[3]);
            mma32(acc[14], a1, p3[0], p3[1]);
            mma32(acc[15], a1, p3[2], p3[3]);
        }

        uint32_t tmp = sl0; sl0 = sl1; sl1 = sl2; sl2 = tmp;
    }

    // ---- epilogue: out = gamma*Acc/den + x ----
    const float gam = gamma_p[0];
    #pragma unroll
    for (int mj = 0; mj < 4; mj++) {
        #pragma unroll
        for (int h = 0; h < 2; h++) {
            const int mc = 64 * whi + 16 * mj + 8 * h + 2 * t;
            float d0 = 0.f, d1 = 0.f;
            #pragma unroll
            for (int nr = 0; nr < 4; nr++) {
                d0 += __ldg(&g_denp[(size_t)(b * 4 + nr) * N_ + m0 + mc]);
                d1 += __ldg(&g_denp[(size_t)(b * 4 + nr) * N_ + m0 + mc + 1]);
            }
            const float di0 = gam / d0;
            const float di1 = gam / d1;
            #pragma unroll
            for (int fi = 0; fi < 2; fi++) {
                const int cc = c0 + 32 * wlo + 16 * fi + g;
                const size_t r0a = (rb + m0 + mc) * C_ + cc;
                const size_t r1a = (rb + m0 + mc + 1) * C_ + cc;
                const float* d = acc[fi * 8 + mj * 2 + h];
                out[r0a]     = d[0] * di0 + __ldg(&x[r0a]);
                out[r1a]     = d[1] * di1 + __ldg(&x[r1a]);
                out[r0a + 8] = d[2] * di0 + __ldg(&x[r0a + 8]);
                out[r1a + 8] = d[3] * di1 + __ldg(&x[r1a + 8]);
            }
        }
    }
}

// =======================================================================
extern "C" void kernel_launch(void* const* d_in, const int* in_sizes, int n_in,
                              void* d_out, int out_size)
{
    const float* x     = (const float*)d_in[0];
    const float* Wk    = (const float*)d_in[1];
    const float* bk    = (const float*)d_in[2];
    const float* Wv    = (const float*)d_in[3];
    const float* bv    = (const float*)d_in[4];
    const float* Wq    = (const float*)d_in[5];
    const float* bq    = (const float*)d_in[6];
    const float* gamma = (const float*)d_in[7];
    float* out = (float*)d_out;

    cudaFuncSetAttribute(proj_hmma,    cudaFuncAttributeMaxDynamicSharedMemorySize, PJ_SMEM_BYTES);
    cudaFuncSetAttribute(pexp_kernel,  cudaFuncAttributeMaxDynamicSharedMemorySize, PX_SMEM_BYTES);
    cudaFuncSetAttribute(attn2_kernel, cudaFuncAttributeMaxDynamicSharedMemorySize, A2_SMEM_BYTES);

    cvt_kernel<<<1184, 256>>>(x, Wk, Wv, Wq);
    proj_hmma<<<dim3(10, 128), 256, PJ_SMEM_BYTES>>>(bk, bv, bq);
    pexp_kernel<<<dim3(32, 4, B_), 256, PX_SMEM_BYTES>>>();
    attn2_kernel<<<dim3(16, 4, B_), 256, A2_SMEM_BYTES>>>(x, gamma, out);
}

// round 12
// speedup vs baseline: 7.4046x; 1.0713x over previous
#include <cuda_runtime.h>
#include <cuda_bf16.h>
#include <cuda_fp8.h>
#include <cstdint>

#define B_  8
#define N_  2048
#define C_  512
#define CR_ 64

// Device-global scratch (no allocs allowed).
__device__ __nv_bfloat16 g_xb[(size_t)B_ * N_ * C_];    // x in bf16
__device__ __nv_bfloat16 g_Wb[(size_t)640 * C_];        // [Wk;Wv;Wq] bf16
__device__ __nv_bfloat16 g_K [(size_t)B_ * N_ * CR_];   // [b*N+n][64]
__device__ __nv_bfloat16 g_V [(size_t)B_ * N_ * CR_];   // [b*N+m][64]
__device__ unsigned char g_Q8[(size_t)B_ * C_ * N_];    // Qt e4m3: [b*C+c][n]
__device__ unsigned char g_P8[(size_t)B_ * N_ * N_];    // P^T e4m3: [b][m][n]
__device__ float         g_denp[(size_t)B_ * 4 * N_];   // partial den

__device__ __forceinline__ uint32_t smem_u32(const void* p) {
    uint32_t a;
    asm("{ .reg .u64 t; cvta.to.shared.u64 t, %1; cvt.u32.u64 %0, t; }" : "=r"(a) : "l"(p));
    return a;
}
__device__ __forceinline__ void cp16(uint32_t dst, const void* src) {
    asm volatile("cp.async.cg.shared.global [%0], [%1], 16;" :: "r"(dst), "l"(src));
}
#define CP_COMMIT() asm volatile("cp.async.commit_group;" ::: "memory")
#define CP_WAIT0()  asm volatile("cp.async.wait_group 0;"  ::: "memory")
#define CP_WAIT1()  asm volatile("cp.async.wait_group 1;"  ::: "memory")

__device__ __forceinline__ unsigned char f2e4m3(float f) {
    return (unsigned char)__nv_cvt_float_to_fp8(f, __NV_SATFINITE, __NV_E4M3);
}

// bf16 warp mma: D(16x8) += A(16x16)*B(16x8)
__device__ __forceinline__ void mma16(float d[4], const uint32_t a[4], uint32_t b0, uint32_t b1) {
    asm volatile(
        "mma.sync.aligned.m16n8k16.row.col.f32.bf16.bf16.f32 "
        "{%0,%1,%2,%3}, {%4,%5,%6,%7}, {%8,%9}, {%0,%1,%2,%3};"
        : "+f"(d[0]), "+f"(d[1]), "+f"(d[2]), "+f"(d[3])
        : "r"(a[0]), "r"(a[1]), "r"(a[2]), "r"(a[3]), "r"(b0), "r"(b1));
}
// fp8 warp mma: D(16x8) += A(16x32)*B(32x8), e4m3
__device__ __forceinline__ void mma32(float d[4], const uint32_t a[4], uint32_t b0, uint32_t b1) {
    asm volatile(
        "mma.sync.aligned.m16n8k32.row.col.f32.e4m3.e4m3.f32 "
        "{%0,%1,%2,%3}, {%4,%5,%6,%7}, {%8,%9}, {%0,%1,%2,%3};"
        : "+f"(d[0]), "+f"(d[1]), "+f"(d[2]), "+f"(d[3])
        : "r"(a[0]), "r"(a[1]), "r"(a[2]), "r"(a[3]), "r"(b0), "r"(b1));
}
__device__ __forceinline__ void ldm4(uint32_t r[4], uint32_t addr) {
    asm volatile("ldmatrix.sync.aligned.m8n8.x4.shared.b16 {%0,%1,%2,%3}, [%4];"
        : "=r"(r[0]), "=r"(r[1]), "=r"(r[2]), "=r"(r[3]) : "r"(addr));
}

// =======================================================================
// Kernel 0: fp32 -> bf16 conversion of x and [Wk;Wv;Wq].
// =======================================================================
__global__ __launch_bounds__(256) void cvt_kernel(
    const float* __restrict__ x,
    const float* __restrict__ Wk, const float* __restrict__ Wv,
    const float* __restrict__ Wq)
{
    const int NX = (B_ * N_ * C_) / 4;
    const int NW = (640 * C_) / 4;
    for (int i = blockIdx.x * blockDim.x + threadIdx.x; i < NX + NW;
         i += gridDim.x * blockDim.x) {
        float4 v;
        __nv_bfloat16* dst;
        if (i < NX) {
            v = ((const float4*)x)[i];
            dst = &g_xb[(size_t)i * 4];
        } else {
            int j = i - NX;
            const int row = (j * 4) / C_;
            const float* src;
            if (row < 64)        src = Wk;
            else if (row < 128)  src = Wv - 64 * C_;
            else                 src = Wq - 128 * C_;
            v = ((const float4*)src)[j];
            dst = &g_Wb[(size_t)j * 4];
        }
        __nv_bfloat162 p0 = __floats2bfloat162_rn(v.x, v.y);
        __nv_bfloat162 p1 = __floats2bfloat162_rn(v.z, v.w);
        ((__nv_bfloat162*)dst)[0] = p0;
        ((__nv_bfloat162*)dst)[1] = p1;
    }
}

// =======================================================================
// Kernel 1: projection GEMM (bf16 HMMA + ldmatrix), ring-3, 1 barrier/iter.
// Outputs: K,V bf16 ; Qt e4m3 (transposed).
// =======================================================================
#define PITCH 72
#define PAB (128 * PITCH * 2)
#define PBB (64  * PITCH * 2)
#define PJ_A 0
#define PJ_B (PJ_A + 3 * PAB)
#define PJ_SMEM_BYTES (PJ_B + 3 * PBB)   // 82944
__global__ __launch_bounds__(256, 2) void proj_hmma(
    const float* __restrict__ bk, const float* __restrict__ bv,
    const float* __restrict__ bq)
{
    extern __shared__ char smc[];
    float* sT = (float*)smc;

    const uint32_t smu = smem_u32(smc);
    const uint32_t sAu = smu + PJ_A, sBu = smu + PJ_B;

    const int tid = threadIdx.x;
    const int wid = tid >> 5, lane = tid & 31;
    const int g = lane >> 2, t = lane & 3;
    const int wlo = wid & 3;
    const int whi = wid >> 2;
    const int lrow = lane & 15;
    const int lcol = (lane >> 4) << 3;

    const int ot = blockIdx.x;
    const int row0 = blockIdx.y * 128;
    const int wrow0 = ot * 64;

    const float* bias;
    if (ot == 0)      bias = bk;
    else if (ot == 1) bias = bv;
    else              bias = bq + (ot - 2) * 64;

    #pragma unroll
    for (int pf = 0; pf < 2; pf++) {
        const int kc = pf * 64;
        const uint32_t ab = sAu + pf * PAB, bb = sBu + pf * PBB;
        #pragma unroll
        for (int l = 0; l < 4; l++) {
            int idx = tid + l * 256;
            int r = idx >> 3, ch = idx & 7;
            cp16(ab + r * 144 + ch * 16, &g_xb[(size_t)(row0 + r) * C_ + kc + ch * 8]);
        }
        #pragma unroll
        for (int l = 0; l < 2; l++) {
            int idx = tid + l * 256;
            int r = idx >> 3, ch = idx & 7;
            cp16(bb + r * 144 + ch * 16, &g_Wb[(size_t)(wrow0 + r) * C_ + kc + ch * 8]);
        }
        CP_COMMIT();
    }

    float acc[8][4];
    #pragma unroll
    for (int i = 0; i < 8; i++)
        #pragma unroll
        for (int j = 0; j < 4; j++) acc[i][j] = 0.f;

    uint32_t sl0 = 0, sl1 = 1, sl2 = 2;
    for (int it = 0; it < 8; it++) {
        CP_WAIT1();
        __syncthreads();

        if (it + 2 < 8) {
            const int kc = (it + 2) * 64;
            const uint32_t ab = sAu + sl2 * PAB, bb = sBu + sl2 * PBB;
            #pragma unroll
            for (int l = 0; l < 4; l++) {
                int idx = tid + l * 256;
                int r = idx >> 3, ch = idx & 7;
                cp16(ab + r * 144 + ch * 16, &g_xb[(size_t)(row0 + r) * C_ + kc + ch * 8]);
            }
            #pragma unroll
            for (int l = 0; l < 2; l++) {
                int idx = tid + l * 256;
                int r = idx >> 3, ch = idx & 7;
                cp16(bb + r * 144 + ch * 16, &g_Wb[(size_t)(wrow0 + r) * C_ + kc + ch * 8]);
            }
        }
        CP_COMMIT();

        const uint32_t Ab = sAu + sl0 * PAB;
        const uint32_t Bb = sBu + sl0 * PBB;

        #pragma unroll
        for (int kk = 0; kk < 64; kk += 16) {
            uint32_t a0[4], a1[4], b0[4], b1[4];
            ldm4(a0, Ab + ((32 * wlo + lrow) * PITCH + kk + lcol) * 2);
            ldm4(a1, Ab + ((32 * wlo + 16 + lrow) * PITCH + kk + lcol) * 2);
            ldm4(b0, Bb + ((32 * whi + lrow) * PITCH + kk + lcol) * 2);
            ldm4(b1, Bb + ((32 * whi + 16 + lrow) * PITCH + kk + lcol) * 2);
            mma16(acc[0], a0, b0[0], b0[2]);
            mma16(acc[1], a0, b0[1], b0[3]);
            mma16(acc[2], a0, b1[0], b1[2]);
            mma16(acc[3], a0, b1[1], b1[3]);
            mma16(acc[4], a1, b0[0], b0[2]);
            mma16(acc[5], a1, b0[1], b0[3]);
            mma16(acc[6], a1, b1[0], b1[2]);
            mma16(acc[7], a1, b1[1], b1[3]);
        }

        uint32_t tmp = sl0; sl0 = sl1; sl1 = sl2; sl2 = tmp;
    }

    CP_WAIT0();
    __syncthreads();  // sT aliases A buffers

    #pragma unroll
    for (int jf = 0; jf < 4; jf++) {
        const int oc = 32 * whi + 8 * jf + 2 * t;
        const float b0v = __ldg(&bias[oc]);
        const float b1v = __ldg(&bias[oc + 1]);
        #pragma unroll
        for (int fi = 0; fi < 2; fi++) {
            const int r = 32 * wlo + 16 * fi + g;
            const float* d = acc[4 * fi + jf];
            float v00 = d[0] + b0v;
            float v01 = d[1] + b1v;
            float v10 = d[2] + b0v;
            float v11 = d[3] + b1v;
            if (ot == 0) {
                g_K[(size_t)(row0 + r) * CR_ + oc]         = __float2bfloat16_rn(v00);
                g_K[(size_t)(row0 + r) * CR_ + oc + 1]     = __float2bfloat16_rn(v01);
                g_K[(size_t)(row0 + r + 8) * CR_ + oc]     = __float2bfloat16_rn(v10);
                g_K[(size_t)(row0 + r + 8) * CR_ + oc + 1] = __float2bfloat16_rn(v11);
            } else if (ot == 1) {
                g_V[(size_t)(row0 + r) * CR_ + oc]         = __float2bfloat16_rn(v00);
                g_V[(size_t)(row0 + r) * CR_ + oc + 1]     = __float2bfloat16_rn(v01);
                g_V[(size_t)(row0 + r + 8) * CR_ + oc]     = __float2bfloat16_rn(v10);
                g_V[(size_t)(row0 + r + 8) * CR_ + oc + 1] = __float2bfloat16_rn(v11);
            } else {
                sT[oc * 132 + r]           = v00;
                sT[(oc + 1) * 132 + r]     = v01;
                sT[oc * 132 + r + 8]       = v10;
                sT[(oc + 1) * 132 + r + 8] = v11;
            }
        }
    }

    if (ot >= 2) {
        __syncthreads();
        const int b  = row0 >> 11;
        const int n0 = row0 & (N_ - 1);
        const size_t qrow0 = (size_t)b * C_ + (ot - 2) * 64;
        #pragma unroll
        for (int l = 0; l < 8; l++) {
            int idx = tid + l * 256;
            int o = idx >> 5, r4 = (idx & 31) << 2;
            float4 v = *(const float4*)&sT[o * 132 + r4];
            uchar4 u;
            u.x = f2e4m3(v.x); u.y = f2e4m3(v.y);
            u.z = f2e4m3(v.z); u.w = f2e4m3(v.w);
            *(uchar4*)&g_Q8[(qrow0 + o) * N_ + n0 + r4] = u;
        }
    }
}

// =======================================================================
// Kernel 2: S = K@V^T (bf16), P = exp(S) -> e4m3, partial den.
// K ring-3, sPT8 x2, copy-out pipelined one iter behind.
// =======================================================================
#define KVB   (64 * PITCH * 2)   // 9216 B
#define P8B   (64 * 80)          // 5120 B: 64 m-rows x 64 fp8 (pitch 80)
#define PX_SV  0
#define PX_SK  (PX_SV + KVB)            // 3 K slots
#define PX_SPT (PX_SK + 3 * KVB)        // 2 sPT8 buffers
#define PX_DEN (PX_SPT + 2 * P8B)
#define PX_SMEM_BYTES (PX_DEN + 256)
__global__ __launch_bounds__(256, 2) void pexp_kernel()
{
    extern __shared__ char smc[];
    float* sDen = (float*)(smc + PX_DEN);

    const uint32_t smu = smem_u32(smc);
    const uint32_t sVu = smu + PX_SV;
    const uint32_t sKu = smu + PX_SK;

    const int tid = threadIdx.x;
    const int wid = tid >> 5, lane = tid & 31;
    const int g = lane >> 2, t = lane & 3;
    const int wlo = wid & 3;
    const int whi = wid >> 2;
    const int lrow = lane & 15;
    const int lcol = (lane >> 4) << 3;

    const int mt = blockIdx.x, nr = blockIdx.y, b = blockIdx.z;
    const int m0 = mt * 64;
    const size_t rb = (size_t)b * N_;
    const size_t pbase = (size_t)b * N_ * N_;

    if (tid < 64) sDen[tid] = 0.f;

    #pragma unroll
    for (int l = 0; l < 2; l++) {
        int idx = tid + l * 256;
        int r = idx >> 3, ch = idx & 7;
        cp16(sVu + r * 144 + ch * 16, &g_V[(rb + m0 + r) * CR_ + ch * 8]);
        cp16(sKu + r * 144 + ch * 16, &g_K[(rb + nr * 512 + r) * CR_ + ch * 8]);
    }
    CP_COMMIT();
    #pragma unroll
    for (int l = 0; l < 2; l++) {
        int idx = tid + l * 256;
        int r = idx >> 3, ch = idx & 7;
        cp16(sKu + KVB + r * 144 + ch * 16, &g_K[(rb + nr * 512 + 64 + r) * CR_ + ch * 8]);
    }
    CP_COMMIT();

    float den[8];
    #pragma unroll
    for (int i = 0; i < 8; i++) den[i] = 0.f;

    uint32_t k0 = 0, k1 = 1, k2 = 2;
    for (int i = 0; i < 8; i++) {
        CP_WAIT1();
        __syncthreads();

        // copy-out sPT8 from iter i-1
        if (i > 0) {
            const unsigned char* spOld =
                (const unsigned char*)(smc + PX_SPT + ((i - 1) & 1) * P8B);
            const int nOld = nr * 512 + (i - 1) * 64;
            int r = tid >> 2, ch = tid & 3;
            float4 v = *(const float4*)(spOld + r * 80 + ch * 16);
            *(float4*)&g_P8[pbase + (size_t)(m0 + r) * N_ + nOld + ch * 16] = v;
        }

        if (i + 2 < 8) {
            const int nn = nr * 512 + (i + 2) * 64;
            const uint32_t kb = sKu + k2 * KVB;
            #pragma unroll
            for (int l = 0; l < 2; l++) {
                int idx = tid + l * 256;
                int r = idx >> 3, ch = idx & 7;
                cp16(kb + r * 144 + ch * 16, &g_K[(rb + nn + r) * CR_ + ch * 8]);
            }
        }
        CP_COMMIT();

        const uint32_t Kb = sKu + k0 * KVB;

        float sacc[4][4];
        #pragma unroll
        for (int ii = 0; ii < 4; ii++)
            #pragma unroll
            for (int j = 0; j < 4; j++) sacc[ii][j] = 0.f;

        #pragma unroll
        for (int kk = 0; kk < 64; kk += 16) {
            uint32_t a[4], bv0[4], bv1[4];
            ldm4(a,   Kb  + ((16 * wlo + lrow) * PITCH + kk + lcol) * 2);
            ldm4(bv0, sVu + ((32 * whi + lrow) * PITCH + kk + lcol) * 2);
            ldm4(bv1, sVu + ((32 * whi + 16 + lrow) * PITCH + kk + lcol) * 2);
            mma16(sacc[0], a, bv0[0], bv0[2]);
            mma16(sacc[1], a, bv0[1], bv0[3]);
            mma16(sacc[2], a, bv1[0], bv1[2]);
            mma16(sacc[3], a, bv1[1], bv1[3]);
        }

        // exp -> sPT8[i&1] (e4m3)
        unsigned char* sPT8 = (unsigned char*)(smc + PX_SPT + (i & 1) * P8B);
        const int nloc = 16 * wlo + g;
        #pragma unroll
        for (int jf = 0; jf < 4; jf++) {
            const int mc = 32 * whi + 8 * jf + 2 * t;
            float e00 = __expf(sacc[jf][0]);
            float e01 = __expf(sacc[jf][1]);
            float e10 = __expf(sacc[jf][2]);
            float e11 = __expf(sacc[jf][3]);
            den[2 * jf]     += e00 + e10;
            den[2 * jf + 1] += e01 + e11;
            sPT8[mc * 80 + nloc]           = f2e4m3(e00);
            sPT8[(mc + 1) * 80 + nloc]     = f2e4m3(e01);
            sPT8[mc * 80 + nloc + 8]       = f2e4m3(e10);
            sPT8[(mc + 1) * 80 + nloc + 8] = f2e4m3(e11);
        }

        uint32_t tmp = k0; k0 = k1; k1 = k2; k2 = tmp;
    }

    __syncthreads();
    {   // final copy-out (i = 7, buffer 1)
        const unsigned char* spOld = (const unsigned char*)(smc + PX_SPT + P8B);
        const int nOld = nr * 512 + 7 * 64;
        int r = tid >> 2, ch = tid & 3;
        float4 v = *(const float4*)(spOld + r * 80 + ch * 16);
        *(float4*)&g_P8[pbase + (size_t)(m0 + r) * N_ + nOld + ch * 16] = v;
    }

    #pragma unroll
    for (int jf = 0; jf < 4; jf++) {
        const int mc = 32 * whi + 8 * jf + 2 * t;
        atomicAdd(&sDen[mc],     den[2 * jf]);
        atomicAdd(&sDen[mc + 1], den[2 * jf + 1]);
    }
    __syncthreads();
    if (tid < 64)
        g_denp[(size_t)(b * 4 + nr) * N_ + m0 + tid] = sDen[tid];
}

// =======================================================================
// Kernel 3: attn2 — fp8 e4m3 GEMM: Acc[c 128][m 64] = Qt @ P^T.
// grid (32 m-tiles, 4 c-tiles, 8 b), ring-3, occupancy 3.
// Warp tile 32c x 32m; per 64-n stage: 8 ldm + 16 mma.
// =======================================================================
#define P8PITCH 80
#define PB8 (64  * P8PITCH)       //  5120 B: P tile (64 m-rows)
#define QB8 (128 * P8PITCH)       // 10240 B: Q tile (128 c-rows)
#define A2_P  0
#define A2_Q  (A2_P + 3 * PB8)
#define A2_SMEM_BYTES (A2_Q + 3 * QB8)   // 46080
#define NT2 32
__global__ __launch_bounds__(256, 3) void attn2_kernel(
    const float* __restrict__ x, const float* __restrict__ gamma_p,
    float* __restrict__ out)
{
    extern __shared__ char smc[];
    const uint32_t smu = smem_u32(smc);
    const uint32_t sPu = smu + A2_P;
    const uint32_t sQu = smu + A2_Q;

    const int tid = threadIdx.x;
    const int wid = tid >> 5, lane = tid & 31;
    const int g = lane >> 2, t = lane & 3;
    const int wlo = wid & 3;        // c group (32): 4 x 32 = 128c
    const int whi = wid >> 2;       // m group (32): 2 x 32 = 64m

    // fp8 A-fragment addressing (16 rows x 32B per ldm.x4)
    const int arow = lane & 15;
    const int acol = (lane >> 4) << 4;
    // fp8 B-fragment addressing
    const int brow = (lane & 7) | ((lane >> 4) << 3);
    const int bcol = ((lane >> 3) & 1) << 4;

    const int mt = blockIdx.x, ct = blockIdx.y, b = blockIdx.z;
    const int m0 = mt * 64, c0 = ct * 128;
    const size_t rb = (size_t)b * N_;
    const size_t qbase = ((size_t)b * C_ + c0) * N_;
    const size_t pbase = (size_t)b * N_ * N_ + (size_t)m0 * N_;

    // prologue: stages 0,1
    #pragma unroll
    for (int s = 0; s < 2; s++) {
        const int n0 = s * 64;
        const uint32_t pb = sPu + s * PB8;
        const uint32_t qb = sQu + s * QB8;
        {   // P: 64 rows x 4 chunks = 256 cp16
            int r = tid >> 2, ch = tid & 3;
            cp16(pb + r * P8PITCH + ch * 16, &g_P8[pbase + (size_t)r * N_ + n0 + ch * 16]);
        }
        #pragma unroll
        for (int l = 0; l < 2; l++) {   // Q: 128 rows x 4 chunks = 512 cp16
            int idx = tid + l * 256;
            int r = idx >> 2, ch = idx & 3;
            cp16(qb + r * P8PITCH + ch * 16, &g_Q8[qbase + (size_t)r * N_ + n0 + ch * 16]);
        }
        CP_COMMIT();
    }

    float acc[8][4];   // [fi*4 + mj]
    #pragma unroll
    for (int i = 0; i < 8; i++)
        #pragma unroll
        for (int j = 0; j < 4; j++) acc[i][j] = 0.f;

    uint32_t sl0 = 0, sl1 = 1, sl2 = 2;
    for (int nt = 0; nt < NT2; nt++) {
        CP_WAIT1();
        __syncthreads();

        if (nt + 2 < NT2) {
            const int n1 = (nt + 2) * 64;
            const uint32_t pb = sPu + sl2 * PB8;
            const uint32_t qb = sQu + sl2 * QB8;
            {
                int r = tid >> 2, ch = tid & 3;
                cp16(pb + r * P8PITCH + ch * 16, &g_P8[pbase + (size_t)r * N_ + n1 + ch * 16]);
            }
            #pragma unroll
            for (int l = 0; l < 2; l++) {
                int idx = tid + l * 256;
                int r = idx >> 2, ch = idx & 3;
                cp16(qb + r * P8PITCH + ch * 16, &g_Q8[qbase + (size_t)r * N_ + n1 + ch * 16]);
            }
        }
        CP_COMMIT();

        const uint32_t Pb = sPu + sl0 * PB8;
        const uint32_t Qb = sQu + sl0 * QB8;

        #pragma unroll
        for (int kk = 0; kk < 64; kk += 32) {   // 2 k32 steps per stage
            uint32_t a0[4], a1[4], p0[4], p1[4];
            ldm4(a0, Qb + (32 * wlo + arow) * P8PITCH + kk + acol);
            ldm4(a1, Qb + (32 * wlo + 16 + arow) * P8PITCH + kk + acol);
            ldm4(p0, Pb + (32 * whi + brow) * P8PITCH + kk + bcol);
            ldm4(p1, Pb + (32 * whi + 16 + brow) * P8PITCH + kk + bcol);
            mma32(acc[0], a0, p0[0], p0[1]);
            mma32(acc[1], a0, p0[2], p0[3]);
            mma32(acc[2], a0, p1[0], p1[1]);
            mma32(acc[3], a0, p1[2], p1[3]);
            mma32(acc[4], a1, p0[0], p0[1]);
            mma32(acc[5], a1, p0[2], p0[3]);
            mma32(acc[6], a1, p1[0], p1[1]);
            mma32(acc[7], a1, p1[2], p1[3]);
        }

        uint32_t tmp = sl0; sl0 = sl1; sl1 = sl2; sl2 = tmp;
    }

    // ---- epilogue: out = gamma*Acc/den + x ----
    const float gam = gamma_p[0];
    #pragma unroll
    for (int mj = 0; mj < 4; mj++) {
        const int mc = 32 * whi + 8 * mj + 2 * t;
        float d0 = 0.f, d1 = 0.f;
        #pragma unroll
        for (int nr = 0; nr < 4; nr++) {
            d0 += __ldg(&g_denp[(size_t)(b * 4 + nr) * N_ + m0 + mc]);
            d1 += __ldg(&g_denp[(size_t)(b * 4 + nr) * N_ + m0 + mc + 1]);
        }
        const float di0 = gam / d0;
        const float di1 = gam / d1;
        #pragma unroll
        for (int fi = 0; fi < 2; fi++) {
            const int cc = c0 + 32 * wlo + 16 * fi + g;
            const size_t r0a = (rb + m0 + mc) * C_ + cc;
            const size_t r1a = (rb + m0 + mc + 1) * C_ + cc;
            const float* d = acc[fi * 4 + mj];
            out[r0a]     = d[0] * di0 + __ldg(&x[r0a]);
            out[r1a]     = d[1] * di1 + __ldg(&x[r1a]);
            out[r0a + 8] = d[2] * di0 + __ldg(&x[r0a + 8]);
            out[r1a + 8] = d[3] * di1 + __ldg(&x[r1a + 8]);
        }
    }
}

// =======================================================================
extern "C" void kernel_launch(void* const* d_in, const int* in_sizes, int n_in,
                              void* d_out, int out_size)
{
    const float* x     = (const float*)d_in[0];
    const float* Wk    = (const float*)d_in[1];
    const float* bk    = (const float*)d_in[2];
    const float* Wv    = (const float*)d_in[3];
    const float* bv    = (const float*)d_in[4];
    const float* Wq    = (const float*)d_in[5];
    const float* bq    = (const float*)d_in[6];
    const float* gamma = (const float*)d_in[7];
    float* out = (float*)d_out;

    cudaFuncSetAttribute(proj_hmma,    cudaFuncAttributeMaxDynamicSharedMemorySize, PJ_SMEM_BYTES);
    cudaFuncSetAttribute(pexp_kernel,  cudaFuncAttributeMaxDynamicSharedMemorySize, PX_SMEM_BYTES);
    cudaFuncSetAttribute(attn2_kernel, cudaFuncAttributeMaxDynamicSharedMemorySize, A2_SMEM_BYTES);

    cvt_kernel<<<1184, 256>>>(x, Wk, Wv, Wq);
    proj_hmma<<<dim3(10, 128), 256, PJ_SMEM_BYTES>>>(bk, bv, bq);
    pexp_kernel<<<dim3(32, 4, B_), 256, PX_SMEM_BYTES>>>();
    attn2_kernel<<<dim3(32, 4, B_), 256, A2_SMEM_BYTES>>>(x, gamma, out);
}

// round 13
// speedup vs baseline: 7.4209x; 1.0022x over previous
#include <cuda_runtime.h>
#include <cuda_bf16.h>
#include <cuda_fp8.h>
#include <cstdint>

#define B_  8
#define N_  2048
#define C_  512
#define CR_ 64

// Device-global scratch (no allocs allowed).
__device__ __nv_bfloat16 g_xb[(size_t)B_ * N_ * C_];    // x in bf16
__device__ __nv_bfloat16 g_Wb[(size_t)640 * C_];        // [Wk;Wv;Wq] bf16
__device__ __nv_bfloat16 g_K [(size_t)B_ * N_ * CR_];   // [b*N+n][64]
__device__ __nv_bfloat16 g_V [(size_t)B_ * N_ * CR_];   // [b*N+m][64]
__device__ unsigned char g_Q8[(size_t)B_ * C_ * N_];    // Qt e4m3: [b*C+c][n]
__device__ unsigned char g_P8[(size_t)B_ * N_ * N_];    // P^T e4m3: [b][m][n]
__device__ float         g_denp[(size_t)B_ * 4 * N_];   // partial den

__device__ __forceinline__ uint32_t smem_u32(const void* p) {
    uint32_t a;
    asm("{ .reg .u64 t; cvta.to.shared.u64 t, %1; cvt.u32.u64 %0, t; }" : "=r"(a) : "l"(p));
    return a;
}
__device__ __forceinline__ void cp16(uint32_t dst, const void* src) {
    asm volatile("cp.async.cg.shared.global [%0], [%1], 16;" :: "r"(dst), "l"(src));
}
#define CP_COMMIT() asm volatile("cp.async.commit_group;" ::: "memory")
#define CP_WAIT0()  asm volatile("cp.async.wait_group 0;"  ::: "memory")
#define CP_WAIT1()  asm volatile("cp.async.wait_group 1;"  ::: "memory")

__device__ __forceinline__ unsigned char f2e4m3(float f) {
    return (unsigned char)__nv_cvt_float_to_fp8(f, __NV_SATFINITE, __NV_E4M3);
}

// bf16 warp mma: D(16x8) += A(16x16)*B(16x8)
__device__ __forceinline__ void mma16(float d[4], const uint32_t a[4], uint32_t b0, uint32_t b1) {
    asm volatile(
        "mma.sync.aligned.m16n8k16.row.col.f32.bf16.bf16.f32 "
        "{%0,%1,%2,%3}, {%4,%5,%6,%7}, {%8,%9}, {%0,%1,%2,%3};"
        : "+f"(d[0]), "+f"(d[1]), "+f"(d[2]), "+f"(d[3])
        : "r"(a[0]), "r"(a[1]), "r"(a[2]), "r"(a[3]), "r"(b0), "r"(b1));
}
// fp8 warp mma: D(16x8) += A(16x32)*B(32x8), e4m3
__device__ __forceinline__ void mma32(float d[4], const uint32_t a[4], uint32_t b0, uint32_t b1) {
    asm volatile(
        "mma.sync.aligned.m16n8k32.row.col.f32.e4m3.e4m3.f32 "
        "{%0,%1,%2,%3}, {%4,%5,%6,%7}, {%8,%9}, {%0,%1,%2,%3};"
        : "+f"(d[0]), "+f"(d[1]), "+f"(d[2]), "+f"(d[3])
        : "r"(a[0]), "r"(a[1]), "r"(a[2]), "r"(a[3]), "r"(b0), "r"(b1));
}
__device__ __forceinline__ void ldm4(uint32_t r[4], uint32_t addr) {
    asm volatile("ldmatrix.sync.aligned.m8n8.x4.shared.b16 {%0,%1,%2,%3}, [%4];"
        : "=r"(r[0]), "=r"(r[1]), "=r"(r[2]), "=r"(r[3]) : "r"(addr));
}

// =======================================================================
// Kernel 0: fp32 -> bf16 conversion of x and [Wk;Wv;Wq].
// =======================================================================
__global__ __launch_bounds__(256) void cvt_kernel(
    const float* __restrict__ x,
    const float* __restrict__ Wk, const float* __restrict__ Wv,
    const float* __restrict__ Wq)
{
    const int NX = (B_ * N_ * C_) / 4;
    const int NW = (640 * C_) / 4;
    for (int i = blockIdx.x * blockDim.x + threadIdx.x; i < NX + NW;
         i += gridDim.x * blockDim.x) {
        float4 v;
        __nv_bfloat16* dst;
        if (i < NX) {
            v = ((const float4*)x)[i];
            dst = &g_xb[(size_t)i * 4];
        } else {
            int j = i - NX;
            const int row = (j * 4) / C_;
            const float* src;
            if (row < 64)        src = Wk;
            else if (row < 128)  src = Wv - 64 * C_;
            else                 src = Wq - 128 * C_;
            v = ((const float4*)src)[j];
            dst = &g_Wb[(size_t)j * 4];
        }
        __nv_bfloat162 p0 = __floats2bfloat162_rn(v.x, v.y);
        __nv_bfloat162 p1 = __floats2bfloat162_rn(v.z, v.w);
        ((__nv_bfloat162*)dst)[0] = p0;
        ((__nv_bfloat162*)dst)[1] = p1;
    }
}

// =======================================================================
// Kernel 1: projection GEMM (bf16 HMMA + ldmatrix), 128x128 tiles,
// ring-3, 1 barrier/iter. grid (5 o-tiles of 128, 128 row-tiles of 128).
// ot 0 -> K(64)+V(64); ot 1..4 -> Qt e4m3 (transposed), 128 chans each.
// =======================================================================
#define PITCH 72
#define PAB (128 * PITCH * 2)   // 18432 B per 128-row tile
#define PJ_A 0
#define PJ_B (PJ_A + 3 * PAB)
#define PJ_SMEM_BYTES (PJ_B + 3 * PAB)   // 110592
__global__ __launch_bounds__(256, 2) void proj_hmma(
    const float* __restrict__ bk, const float* __restrict__ bv,
    const float* __restrict__ bq)
{
    extern __shared__ char smc[];
    float* sT = (float*)smc;   // staging [128 oc][132 r] floats (67.6 KB)

    const uint32_t smu = smem_u32(smc);
    const uint32_t sAu = smu + PJ_A, sBu = smu + PJ_B;

    const int tid = threadIdx.x;
    const int wid = tid >> 5, lane = tid & 31;
    const int g = lane >> 2, t = lane & 3;
    const int wlo = wid & 3;        // row group (32 of 128)
    const int whi = wid >> 2;       // o group (64 of 128)
    const int lrow = lane & 15;
    const int lcol = (lane >> 4) << 3;

    const int ot = blockIdx.x;      // 0..4
    const int row0 = blockIdx.y * 128;
    const int wrow0 = ot * 128;     // row offset in g_Wb

    // prologue: stages 0,1
    #pragma unroll
    for (int pf = 0; pf < 2; pf++) {
        const int kc = pf * 64;
        const uint32_t ab = sAu + pf * PAB, bb = sBu + pf * PAB;
        #pragma unroll
        for (int l = 0; l < 4; l++) {
            int idx = tid + l * 256;
            int r = idx >> 3, ch = idx & 7;
            cp16(ab + r * 144 + ch * 16, &g_xb[(size_t)(row0 + r) * C_ + kc + ch * 8]);
            cp16(bb + r * 144 + ch * 16, &g_Wb[(size_t)(wrow0 + r) * C_ + kc + ch * 8]);
        }
        CP_COMMIT();
    }

    float acc[16][4];   // [fi*8 + jf]
    #pragma unroll
    for (int i = 0; i < 16; i++)
        #pragma unroll
        for (int j = 0; j < 4; j++) acc[i][j] = 0.f;

    // hoisted ldm offsets
    const uint32_t aoff0 = ((32 * wlo + lrow) * PITCH + lcol) * 2;
    const uint32_t aoff1 = aoff0 + 16 * PITCH * 2;
    const uint32_t boff0 = ((64 * whi + lrow) * PITCH + lcol) * 2;
    const uint32_t boff1 = boff0 + 16 * PITCH * 2;
    const uint32_t boff2 = boff0 + 32 * PITCH * 2;
    const uint32_t boff3 = boff0 + 48 * PITCH * 2;

    uint32_t sl0 = 0, sl1 = 1, sl2 = 2;
    for (int it = 0; it < 8; it++) {
        CP_WAIT1();
        __syncthreads();

        if (it + 2 < 8) {
            const int kc = (it + 2) * 64;
            const uint32_t ab = sAu + sl2 * PAB, bb = sBu + sl2 * PAB;
            #pragma unroll
            for (int l = 0; l < 4; l++) {
                int idx = tid + l * 256;
                int r = idx >> 3, ch = idx & 7;
                cp16(ab + r * 144 + ch * 16, &g_xb[(size_t)(row0 + r) * C_ + kc + ch * 8]);
                cp16(bb + r * 144 + ch * 16, &g_Wb[(size_t)(wrow0 + r) * C_ + kc + ch * 8]);
            }
        }
        CP_COMMIT();

        const uint32_t Ab = sAu + sl0 * PAB;
        const uint32_t Bb = sBu + sl0 * PAB;

        #pragma unroll
        for (int kk = 0; kk < 64; kk += 16) {
            uint32_t a0[4], a1[4], b0[4], b1[4], b2[4], b3[4];
            ldm4(a0, Ab + aoff0 + kk * 2);
            ldm4(a1, Ab + aoff1 + kk * 2);
            ldm4(b0, Bb + boff0 + kk * 2);
            ldm4(b1, Bb + boff1 + kk * 2);
            ldm4(b2, Bb + boff2 + kk * 2);
            ldm4(b3, Bb + boff3 + kk * 2);
            mma16(acc[0],  a0, b0[0], b0[2]);
            mma16(acc[1],  a0, b0[1], b0[3]);
            mma16(acc[2],  a0, b1[0], b1[2]);
            mma16(acc[3],  a0, b1[1], b1[3]);
            mma16(acc[4],  a0, b2[0], b2[2]);
            mma16(acc[5],  a0, b2[1], b2[3]);
            mma16(acc[6],  a0, b3[0], b3[2]);
            mma16(acc[7],  a0, b3[1], b3[3]);
            mma16(acc[8],  a1, b0[0], b0[2]);
            mma16(acc[9],  a1, b0[1], b0[3]);
            mma16(acc[10], a1, b1[0], b1[2]);
            mma16(acc[11], a1, b1[1], b1[3]);
            mma16(acc[12], a1, b2[0], b2[2]);
            mme16_l:;
            mma16(acc[13], a1, b2[1], b2[3]);
            mma16(acc[14], a1, b3[0], b3[2]);
            mma16(acc[15], a1, b3[1], b3[3]);
        }

        uint32_t tmp = sl0; sl0 = sl1; sl1 = sl2; sl2 = tmp;
    }

    CP_WAIT0();
    __syncthreads();  // sT aliases buffers; all mma done

    #pragma unroll
    for (int jf = 0; jf < 8; jf++) {
        const int oc = 64 * whi + 8 * jf + 2 * t;
        float b0v, b1v;
        if (ot == 0) {
            if (whi == 0) { b0v = __ldg(&bk[oc]);      b1v = __ldg(&bk[oc + 1]); }
            else          { b0v = __ldg(&bv[oc - 64]); b1v = __ldg(&bv[oc - 63]); }
        } else {
            b0v = __ldg(&bq[(ot - 1) * 128 + oc]);
            b1v = __ldg(&bq[(ot - 1) * 128 + oc + 1]);
        }
        #pragma unroll
        for (int fi = 0; fi < 2; fi++) {
            const int r = 32 * wlo + 16 * fi + g;
            const float* d = acc[fi * 8 + jf];
            float v00 = d[0] + b0v;
            float v01 = d[1] + b1v;
            float v10 = d[2] + b0v;
            float v11 = d[3] + b1v;
            if (ot == 0) {
                if (whi == 0) {
                    g_K[(size_t)(row0 + r) * CR_ + oc]         = __float2bfloat16_rn(v00);
                    g_K[(size_t)(row0 + r) * CR_ + oc + 1]     = __float2bfloat16_rn(v01);
                    g_K[(size_t)(row0 + r + 8) * CR_ + oc]     = __float2bfloat16_rn(v10);
                    g_K[(size_t)(row0 + r + 8) * CR_ + oc + 1] = __float2bfloat16_rn(v11);
                } else {
                    const int vc = oc - 64;
                    g_V[(size_t)(row0 + r) * CR_ + vc]         = __float2bfloat16_rn(v00);
                    g_V[(size_t)(row0 + r) * CR_ + vc + 1]     = __float2bfloat16_rn(v01);
                    g_V[(size_t)(row0 + r + 8) * CR_ + vc]     = __float2bfloat16_rn(v10);
                    g_V[(size_t)(row0 + r + 8) * CR_ + vc + 1] = __float2bfloat16_rn(v11);
                }
            } else {
                sT[oc * 132 + r]           = v00;
                sT[(oc + 1) * 132 + r]     = v01;
                sT[oc * 132 + r + 8]       = v10;
                sT[(oc + 1) * 132 + r + 8] = v11;
            }
        }
    }

    if (ot >= 1) {
        __syncthreads();
        const int b  = row0 >> 11;
        const int n0 = row0 & (N_ - 1);
        const size_t qrow0 = (size_t)b * C_ + (ot - 1) * 128;
        #pragma unroll
        for (int l = 0; l < 16; l++) {
            int idx = tid + l * 256;            // 0..4095
            int o = idx >> 5, r4 = (idx & 31) << 2;
            float4 v = *(const float4*)&sT[o * 132 + r4];
            uchar4 u;
            u.x = f2e4m3(v.x); u.y = f2e4m3(v.y);
            u.z = f2e4m3(v.z); u.w = f2e4m3(v.w);
            *(uchar4*)&g_Q8[(qrow0 + o) * N_ + n0 + r4] = u;
        }
    }
}

// =======================================================================
// Kernel 2: S = K@V^T (bf16), P = exp(S) -> e4m3, partial den.
// K ring-3, sPT8 x2, copy-out pipelined one iter behind.
// =======================================================================
#define KVB   (64 * PITCH * 2)   // 9216 B
#define P8B   (64 * 80)          // 5120 B
#define PX_SV  0
#define PX_SK  (PX_SV + KVB)            // 3 K slots
#define PX_SPT (PX_SK + 3 * KVB)        // 2 sPT8 buffers
#define PX_DEN (PX_SPT + 2 * P8B)
#define PX_SMEM_BYTES (PX_DEN + 256)
__global__ __launch_bounds__(256, 2) void pexp_kernel()
{
    extern __shared__ char smc[];
    float* sDen = (float*)(smc + PX_DEN);

    const uint32_t smu = smem_u32(smc);
    const uint32_t sVu = smu + PX_SV;
    const uint32_t sKu = smu + PX_SK;

    const int tid = threadIdx.x;
    const int wid = tid >> 5, lane = tid & 31;
    const int g = lane >> 2, t = lane & 3;
    const int wlo = wid & 3;
    const int whi = wid >> 2;
    const int lrow = lane & 15;
    const int lcol = (lane >> 4) << 3;

    const int mt = blockIdx.x, nr = blockIdx.y, b = blockIdx.z;
    const int m0 = mt * 64;
    const size_t rb = (size_t)b * N_;
    const size_t pbase = (size_t)b * N_ * N_;

    if (tid < 64) sDen[tid] = 0.f;

    #pragma unroll
    for (int l = 0; l < 2; l++) {
        int idx = tid + l * 256;
        int r = idx >> 3, ch = idx & 7;
        cp16(sVu + r * 144 + ch * 16, &g_V[(rb + m0 + r) * CR_ + ch * 8]);
        cp16(sKu + r * 144 + ch * 16, &g_K[(rb + nr * 512 + r) * CR_ + ch * 8]);
    }
    CP_COMMIT();
    #pragma unroll
    for (int l = 0; l < 2; l++) {
        int idx = tid + l * 256;
        int r = idx >> 3, ch = idx & 7;
        cp16(sKu + KVB + r * 144 + ch * 16, &g_K[(rb + nr * 512 + 64 + r) * CR_ + ch * 8]);
    }
    CP_COMMIT();

    float den[8];
    #pragma unroll
    for (int i = 0; i < 8; i++) den[i] = 0.f;

    uint32_t k0 = 0, k1 = 1, k2 = 2;
    for (int i = 0; i < 8; i++) {
        CP_WAIT1();
        __syncthreads();

        if (i > 0) {
            const unsigned char* spOld =
                (const unsigned char*)(smc + PX_SPT + ((i - 1) & 1) * P8B);
            const int nOld = nr * 512 + (i - 1) * 64;
            int r = tid >> 2, ch = tid & 3;
            float4 v = *(const float4*)(spOld + r * 80 + ch * 16);
            *(float4*)&g_P8[pbase + (size_t)(m0 + r) * N_ + nOld + ch * 16] = v;
        }

        if (i + 2 < 8) {
            const int nn = nr * 512 + (i + 2) * 64;
            const uint32_t kb = sKu + k2 * KVB;
            #pragma unroll
            for (int l = 0; l < 2; l++) {
                int idx = tid + l * 256;
                int r = idx >> 3, ch = idx & 7;
                cp16(kb + r * 144 + ch * 16, &g_K[(rb + nn + r) * CR_ + ch * 8]);
            }
        }
        CP_COMMIT();

        const uint32_t Kb = sKu + k0 * KVB;

        float sacc[4][4];
        #pragma unroll
        for (int ii = 0; ii < 4; ii++)
            #pragma unroll
            for (int j = 0; j < 4; j++) sacc[ii][j] = 0.f;

        #pragma unroll
        for (int kk = 0; kk < 64; kk += 16) {
            uint32_t a[4], bv0[4], bv1[4];
            ldm4(a,   Kb  + ((16 * wlo + lrow) * PITCH + kk + lcol) * 2);
            ldm4(bv0, sVu + ((32 * whi + lrow) * PITCH + kk + lcol) * 2);
            ldm4(bv1, sVu + ((32 * whi + 16 + lrow) * PITCH + kk + lcol) * 2);
            mma16(sacc[0], a, bv0[0], bv0[2]);
            mma16(sacc[1], a, bv0[1], bv0[3]);
            mma16(sacc[2], a, bv1[0], bv1[2]);
            mma16(sacc[3], a, bv1[1], bv1[3]);
        }

        unsigned char* sPT8 = (unsigned char*)(smc + PX_SPT + (i & 1) * P8B);
        const int nloc = 16 * wlo + g;
        #pragma unroll
        for (int jf = 0; jf < 4; jf++) {
            const int mc = 32 * whi + 8 * jf + 2 * t;
            float e00 = __expf(sacc[jf][0]);
            float e01 = __expf(sacc[jf][1]);
            float e10 = __expf(sacc[jf][2]);
            float e11 = __expf(sacc[jf][3]);
            den[2 * jf]     += e00 + e10;
            den[2 * jf + 1] += e01 + e11;
            sPT8[mc * 80 + nloc]           = f2e4m3(e00);
            sPT8[(mc + 1) * 80 + nloc]     = f2e4m3(e01);
            sPT8[mc * 80 + nloc + 8]       = f2e4m3(e10);
            sPT8[(mc + 1) * 80 + nloc + 8] = f2e4m3(e11);
        }

        uint32_t tmp = k0; k0 = k1; k1 = k2; k2 = tmp;
    }

    __syncthreads();
    {
        const unsigned char* spOld = (const unsigned char*)(smc + PX_SPT + P8B);
        const int nOld = nr * 512 + 7 * 64;
        int r = tid >> 2, ch = tid & 3;
        float4 v = *(const float4*)(spOld + r * 80 + ch * 16);
        *(float4*)&g_P8[pbase + (size_t)(m0 + r) * N_ + nOld + ch * 16] = v;
    }

    #pragma unroll
    for (int jf = 0; jf < 4; jf++) {
        const int mc = 32 * whi + 8 * jf + 2 * t;
        atomicAdd(&sDen[mc],     den[2 * jf]);
        atomicAdd(&sDen[mc + 1], den[2 * jf + 1]);
    }
    __syncthreads();
    if (tid < 64)
        g_denp[(size_t)(b * 4 + nr) * N_ + m0 + tid] = sDen[tid];
}

// =======================================================================
// Kernel 3: attn2 — fp8 e4m3 GEMM: Acc[c 128][m 64] = Qt @ P^T.
// grid (32 m-tiles, 4 c-tiles, 8 b), ring-3, occupancy 3.
// Hoisted ldm offsets + incremental prefetch pointers.
// =======================================================================
#define P8PITCH 80
#define PB8 (64  * P8PITCH)
#define QB8 (128 * P8PITCH)
#define A2_P  0
#define A2_Q  (A2_P + 3 * PB8)
#define A2_SMEM_BYTES (A2_Q + 3 * QB8)   // 46080
#define NT2 32
__global__ __launch_bounds__(256, 3) void attn2_kernel(
    const float* __restrict__ x, const float* __restrict__ gamma_p,
    float* __restrict__ out)
{
    extern __shared__ char smc[];
    const uint32_t smu = smem_u32(smc);
    const uint32_t sPu = smu + A2_P;
    const uint32_t sQu = smu + A2_Q;

    const int tid = threadIdx.x;
    const int wid = tid >> 5, lane = tid & 31;
    const int g = lane >> 2, t = lane & 3;
    const int wlo = wid & 3;
    const int whi = wid >> 2;

    const int arow = lane & 15;
    const int acol = (lane >> 4) << 4;
    const int brow = (lane & 7) | ((lane >> 4) << 3);
    const int bcol = ((lane >> 3) & 1) << 4;

    // hoisted ldm byte offsets (loop-invariant per warp)
    const uint32_t aoff0 = (32 * wlo + arow) * P8PITCH + acol;
    const uint32_t aoff1 = aoff0 + 16 * P8PITCH;
    const uint32_t boff0 = (32 * whi + brow) * P8PITCH + bcol;
    const uint32_t boff1 = boff0 + 16 * P8PITCH;

    const int mt = blockIdx.x, ct = blockIdx.y, b = blockIdx.z;
    const int m0 = mt * 64, c0 = ct * 128;
    const size_t rb = (size_t)b * N_;

    // incremental prefetch source pointers (advance 64 B per stage)
    const unsigned char* gP  = &g_P8[(size_t)b * N_ * N_ + (size_t)(m0 + (tid >> 2)) * N_ + (tid & 3) * 16];
    const unsigned char* gQ0 = &g_Q8[((size_t)b * C_ + c0 + (tid >> 2)) * N_ + (tid & 3) * 16];
    const unsigned char* gQ1 = gQ0 + (size_t)64 * N_;
    const uint32_t pdst  = sPu + (tid >> 2) * P8PITCH + (tid & 3) * 16;
    const uint32_t qdst0 = sQu + (tid >> 2) * P8PITCH + (tid & 3) * 16;
    const uint32_t qdst1 = qdst0 + 64 * P8PITCH;

    // prologue: stages 0,1
    #pragma unroll
    for (int s = 0; s < 2; s++) {
        cp16(pdst  + s * PB8, gP  + s * 64);
        cp16(qdst0 + s * QB8, gQ0 + s * 64);
        cp16(qdst1 + s * QB8, gQ1 + s * 64);
        CP_COMMIT();
    }
    gP += 128; gQ0 += 128; gQ1 += 128;   // next prefetch n = 128

    float acc[8][4];
    #pragma unroll
    for (int i = 0; i < 8; i++)
        #pragma unroll
        for (int j = 0; j < 4; j++) acc[i][j] = 0.f;

    uint32_t sl0 = 0, sl1 = 1, sl2 = 2;
    for (int nt = 0; nt < NT2; nt++) {
        CP_WAIT1();
        __syncthreads();

        if (nt + 2 < NT2) {
            cp16(pdst  + sl2 * PB8, gP);
            cp16(qdst0 + sl2 * QB8, gQ0);
            cp16(qdst1 + sl2 * QB8, gQ1);
            gP += 64; gQ0 += 64; gQ1 += 64;
        }
        CP_COMMIT();

        const uint32_t Pb = sPu + sl0 * PB8;
        const uint32_t Qb = sQu + sl0 * QB8;

        #pragma unroll
        for (int kk = 0; kk < 64; kk += 32) {
            uint32_t a0[4], a1[4], p0[4], p1[4];
            ldm4(a0, Qb + aoff0 + kk);
            ldm4(a1, Qb + aoff1 + kk);
            ldm4(p0, Pb + boff0 + kk);
            ldm4(p1, Pb + boff1 + kk);
            mma32(acc[0], a0, p0[0], p0[1]);
            mma32(acc[1], a0, p0[2], p0[3]);
            mma32(acc[2], a0, p1[0], p1[1]);
            mma32(acc[3], a0, p1[2], p1[3]);
            mma32(acc[4], a1, p0[0], p0[1]);
            mma32(acc[5], a1, p0[2], p0[3]);
            mma32(acc[6], a1, p1[0], p1[1]);
            mma32(acc[7], a1, p1[2], p1[3]);
        }

        uint32_t tmp = sl0; sl0 = sl1; sl1 = sl2; sl2 = tmp;
    }

    // ---- epilogue ----
    const float gam = gamma_p[0];
    #pragma unroll
    for (int mj = 0; mj < 4; mj++) {
        const int mc = 32 * whi + 8 * mj + 2 * t;
        float d0 = 0.f, d1 = 0.f;
        #pragma unroll
        for (int nr = 0; nr < 4; nr++) {
            d0 += __ldg(&g_denp[(size_t)(b * 4 + nr) * N_ + m0 + mc]);
            d1 += __ldg(&g_denp[(size_t)(b * 4 + nr) * N_ + m0 + mc + 1]);
        }
        const float di0 = gam / d0;
        const float di1 = gam / d1;
        #pragma unroll
        for (int fi = 0; fi < 2; fi++) {
            const int cc = c0 + 32 * wlo + 16 * fi + g;
            const size_t r0a = (rb + m0 + mc) * C_ + cc;
            const size_t r1a = (rb + m0 + mc + 1) * C_ + cc;
            const float* d = acc[fi * 4 + mj];
            out[r0a]     = d[0] * di0 + __ldg(&x[r0a]);
            out[r1a]     = d[1] * di1 + __ldg(&x[r1a]);
            out[r0a + 8] = d[2] * di0 + __ldg(&x[r0a + 8]);
            out[r1a + 8] = d[3] * di1 + __ldg(&x[r1a + 8]);
        }
    }
}

// =======================================================================
extern "C" void kernel_launch(void* const* d_in, const int* in_sizes, int n_in,
                              void* d_out, int out_size)
{
    const float* x     = (const float*)d_in[0];
    const float* Wk    = (const float*)d_in[1];
    const float* bk    = (const float*)d_in[2];
    const float* Wv    = (const float*)d_in[3];
    const float* bv    = (const float*)d_in[4];
    const float* Wq    = (const float*)d_in[5];
    const float* bq    = (const float*)d_in[6];
    const float* gamma = (const float*)d_in[7];
    float* out = (float*)d_out;

    cudaFuncSetAttribute(proj_hmma,    cudaFuncAttributeMaxDynamicSharedMemorySize, PJ_SMEM_BYTES);
    cudaFuncSetAttribute(pexp_kernel,  cudaFuncAttributeMaxDynamicSharedMemorySize, PX_SMEM_BYTES);
    cudaFuncSetAttribute(attn2_kernel, cudaFuncAttributeMaxDynamicSharedMemorySize, A2_SMEM_BYTES);

    cvt_kernel<<<1184, 256>>>(x, Wk, Wv, Wq);
    proj_hmma<<<dim3(5, 128), 256, PJ_SMEM_BYTES>>>(bk, bv, bq);
    pexp_kernel<<<dim3(32, 4, B_), 256, PX_SMEM_BYTES>>>();
    attn2_kernel<<<dim3(32, 4, B_), 256, A2_SMEM_BYTES>>>(x, gamma, out);
}